// round 1
// baseline (speedup 1.0000x reference)
#include <cuda_runtime.h>
#include <math.h>
#include <float.h>

// Problem constants
constexpr int NB = 2;
constexpr int NS = 1024;
constexpr int NC = 1024;
constexpr int NH = 16;
constexpr int HD = 64;
constexpr int NE = 4;

// ---------------------------------------------------------------------------
// Scratch (device globals — no runtime allocation allowed)
// ---------------------------------------------------------------------------
__device__ float g_comb[NB*NS*NC];
__device__ float g_cx  [NB*NS*NC];
__device__ float g_ae  [NB*2*NS*NC];
__device__ float g_q   [NB*NS*NC];
__device__ float g_k   [NB*2*NS*NC];
__device__ float g_v   [NB*2*NS*NC];
__device__ float g_lg  [(size_t)NB*NH*NS*2*NS];   // 256 MB logits/probs
__device__ float g_o   [NB*NS*NC];
__device__ float g_x   [NB*NS*NC];
__device__ float g_h   [NB*NS*NC];
__device__ float g_m1  [NB*NS*NE*NC];

// ---------------------------------------------------------------------------
// Block reductions (256 threads)
// ---------------------------------------------------------------------------
__device__ __forceinline__ float2 block_reduce_sum2(float a, float b) {
    __shared__ float sha[8], shb[8];
    #pragma unroll
    for (int o = 16; o > 0; o >>= 1) {
        a += __shfl_xor_sync(0xffffffffu, a, o);
        b += __shfl_xor_sync(0xffffffffu, b, o);
    }
    int lane = threadIdx.x & 31, w = threadIdx.x >> 5;
    __syncthreads();
    if (lane == 0) { sha[w] = a; shb[w] = b; }
    __syncthreads();
    a = sha[lane & 7]; b = shb[lane & 7];
    #pragma unroll
    for (int o = 4; o > 0; o >>= 1) {
        a += __shfl_xor_sync(0xffffffffu, a, o);
        b += __shfl_xor_sync(0xffffffffu, b, o);
    }
    return make_float2(a, b);
}

__device__ __forceinline__ float block_reduce_max(float a) {
    __shared__ float sh[8];
    #pragma unroll
    for (int o = 16; o > 0; o >>= 1) a = fmaxf(a, __shfl_xor_sync(0xffffffffu, a, o));
    int lane = threadIdx.x & 31, w = threadIdx.x >> 5;
    __syncthreads();
    if (lane == 0) sh[w] = a;
    __syncthreads();
    a = sh[lane & 7];
    #pragma unroll
    for (int o = 4; o > 0; o >>= 1) a = fmaxf(a, __shfl_xor_sync(0xffffffffu, a, o));
    return a;
}

__device__ __forceinline__ float block_reduce_sum(float a) {
    __shared__ float sh[8];
    #pragma unroll
    for (int o = 16; o > 0; o >>= 1) a += __shfl_xor_sync(0xffffffffu, a, o);
    int lane = threadIdx.x & 31, w = threadIdx.x >> 5;
    __syncthreads();
    if (lane == 0) sh[w] = a;
    __syncthreads();
    a = sh[lane & 7];
    #pragma unroll
    for (int o = 4; o > 0; o >>= 1) a += __shfl_xor_sync(0xffffffffu, a, o);
    return a;
}

// ---------------------------------------------------------------------------
// LN kernels (one block of 256 threads per row of 1024)
// ---------------------------------------------------------------------------
__global__ void ln_comb_kernel(const float* __restrict__ fwd, const float* __restrict__ bwd,
                               const float* __restrict__ g, const float* __restrict__ bta,
                               float* __restrict__ comb, float* __restrict__ cx)
{
    int row = blockIdx.x;                 // [0, NB*NS)
    int b = row / NS, s = row % NS;
    const float* fp = fwd + ((long)b*(NS+1) + s) * NC;
    const float* rp = bwd + ((long)b*(NS+1) + s + 1) * NC;
    const float rs2 = 0.70710678118654752f;
    float vals[4];
    float sum = 0.f, sq = 0.f;
    #pragma unroll
    for (int t = 0; t < 4; t++) {
        int i = threadIdx.x + t*256;
        float c = (fp[i] + rp[i]) * rs2;
        vals[t] = c; sum += c; sq += c*c;
        comb[(long)row*NC + i] = c;
    }
    float2 r2 = block_reduce_sum2(sum, sq);
    float mean = r2.x * (1.f/NC);
    float var  = r2.y * (1.f/NC) - mean*mean;
    float rinv = rsqrtf(var + 1e-5f);
    #pragma unroll
    for (int t = 0; t < 4; t++) {
        int i = threadIdx.x + t*256;
        cx[(long)row*NC + i] = (vals[t] - mean) * rinv * g[i] + bta[i];
    }
}

__global__ void ln_ae_kernel(const float* __restrict__ fwd, const float* __restrict__ bwd,
                             const float* __restrict__ g, const float* __restrict__ bta,
                             float* __restrict__ ae)
{
    int row = blockIdx.x;                 // [0, NB*2*NS)
    int b = row / (2*NS), t = row % (2*NS);
    const float* src = (t < NS) ? fwd + ((long)b*(NS+1) + t) * NC
                                : bwd + ((long)b*(NS+1) + (t - NS) + 1) * NC;
    float vals[4];
    float sum = 0.f, sq = 0.f;
    #pragma unroll
    for (int u = 0; u < 4; u++) {
        int i = threadIdx.x + u*256;
        float c = src[i];
        vals[u] = c; sum += c; sq += c*c;
    }
    float2 r2 = block_reduce_sum2(sum, sq);
    float mean = r2.x * (1.f/NC);
    float var  = r2.y * (1.f/NC) - mean*mean;
    float rinv = rsqrtf(var + 1e-5f);
    #pragma unroll
    for (int u = 0; u < 4; u++) {
        int i = threadIdx.x + u*256;
        ae[(long)row*NC + i] = (vals[u] - mean) * rinv * g[i] + bta[i];
    }
}

__global__ void double_ln_kernel(const float* __restrict__ xin,
                                 const float* __restrict__ g2, const float* __restrict__ b2,
                                 const float* __restrict__ gm, const float* __restrict__ bm,
                                 float* __restrict__ hout)
{
    int row = blockIdx.x;                 // [0, NB*NS)
    const float* xp = xin + (long)row*NC;
    float vals[4];
    float s = 0.f, sq = 0.f;
    #pragma unroll
    for (int t = 0; t < 4; t++) {
        int i = threadIdx.x + t*256;
        float vv = xp[i];
        vals[t] = vv; s += vv; sq += vv*vv;
    }
    float2 r2 = block_reduce_sum2(s, sq);
    float mean = r2.x * (1.f/NC);
    float var  = r2.y * (1.f/NC) - mean*mean;
    float rinv = rsqrtf(var + 1e-5f);
    s = 0.f; sq = 0.f;
    #pragma unroll
    for (int t = 0; t < 4; t++) {
        int i = threadIdx.x + t*256;
        float y = (vals[t] - mean) * rinv * g2[i] + b2[i];
        vals[t] = y; s += y; sq += y*y;
    }
    r2 = block_reduce_sum2(s, sq);
    mean = r2.x * (1.f/NC);
    var  = r2.y * (1.f/NC) - mean*mean;
    rinv = rsqrtf(var + 1e-5f);
    #pragma unroll
    for (int t = 0; t < 4; t++) {
        int i = threadIdx.x + t*256;
        hout[(long)row*NC + i] = (vals[t] - mean) * rinv * gm[i] + bm[i];
    }
}

// ---------------------------------------------------------------------------
// Masked softmax over rows of length 2S (one block per (b,h,q) row)
// ---------------------------------------------------------------------------
__global__ void softmax_kernel(float* __restrict__ logits)
{
    long row = blockIdx.x;                // [0, NB*NH*NS)
    int qi = (int)(row % NS);
    float* p = logits + row * (long)(2*NS);
    float v[8]; bool ok[8];
    float mx = -FLT_MAX;
    #pragma unroll
    for (int t = 0; t < 8; t++) {
        int kj = threadIdx.x + t*256;
        bool o = (kj < NS) ? (kj <= qi) : ((kj - NS) >= qi);
        float x = p[kj];
        ok[t] = o; v[t] = x;
        if (o) mx = fmaxf(mx, x);
    }
    mx = block_reduce_max(mx);
    float sum = 0.f;
    #pragma unroll
    for (int t = 0; t < 8; t++) {
        float e = ok[t] ? expf(v[t] - mx) : 0.f;
        v[t] = e; sum += e;
    }
    sum = block_reduce_sum(sum);
    float inv = 1.f / sum;
    #pragma unroll
    for (int t = 0; t < 8; t++) {
        int kj = threadIdx.x + t*256;
        p[kj] = v[t] * inv;
    }
}

// ---------------------------------------------------------------------------
// Tiled fp32 GEMM: C = A(MxK) * B + epilogue.
//   NT=false: B is KxN row-major.  NT=true: B is NxK row-major (C=A*B^T).
// All dims assumed exact multiples of tile sizes (true for this problem).
// Optional batching over blockIdx.z with (b,h) decomposition via Hn.
// ---------------------------------------------------------------------------
enum { EPI_NONE = 0, EPI_BIAS = 1, EPI_POS = 2, EPI_ADD = 3, EPI_GELU = 4 };

template<int BM, int BN, int BK, int TM, int TN, bool NT, int EPI>
__global__ __launch_bounds__(256)
void gemm_kernel(const float* __restrict__ A, int lda,
                 const float* __restrict__ Bp, int ldb,
                 float* __restrict__ Cp, int ldc,
                 int M, int N, int K,
                 const float* __restrict__ bias,
                 const float* __restrict__ pos,
                 const float* __restrict__ addm,
                 float scale, int Hn,
                 long sAb, long sAh, long sBb, long sBh, long sCb, long sCh)
{
    if (Hn > 0) {
        int bz = blockIdx.z / Hn, hz = blockIdx.z % Hn;
        A  += (long)bz*sAb + (long)hz*sAh;
        Bp += (long)bz*sBb + (long)hz*sBh;
        Cp += (long)bz*sCb + (long)hz*sCh;
    }
    __shared__ float As[BK][BM];
    __shared__ float Bs[BK][BN];
    const int tid = threadIdx.x;
    const int tileM = blockIdx.y * BM;
    const int tileN = blockIdx.x * BN;
    constexpr int TCOLS = BN / TN;
    const int rowBase = (tid / TCOLS) * TM;
    const int colBase = (tid % TCOLS) * TN;

    float acc[TM][TN];
    #pragma unroll
    for (int i = 0; i < TM; i++)
        #pragma unroll
        for (int j = 0; j < TN; j++) acc[i][j] = 0.f;

    constexpr int KF4  = BK/4;
    constexpr int AP   = (BM*BK)/(4*256);
    constexpr int NF4  = BN/4;
    constexpr int BPNN = (BK*BN)/(4*256) > 0 ? (BK*BN)/(4*256) : 1;
    constexpr int BPNT = (BN*BK)/(4*256) > 0 ? (BN*BK)/(4*256) : 1;

    for (int k0 = 0; k0 < K; k0 += BK) {
        #pragma unroll
        for (int i = 0; i < AP; i++) {
            int vI = tid + i*256;
            int r = vI / KF4, c4 = vI % KF4;
            float4 t4 = *reinterpret_cast<const float4*>(A + (long)(tileM + r)*lda + k0 + c4*4);
            As[c4*4+0][r] = t4.x; As[c4*4+1][r] = t4.y;
            As[c4*4+2][r] = t4.z; As[c4*4+3][r] = t4.w;
        }
        if (NT) {
            #pragma unroll
            for (int i = 0; i < BPNT; i++) {
                int vI = tid + i*256;
                if (BPNT*256 < BN*KF4 && vI >= BN*KF4) break;
                int r = vI / KF4, c4 = vI % KF4;
                float4 t4 = *reinterpret_cast<const float4*>(Bp + (long)(tileN + r)*ldb + k0 + c4*4);
                Bs[c4*4+0][r] = t4.x; Bs[c4*4+1][r] = t4.y;
                Bs[c4*4+2][r] = t4.z; Bs[c4*4+3][r] = t4.w;
            }
        } else {
            #pragma unroll
            for (int i = 0; i < BPNN; i++) {
                int vI = tid + i*256;
                if (BPNN*256 < BK*NF4 && vI >= BK*NF4) break;
                int rk = vI / NF4, c4 = vI % NF4;
                *reinterpret_cast<float4*>(&Bs[rk][c4*4]) =
                    *reinterpret_cast<const float4*>(Bp + (long)(k0 + rk)*ldb + tileN + c4*4);
            }
        }
        __syncthreads();
        #pragma unroll
        for (int kk = 0; kk < BK; kk++) {
            float a[TM], bb[TN];
            #pragma unroll
            for (int i = 0; i < TM/4; i++)
                *reinterpret_cast<float4*>(&a[4*i]) =
                    *reinterpret_cast<const float4*>(&As[kk][rowBase + 4*i]);
            #pragma unroll
            for (int j = 0; j < TN/4; j++)
                *reinterpret_cast<float4*>(&bb[4*j]) =
                    *reinterpret_cast<const float4*>(&Bs[kk][colBase + 4*j]);
            #pragma unroll
            for (int i = 0; i < TM; i++)
                #pragma unroll
                for (int j = 0; j < TN; j++)
                    acc[i][j] = fmaf(a[i], bb[j], acc[i][j]);
        }
        __syncthreads();
    }

    #pragma unroll
    for (int i = 0; i < TM; i++) {
        int gm = tileM + rowBase + i;
        #pragma unroll
        for (int j = 0; j < TN; j++) {
            int gn = tileN + colBase + j;
            float vv = acc[i][j];
            if (EPI == EPI_BIAS) {
                vv += bias[gn];
            } else if (EPI == EPI_POS) {
                vv = (vv + bias[gn] + pos[(gm % NS)*HD + (gn & (HD-1))]) * scale;
            } else if (EPI == EPI_ADD) {
                vv += bias[gn] + addm[(long)gm*ldc + gn];
            } else if (EPI == EPI_GELU) {
                float t = vv + bias[gn];
                vv = 0.5f * t * (1.f + erff(t * 0.70710678118654752f));
            }
            Cp[(long)gm*ldc + gn] = vv;
        }
    }
}

// ---------------------------------------------------------------------------
// Launch
// ---------------------------------------------------------------------------
extern "C" void kernel_launch(void* const* d_in, const int* in_sizes, int n_in,
                              void* d_out, int out_size)
{
    (void)in_sizes; (void)n_in; (void)out_size;
    const float* fwd  = (const float*)d_in[0];
    const float* bwd  = (const float*)d_in[1];
    const float* pos  = (const float*)d_in[2];
    const float* ln1g = (const float*)d_in[3];
    const float* ln1b = (const float*)d_in[4];
    const float* Wq   = (const float*)d_in[5];
    const float* bq   = (const float*)d_in[6];
    const float* Wk   = (const float*)d_in[7];
    const float* bk   = (const float*)d_in[8];
    const float* Wv   = (const float*)d_in[9];
    const float* bv   = (const float*)d_in[10];
    const float* Wo   = (const float*)d_in[11];
    const float* bo   = (const float*)d_in[12];
    const float* ln2g = (const float*)d_in[13];
    const float* ln2b = (const float*)d_in[14];
    const float* mlpg = (const float*)d_in[15];
    const float* mlpb = (const float*)d_in[16];
    const float* W1   = (const float*)d_in[17];
    const float* b1   = (const float*)d_in[18];
    const float* W2   = (const float*)d_in[19];
    const float* b2   = (const float*)d_in[20];
    float* out = (float*)d_out;

    float *comb, *cx, *ae, *q, *k, *v, *lg, *o, *x, *h, *m1;
    cudaGetSymbolAddress((void**)&comb, g_comb);
    cudaGetSymbolAddress((void**)&cx,   g_cx);
    cudaGetSymbolAddress((void**)&ae,   g_ae);
    cudaGetSymbolAddress((void**)&q,    g_q);
    cudaGetSymbolAddress((void**)&k,    g_k);
    cudaGetSymbolAddress((void**)&v,    g_v);
    cudaGetSymbolAddress((void**)&lg,   g_lg);
    cudaGetSymbolAddress((void**)&o,    g_o);
    cudaGetSymbolAddress((void**)&x,    g_x);
    cudaGetSymbolAddress((void**)&h,    g_h);
    cudaGetSymbolAddress((void**)&m1,   g_m1);

    // 1,2: LayerNorms of comb and all_embed
    ln_comb_kernel<<<NB*NS, 256>>>(fwd, bwd, ln1g, ln1b, comb, cx);
    ln_ae_kernel<<<NB*2*NS, 256>>>(fwd, bwd, ln1g, ln1b, ae);

    // 3: Q = (cx @ Wq + bq + pos) * 1/sqrt(HD)
    gemm_kernel<128,128,16,8,8,false,EPI_POS><<<dim3(NC/128, (NB*NS)/128, 1), 256>>>(
        cx, NC, Wq, NC, q, NC, NB*NS, NC, NC, bq, pos, nullptr, 0.125f, 0, 0,0,0,0,0,0);
    // 4: K = ae @ Wk + bk + pos2
    gemm_kernel<128,128,16,8,8,false,EPI_POS><<<dim3(NC/128, (NB*2*NS)/128, 1), 256>>>(
        ae, NC, Wk, NC, k, NC, NB*2*NS, NC, NC, bk, pos, nullptr, 1.0f, 0, 0,0,0,0,0,0);
    // 5: V = ae @ Wv + bv
    gemm_kernel<128,128,16,8,8,false,EPI_BIAS><<<dim3(NC/128, (NB*2*NS)/128, 1), 256>>>(
        ae, NC, Wv, NC, v, NC, NB*2*NS, NC, NC, bv, nullptr, nullptr, 1.0f, 0, 0,0,0,0,0,0);

    // 6: logits[b,h] = Q_bh (S x 64) @ K_bh^T (64 x 2S), batched over b,h
    gemm_kernel<128,128,16,8,8,true,EPI_NONE><<<dim3((2*NS)/128, NS/128, NB*NH), 256>>>(
        q, NC, k, NC, lg, 2*NS, NS, 2*NS, HD, nullptr, nullptr, nullptr, 1.0f, NH,
        (long)NS*NC, (long)HD, (long)2*NS*NC, (long)HD,
        (long)NH*NS*2*NS, (long)NS*2*NS);

    // 7: masked softmax in-place
    softmax_kernel<<<NB*NH*NS, 256>>>(lg);

    // 8: O_bh = P_bh (S x 2S) @ V_bh (2S x 64), batched
    gemm_kernel<128,64,16,8,4,false,EPI_NONE><<<dim3(1, NS/128, NB*NH), 256>>>(
        lg, 2*NS, v, NC, o, NC, NS, HD, 2*NS, nullptr, nullptr, nullptr, 1.0f, NH,
        (long)NH*NS*2*NS, (long)NS*2*NS, (long)2*NS*NC, (long)HD,
        (long)NS*NC, (long)HD);

    // 9: x = comb + (o @ Wo + bo)
    gemm_kernel<128,128,16,8,8,false,EPI_ADD><<<dim3(NC/128, (NB*NS)/128, 1), 256>>>(
        o, NC, Wo, NC, x, NC, NB*NS, NC, NC, bo, nullptr, comb, 1.0f, 0, 0,0,0,0,0,0);

    // 10: h = LN(LN(x, ln2), mlp)
    double_ln_kernel<<<NB*NS, 256>>>(x, ln2g, ln2b, mlpg, mlpb, h);

    // 11: m1 = gelu(h @ W1 + b1)
    gemm_kernel<128,128,16,8,8,false,EPI_GELU><<<dim3((NE*NC)/128, (NB*NS)/128, 1), 256>>>(
        h, NC, W1, NE*NC, m1, NE*NC, NB*NS, NE*NC, NC, b1, nullptr, nullptr, 1.0f, 0, 0,0,0,0,0,0);

    // 12: out = x + (m1 @ W2 + b2)
    gemm_kernel<128,128,16,8,8,false,EPI_ADD><<<dim3(NC/128, (NB*NS)/128, 1), 256>>>(
        m1, NE*NC, W2, NC, out, NC, NB*NS, NC, NE*NC, b2, nullptr, x, 1.0f, 0, 0,0,0,0,0,0);
}

// round 4
// speedup vs baseline: 1.4616x; 1.4616x over previous
#include <cuda_runtime.h>
#include <cuda_bf16.h>
#include <math.h>
#include <float.h>
#include <stdint.h>

// Problem constants
constexpr int NB = 2;
constexpr int NS = 1024;
constexpr int NC = 1024;
constexpr int NH = 16;
constexpr int HD = 64;
constexpr int NE = 4;

// ---------------------------------------------------------------------------
// Scratch (device globals — no runtime allocation allowed)
// ---------------------------------------------------------------------------
__device__ float g_comb[NB*NS*NC];
__device__ float g_cx  [NB*NS*NC];
__device__ float g_ae  [NB*2*NS*NC];
__device__ float g_q   [NB*NS*NC];
__device__ float g_k   [NB*2*NS*NC];
__device__ float g_v   [NB*2*NS*NC];
__device__ float g_lg  [(size_t)NB*NH*NS*2*NS];   // 256 MB logits/probs
__device__ float g_o   [NB*NS*NC];
__device__ float g_x   [NB*NS*NC];
__device__ float g_h   [NB*NS*NC];
__device__ float g_m1  [NB*NS*NE*NC];

// Split-bf16 transposed weights (N x K, K-contiguous)
__device__ __nv_bfloat16 g_wthi[12u<<20];
__device__ __nv_bfloat16 g_wtlo[12u<<20];
constexpr size_t WT_Q = 0;
constexpr size_t WT_K = (size_t)1<<20;
constexpr size_t WT_V = (size_t)2<<20;
constexpr size_t WT_O = (size_t)3<<20;
constexpr size_t WT_1 = (size_t)4<<20;
constexpr size_t WT_2 = (size_t)8<<20;

// ---------------------------------------------------------------------------
// Small helpers
// ---------------------------------------------------------------------------
__device__ __forceinline__ uint32_t smem_u32(const void* p) {
    uint32_t a;
    asm("{ .reg .u64 t; cvta.to.shared.u64 t, %1; cvt.u32.u64 %0, t; }" : "=r"(a) : "l"(p));
    return a;
}
__device__ __forceinline__ uint32_t pack_bf(float a, float b) {
    __nv_bfloat162 h = __floats2bfloat162_rn(a, b);
    return *reinterpret_cast<uint32_t*>(&h);
}
__device__ __forceinline__ void ldm_x4(uint32_t* r, uint32_t addr) {
    asm volatile("ldmatrix.sync.aligned.m8n8.x4.shared.b16 {%0,%1,%2,%3}, [%4];"
        : "=r"(r[0]), "=r"(r[1]), "=r"(r[2]), "=r"(r[3]) : "r"(addr));
}
__device__ __forceinline__ void mma16816(float* d, const uint32_t* a, uint32_t b0, uint32_t b1) {
    asm volatile(
        "mma.sync.aligned.m16n8k16.row.col.f32.bf16.bf16.f32 "
        "{%0,%1,%2,%3}, {%4,%5,%6,%7}, {%8,%9}, {%0,%1,%2,%3};"
        : "+f"(d[0]), "+f"(d[1]), "+f"(d[2]), "+f"(d[3])
        : "r"(a[0]), "r"(a[1]), "r"(a[2]), "r"(a[3]), "r"(b0), "r"(b1));
}

// ---------------------------------------------------------------------------
// Weight transform: W[K,N] fp32 -> Wt_hi/Wt_lo [N,K] bf16
// ---------------------------------------------------------------------------
__global__ void wt_split_kernel(const float* __restrict__ W,
                                __nv_bfloat16* __restrict__ hi,
                                __nv_bfloat16* __restrict__ lo,
                                int K, int N)
{
    __shared__ float t[32][33];
    int n0 = blockIdx.x * 32, k0 = blockIdx.y * 32;
    #pragma unroll
    for (int i = 0; i < 4; i++) {
        int k = k0 + threadIdx.y + 8*i;
        t[threadIdx.y + 8*i][threadIdx.x] = W[(size_t)k*N + n0 + threadIdx.x];
    }
    __syncthreads();
    #pragma unroll
    for (int i = 0; i < 4; i++) {
        int n = n0 + threadIdx.y + 8*i;
        int k = k0 + threadIdx.x;
        float v = t[threadIdx.x][threadIdx.y + 8*i];
        __nv_bfloat16 h = __float2bfloat16_rn(v);
        __nv_bfloat16 l = __float2bfloat16_rn(v - __bfloat162float(h));
        hi[(size_t)n*K + k] = h;
        lo[(size_t)n*K + k] = l;
    }
}

// ---------------------------------------------------------------------------
// MMA bf16x3 GEMM: C[M,N] = A[M,K](fp32) @ Wt[N,K]^T (+epilogue), fp32 out
// CTA tile 128x128, BK=32, 256 threads (8 warps = 4M x 2N, warp tile 32x64)
// ---------------------------------------------------------------------------
enum { EPI_NONE = 0, EPI_BIAS = 1, EPI_POS = 2, EPI_ADD = 3, EPI_GELU = 4 };

constexpr int MMA_LDS  = 56;                 // smem row stride (bf16 elems): 112B
constexpr int SM_AHI = 0;
constexpr int SM_ALO = 128*MMA_LDS;
constexpr int SM_BHI = 2*128*MMA_LDS;
constexpr int SM_BLO = 3*128*MMA_LDS;
constexpr int MMA_SMEM_BYTES = 4*128*MMA_LDS*2;   // 57344

template<int EPI>
__device__ __forceinline__ float2 apply_epi(int gm, int gn, float v0, float v1,
                                            const float* bias, const float* pos,
                                            const float* addm, float scale, int ldc)
{
    if (EPI == EPI_BIAS) {
        v0 += bias[gn]; v1 += bias[gn+1];
    } else if (EPI == EPI_POS) {
        const float* pr = pos + (gm % NS)*HD;
        v0 = (v0 + bias[gn]   + pr[gn & (HD-1)])     * scale;
        v1 = (v1 + bias[gn+1] + pr[(gn+1) & (HD-1)]) * scale;
    } else if (EPI == EPI_ADD) {
        float2 am = *reinterpret_cast<const float2*>(addm + (size_t)gm*ldc + gn);
        v0 += bias[gn]   + am.x;
        v1 += bias[gn+1] + am.y;
    } else if (EPI == EPI_GELU) {
        float t0 = v0 + bias[gn], t1 = v1 + bias[gn+1];
        v0 = 0.5f*t0*(1.f + erff(t0*0.70710678118654752f));
        v1 = 0.5f*t1*(1.f + erff(t1*0.70710678118654752f));
    }
    return make_float2(v0, v1);
}

template<int EPI>
__global__ __launch_bounds__(256)
void mma_gemm(const float* __restrict__ A, int lda,
              const __nv_bfloat16* __restrict__ Bhi,
              const __nv_bfloat16* __restrict__ Blo,
              float* __restrict__ C, int ldc,
              int K,
              const float* __restrict__ bias,
              const float* __restrict__ pos,
              const float* __restrict__ addm,
              float scale)
{
    extern __shared__ __nv_bfloat16 sm[];
    const uint32_t smb = smem_u32(sm);

    const int tid  = threadIdx.x;
    const int lane = tid & 31;
    const int wid  = tid >> 5;
    const int wm   = wid >> 1;       // 0..3
    const int wn   = wid & 1;        // 0..1
    const int tileM = blockIdx.y * 128;
    const int tileN = blockIdx.x * 128;

    float acc[2][8][4];
    #pragma unroll
    for (int i = 0; i < 2; i++)
        #pragma unroll
        for (int j = 0; j < 8; j++)
            #pragma unroll
            for (int q = 0; q < 4; q++) acc[i][j][q] = 0.f;

    // ldmatrix source addresses (per-lane)
    const int a_row = wm*32 + (lane & 15);
    const int b_row = wn*64 + (lane & 15);
    const int half8 = (lane >> 4) << 3;     // 0 or 8 elems

    for (int k0 = 0; k0 < K; k0 += 32) {
        // ---- load A tile (fp32 -> split bf16) ----
        #pragma unroll
        for (int i = 0; i < 4; i++) {
            int v = tid + i*256;             // 0..1023
            int r = v >> 3, c4 = (v & 7) * 4;
            float4 f = *reinterpret_cast<const float4*>(A + (size_t)(tileM + r)*lda + k0 + c4);
            __nv_bfloat16 h0 = __float2bfloat16_rn(f.x);
            __nv_bfloat16 h1 = __float2bfloat16_rn(f.y);
            __nv_bfloat16 h2 = __float2bfloat16_rn(f.z);
            __nv_bfloat16 h3 = __float2bfloat16_rn(f.w);
            uint2 hv = make_uint2(pack_bf(f.x, f.y), pack_bf(f.z, f.w));
            uint2 lv = make_uint2(
                pack_bf(f.x - __bfloat162float(h0), f.y - __bfloat162float(h1)),
                pack_bf(f.z - __bfloat162float(h2), f.w - __bfloat162float(h3)));
            *reinterpret_cast<uint2*>(&sm[SM_AHI + r*MMA_LDS + c4]) = hv;
            *reinterpret_cast<uint2*>(&sm[SM_ALO + r*MMA_LDS + c4]) = lv;
        }
        // ---- load B tile (pre-split bf16, K-major): 128 rows x 32 cols ----
        #pragma unroll
        for (int i = 0; i < 2; i++) {
            int v = tid + i*256;             // 0..511
            int r = v >> 2, c8 = (v & 3) * 8;   // FIXED: 4 chunks of 8 per row
            size_t ga = (size_t)(tileN + r)*K + k0 + c8;
            *reinterpret_cast<uint4*>(&sm[SM_BHI + r*MMA_LDS + c8]) =
                *reinterpret_cast<const uint4*>(Bhi + ga);
            *reinterpret_cast<uint4*>(&sm[SM_BLO + r*MMA_LDS + c8]) =
                *reinterpret_cast<const uint4*>(Blo + ga);
        }
        __syncthreads();

        #pragma unroll
        for (int ks = 0; ks < 32; ks += 16) {
            uint32_t ahi[2][4], alo[2][4];
            #pragma unroll
            for (int mt = 0; mt < 2; mt++) {
                uint32_t off = ((a_row + mt*16)*MMA_LDS + ks + half8) * 2;
                ldm_x4(ahi[mt], smb + (SM_AHI*2) + off);
                ldm_x4(alo[mt], smb + (SM_ALO*2) + off);
            }
            #pragma unroll
            for (int ntp = 0; ntp < 4; ntp++) {
                uint32_t off = ((b_row + ntp*16)*MMA_LDS + ks + half8) * 2;
                uint32_t bh[4], bl[4];
                ldm_x4(bh, smb + (SM_BHI*2) + off);
                ldm_x4(bl, smb + (SM_BLO*2) + off);
                #pragma unroll
                for (int mt = 0; mt < 2; mt++) {
                    float* a0 = acc[mt][ntp*2];
                    float* a1 = acc[mt][ntp*2+1];
                    mma16816(a0, ahi[mt], bh[0], bh[2]);
                    mma16816(a0, ahi[mt], bl[0], bl[2]);
                    mma16816(a0, alo[mt], bh[0], bh[2]);
                    mma16816(a1, ahi[mt], bh[1], bh[3]);
                    mma16816(a1, ahi[mt], bl[1], bl[3]);
                    mma16816(a1, alo[mt], bh[1], bh[3]);
                }
            }
        }
        __syncthreads();
    }

    // ---- epilogue from registers ----
    #pragma unroll
    for (int mt = 0; mt < 2; mt++) {
        #pragma unroll
        for (int nt = 0; nt < 8; nt++) {
            int gm = tileM + wm*32 + mt*16 + (lane >> 2);
            int gn = tileN + wn*64 + nt*8 + (lane & 3)*2;
            float2 r0 = apply_epi<EPI>(gm, gn, acc[mt][nt][0], acc[mt][nt][1],
                                       bias, pos, addm, scale, ldc);
            *reinterpret_cast<float2*>(C + (size_t)gm*ldc + gn) = r0;
            float2 r1 = apply_epi<EPI>(gm+8, gn, acc[mt][nt][2], acc[mt][nt][3],
                                       bias, pos, addm, scale, ldc);
            *reinterpret_cast<float2*>(C + (size_t)(gm+8)*ldc + gn) = r1;
        }
    }
}

// ---------------------------------------------------------------------------
// Block reductions (256 threads)
// ---------------------------------------------------------------------------
__device__ __forceinline__ float2 block_reduce_sum2(float a, float b) {
    __shared__ float sha[8], shb[8];
    #pragma unroll
    for (int o = 16; o > 0; o >>= 1) {
        a += __shfl_xor_sync(0xffffffffu, a, o);
        b += __shfl_xor_sync(0xffffffffu, b, o);
    }
    int lane = threadIdx.x & 31, w = threadIdx.x >> 5;
    __syncthreads();
    if (lane == 0) { sha[w] = a; shb[w] = b; }
    __syncthreads();
    a = sha[lane & 7]; b = shb[lane & 7];
    #pragma unroll
    for (int o = 4; o > 0; o >>= 1) {
        a += __shfl_xor_sync(0xffffffffu, a, o);
        b += __shfl_xor_sync(0xffffffffu, b, o);
    }
    return make_float2(a, b);
}

__device__ __forceinline__ float block_reduce_max(float a) {
    __shared__ float sh[8];
    #pragma unroll
    for (int o = 16; o > 0; o >>= 1) a = fmaxf(a, __shfl_xor_sync(0xffffffffu, a, o));
    int lane = threadIdx.x & 31, w = threadIdx.x >> 5;
    __syncthreads();
    if (lane == 0) sh[w] = a;
    __syncthreads();
    a = sh[lane & 7];
    #pragma unroll
    for (int o = 4; o > 0; o >>= 1) a = fmaxf(a, __shfl_xor_sync(0xffffffffu, a, o));
    return a;
}

__device__ __forceinline__ float block_reduce_sum(float a) {
    __shared__ float sh[8];
    #pragma unroll
    for (int o = 16; o > 0; o >>= 1) a += __shfl_xor_sync(0xffffffffu, a, o);
    int lane = threadIdx.x & 31, w = threadIdx.x >> 5;
    __syncthreads();
    if (lane == 0) sh[w] = a;
    __syncthreads();
    a = sh[lane & 7];
    #pragma unroll
    for (int o = 4; o > 0; o >>= 1) a += __shfl_xor_sync(0xffffffffu, a, o);
    return a;
}

// ---------------------------------------------------------------------------
// LN kernels
// ---------------------------------------------------------------------------
__global__ void ln_comb_kernel(const float* __restrict__ fwd, const float* __restrict__ bwd,
                               const float* __restrict__ g, const float* __restrict__ bta,
                               float* __restrict__ comb, float* __restrict__ cx)
{
    int row = blockIdx.x;
    int b = row / NS, s = row % NS;
    const float* fp = fwd + ((size_t)b*(NS+1) + s) * NC;
    const float* rp = bwd + ((size_t)b*(NS+1) + s + 1) * NC;
    const float rs2 = 0.70710678118654752f;
    float vals[4];
    float sum = 0.f, sq = 0.f;
    #pragma unroll
    for (int t = 0; t < 4; t++) {
        int i = threadIdx.x + t*256;
        float c = (fp[i] + rp[i]) * rs2;
        vals[t] = c; sum += c; sq += c*c;
        comb[(size_t)row*NC + i] = c;
    }
    float2 r2 = block_reduce_sum2(sum, sq);
    float mean = r2.x * (1.f/NC);
    float var  = r2.y * (1.f/NC) - mean*mean;
    float rinv = rsqrtf(var + 1e-5f);
    #pragma unroll
    for (int t = 0; t < 4; t++) {
        int i = threadIdx.x + t*256;
        cx[(size_t)row*NC + i] = (vals[t] - mean) * rinv * g[i] + bta[i];
    }
}

__global__ void ln_ae_kernel(const float* __restrict__ fwd, const float* __restrict__ bwd,
                             const float* __restrict__ g, const float* __restrict__ bta,
                             float* __restrict__ ae)
{
    int row = blockIdx.x;
    int b = row / (2*NS), t = row % (2*NS);
    const float* src = (t < NS) ? fwd + ((size_t)b*(NS+1) + t) * NC
                                : bwd + ((size_t)b*(NS+1) + (t - NS) + 1) * NC;
    float vals[4];
    float sum = 0.f, sq = 0.f;
    #pragma unroll
    for (int u = 0; u < 4; u++) {
        int i = threadIdx.x + u*256;
        float c = src[i];
        vals[u] = c; sum += c; sq += c*c;
    }
    float2 r2 = block_reduce_sum2(sum, sq);
    float mean = r2.x * (1.f/NC);
    float var  = r2.y * (1.f/NC) - mean*mean;
    float rinv = rsqrtf(var + 1e-5f);
    #pragma unroll
    for (int u = 0; u < 4; u++) {
        int i = threadIdx.x + u*256;
        ae[(size_t)row*NC + i] = (vals[u] - mean) * rinv * g[i] + bta[i];
    }
}

__global__ void double_ln_kernel(const float* __restrict__ xin,
                                 const float* __restrict__ g2, const float* __restrict__ b2,
                                 const float* __restrict__ gm, const float* __restrict__ bm,
                                 float* __restrict__ hout)
{
    int row = blockIdx.x;
    const float* xp = xin + (size_t)row*NC;
    float vals[4];
    float s = 0.f, sq = 0.f;
    #pragma unroll
    for (int t = 0; t < 4; t++) {
        int i = threadIdx.x + t*256;
        float vv = xp[i];
        vals[t] = vv; s += vv; sq += vv*vv;
    }
    float2 r2 = block_reduce_sum2(s, sq);
    float mean = r2.x * (1.f/NC);
    float var  = r2.y * (1.f/NC) - mean*mean;
    float rinv = rsqrtf(var + 1e-5f);
    s = 0.f; sq = 0.f;
    #pragma unroll
    for (int t = 0; t < 4; t++) {
        int i = threadIdx.x + t*256;
        float y = (vals[t] - mean) * rinv * g2[i] + b2[i];
        vals[t] = y; s += y; sq += y*y;
    }
    r2 = block_reduce_sum2(s, sq);
    mean = r2.x * (1.f/NC);
    var  = r2.y * (1.f/NC) - mean*mean;
    rinv = rsqrtf(var + 1e-5f);
    #pragma unroll
    for (int t = 0; t < 4; t++) {
        int i = threadIdx.x + t*256;
        hout[(size_t)row*NC + i] = (vals[t] - mean) * rinv * gm[i] + bm[i];
    }
}

// ---------------------------------------------------------------------------
// Masked softmax over rows of length 2S
// ---------------------------------------------------------------------------
__global__ void softmax_kernel(float* __restrict__ logits)
{
    long row = blockIdx.x;
    int qi = (int)(row % NS);
    float* p = logits + row * (long)(2*NS);
    float v[8]; bool ok[8];
    float mx = -FLT_MAX;
    #pragma unroll
    for (int t = 0; t < 8; t++) {
        int kj = threadIdx.x + t*256;
        bool o = (kj < NS) ? (kj <= qi) : ((kj - NS) >= qi);
        float x = p[kj];
        ok[t] = o; v[t] = x;
        if (o) mx = fmaxf(mx, x);
    }
    mx = block_reduce_max(mx);
    float sum = 0.f;
    #pragma unroll
    for (int t = 0; t < 8; t++) {
        float e = ok[t] ? expf(v[t] - mx) : 0.f;
        v[t] = e; sum += e;
    }
    sum = block_reduce_sum(sum);
    float inv = 1.f / sum;
    #pragma unroll
    for (int t = 0; t < 8; t++) {
        int kj = threadIdx.x + t*256;
        p[kj] = v[t] * inv;
    }
}

// ---------------------------------------------------------------------------
// fp32 tiled GEMM (attention batched GEMMs)
// ---------------------------------------------------------------------------
template<int BM, int BN, int BK, int TM, int TN, bool NT, int EPI>
__global__ __launch_bounds__(256)
void gemm_kernel(const float* __restrict__ A, int lda,
                 const float* __restrict__ Bp, int ldb,
                 float* __restrict__ Cp, int ldc,
                 int M, int N, int K,
                 const float* __restrict__ bias,
                 const float* __restrict__ pos,
                 const float* __restrict__ addm,
                 float scale, int Hn,
                 long sAb, long sAh, long sBb, long sBh, long sCb, long sCh)
{
    if (Hn > 0) {
        int bz = blockIdx.z / Hn, hz = blockIdx.z % Hn;
        A  += (long)bz*sAb + (long)hz*sAh;
        Bp += (long)bz*sBb + (long)hz*sBh;
        Cp += (long)bz*sCb + (long)hz*sCh;
    }
    __shared__ float As[BK][BM];
    __shared__ float Bs[BK][BN];
    const int tid = threadIdx.x;
    const int tileM = blockIdx.y * BM;
    const int tileN = blockIdx.x * BN;
    constexpr int TCOLS = BN / TN;
    const int rowBase = (tid / TCOLS) * TM;
    const int colBase = (tid % TCOLS) * TN;

    float acc[TM][TN];
    #pragma unroll
    for (int i = 0; i < TM; i++)
        #pragma unroll
        for (int j = 0; j < TN; j++) acc[i][j] = 0.f;

    constexpr int KF4  = BK/4;
    constexpr int AP   = (BM*BK)/(4*256);
    constexpr int NF4  = BN/4;
    constexpr int BPNN = (BK*BN)/(4*256) > 0 ? (BK*BN)/(4*256) : 1;
    constexpr int BPNT = (BN*BK)/(4*256) > 0 ? (BN*BK)/(4*256) : 1;

    for (int k0 = 0; k0 < K; k0 += BK) {
        #pragma unroll
        for (int i = 0; i < AP; i++) {
            int vI = tid + i*256;
            int r = vI / KF4, c4 = vI % KF4;
            float4 t4 = *reinterpret_cast<const float4*>(A + (long)(tileM + r)*lda + k0 + c4*4);
            As[c4*4+0][r] = t4.x; As[c4*4+1][r] = t4.y;
            As[c4*4+2][r] = t4.z; As[c4*4+3][r] = t4.w;
        }
        if (NT) {
            #pragma unroll
            for (int i = 0; i < BPNT; i++) {
                int vI = tid + i*256;
                if (BPNT*256 < BN*KF4 && vI >= BN*KF4) break;
                int r = vI / KF4, c4 = vI % KF4;
                float4 t4 = *reinterpret_cast<const float4*>(Bp + (long)(tileN + r)*ldb + k0 + c4*4);
                Bs[c4*4+0][r] = t4.x; Bs[c4*4+1][r] = t4.y;
                Bs[c4*4+2][r] = t4.z; Bs[c4*4+3][r] = t4.w;
            }
        } else {
            #pragma unroll
            for (int i = 0; i < BPNN; i++) {
                int vI = tid + i*256;
                if (BPNN*256 < BK*NF4 && vI >= BK*NF4) break;
                int rk = vI / NF4, c4 = vI % NF4;
                *reinterpret_cast<float4*>(&Bs[rk][c4*4]) =
                    *reinterpret_cast<const float4*>(Bp + (long)(k0 + rk)*ldb + tileN + c4*4);
            }
        }
        __syncthreads();
        #pragma unroll
        for (int kk = 0; kk < BK; kk++) {
            float a[TM], bb[TN];
            #pragma unroll
            for (int i = 0; i < TM/4; i++)
                *reinterpret_cast<float4*>(&a[4*i]) =
                    *reinterpret_cast<const float4*>(&As[kk][rowBase + 4*i]);
            #pragma unroll
            for (int j = 0; j < TN/4; j++)
                *reinterpret_cast<float4*>(&bb[4*j]) =
                    *reinterpret_cast<const float4*>(&Bs[kk][colBase + 4*j]);
            #pragma unroll
            for (int i = 0; i < TM; i++)
                #pragma unroll
                for (int j = 0; j < TN; j++)
                    acc[i][j] = fmaf(a[i], bb[j], acc[i][j]);
        }
        __syncthreads();
    }

    #pragma unroll
    for (int i = 0; i < TM; i++) {
        int gm = tileM + rowBase + i;
        #pragma unroll
        for (int j = 0; j < TN; j++) {
            int gn = tileN + colBase + j;
            float vv = acc[i][j];
            if (EPI == EPI_BIAS) {
                vv += bias[gn];
            } else if (EPI == EPI_ADD) {
                vv += bias[gn] + addm[(long)gm*ldc + gn];
            }
            Cp[(long)gm*ldc + gn] = vv;
        }
    }
}

// ---------------------------------------------------------------------------
// Launch
// ---------------------------------------------------------------------------
extern "C" void kernel_launch(void* const* d_in, const int* in_sizes, int n_in,
                              void* d_out, int out_size)
{
    (void)in_sizes; (void)n_in; (void)out_size;
    const float* fwd  = (const float*)d_in[0];
    const float* bwd  = (const float*)d_in[1];
    const float* pos  = (const float*)d_in[2];
    const float* ln1g = (const float*)d_in[3];
    const float* ln1b = (const float*)d_in[4];
    const float* Wq   = (const float*)d_in[5];
    const float* bq   = (const float*)d_in[6];
    const float* Wk   = (const float*)d_in[7];
    const float* bk   = (const float*)d_in[8];
    const float* Wv   = (const float*)d_in[9];
    const float* bv   = (const float*)d_in[10];
    const float* Wo   = (const float*)d_in[11];
    const float* bo   = (const float*)d_in[12];
    const float* ln2g = (const float*)d_in[13];
    const float* ln2b = (const float*)d_in[14];
    const float* mlpg = (const float*)d_in[15];
    const float* mlpb = (const float*)d_in[16];
    const float* W1   = (const float*)d_in[17];
    const float* b1   = (const float*)d_in[18];
    const float* W2   = (const float*)d_in[19];
    const float* b2   = (const float*)d_in[20];
    float* out = (float*)d_out;

    float *comb, *cx, *ae, *q, *k, *v, *lg, *o, *x, *h, *m1;
    __nv_bfloat16 *wthi, *wtlo;
    cudaGetSymbolAddress((void**)&comb, g_comb);
    cudaGetSymbolAddress((void**)&cx,   g_cx);
    cudaGetSymbolAddress((void**)&ae,   g_ae);
    cudaGetSymbolAddress((void**)&q,    g_q);
    cudaGetSymbolAddress((void**)&k,    g_k);
    cudaGetSymbolAddress((void**)&v,    g_v);
    cudaGetSymbolAddress((void**)&lg,   g_lg);
    cudaGetSymbolAddress((void**)&o,    g_o);
    cudaGetSymbolAddress((void**)&x,    g_x);
    cudaGetSymbolAddress((void**)&h,    g_h);
    cudaGetSymbolAddress((void**)&m1,   g_m1);
    cudaGetSymbolAddress((void**)&wthi, g_wthi);
    cudaGetSymbolAddress((void**)&wtlo, g_wtlo);

    cudaFuncSetAttribute(mma_gemm<EPI_POS>,  cudaFuncAttributeMaxDynamicSharedMemorySize, MMA_SMEM_BYTES);
    cudaFuncSetAttribute(mma_gemm<EPI_BIAS>, cudaFuncAttributeMaxDynamicSharedMemorySize, MMA_SMEM_BYTES);
    cudaFuncSetAttribute(mma_gemm<EPI_ADD>,  cudaFuncAttributeMaxDynamicSharedMemorySize, MMA_SMEM_BYTES);
    cudaFuncSetAttribute(mma_gemm<EPI_GELU>, cudaFuncAttributeMaxDynamicSharedMemorySize, MMA_SMEM_BYTES);

    // 0: weight transforms (transpose + bf16 split)
    {
        dim3 blk(32, 8);
        wt_split_kernel<<<dim3(NC/32, NC/32), blk>>>(Wq, wthi + WT_Q, wtlo + WT_Q, NC, NC);
        wt_split_kernel<<<dim3(NC/32, NC/32), blk>>>(Wk, wthi + WT_K, wtlo + WT_K, NC, NC);
        wt_split_kernel<<<dim3(NC/32, NC/32), blk>>>(Wv, wthi + WT_V, wtlo + WT_V, NC, NC);
        wt_split_kernel<<<dim3(NC/32, NC/32), blk>>>(Wo, wthi + WT_O, wtlo + WT_O, NC, NC);
        wt_split_kernel<<<dim3((NE*NC)/32, NC/32), blk>>>(W1, wthi + WT_1, wtlo + WT_1, NC, NE*NC);
        wt_split_kernel<<<dim3(NC/32, (NE*NC)/32), blk>>>(W2, wthi + WT_2, wtlo + WT_2, NE*NC, NC);
    }

    // 1,2: LayerNorms
    ln_comb_kernel<<<NB*NS, 256>>>(fwd, bwd, ln1g, ln1b, comb, cx);
    ln_ae_kernel<<<NB*2*NS, 256>>>(fwd, bwd, ln1g, ln1b, ae);

    // 3: Q = (cx @ Wq + bq + pos) * 1/sqrt(HD)
    mma_gemm<EPI_POS><<<dim3(NC/128, (NB*NS)/128), 256, MMA_SMEM_BYTES>>>(
        cx, NC, wthi + WT_Q, wtlo + WT_Q, q, NC, NC, bq, pos, nullptr, 0.125f);
    // 4: K = ae @ Wk + bk + pos2
    mma_gemm<EPI_POS><<<dim3(NC/128, (NB*2*NS)/128), 256, MMA_SMEM_BYTES>>>(
        ae, NC, wthi + WT_K, wtlo + WT_K, k, NC, NC, bk, pos, nullptr, 1.0f);
    // 5: V = ae @ Wv + bv
    mma_gemm<EPI_BIAS><<<dim3(NC/128, (NB*2*NS)/128), 256, MMA_SMEM_BYTES>>>(
        ae, NC, wthi + WT_V, wtlo + WT_V, v, NC, NC, bv, nullptr, nullptr, 1.0f);

    // 6: logits = Q @ K^T (fp32, batched over b,h)
    gemm_kernel<128,128,16,8,8,true,EPI_NONE><<<dim3((2*NS)/128, NS/128, NB*NH), 256>>>(
        q, NC, k, NC, lg, 2*NS, NS, 2*NS, HD, nullptr, nullptr, nullptr, 1.0f, NH,
        (long)NS*NC, (long)HD, (long)2*NS*NC, (long)HD,
        (long)NH*NS*2*NS, (long)NS*2*NS);

    // 7: masked softmax
    softmax_kernel<<<NB*NH*NS, 256>>>(lg);

    // 8: O = P @ V (fp32, batched)
    gemm_kernel<128,64,16,8,4,false,EPI_NONE><<<dim3(1, NS/128, NB*NH), 256>>>(
        lg, 2*NS, v, NC, o, NC, NS, HD, 2*NS, nullptr, nullptr, nullptr, 1.0f, NH,
        (long)NH*NS*2*NS, (long)NS*2*NS, (long)2*NS*NC, (long)HD,
        (long)NS*NC, (long)HD);

    // 9: x = comb + (o @ Wo + bo)
    mma_gemm<EPI_ADD><<<dim3(NC/128, (NB*NS)/128), 256, MMA_SMEM_BYTES>>>(
        o, NC, wthi + WT_O, wtlo + WT_O, x, NC, NC, bo, nullptr, comb, 1.0f);

    // 10: h = LN(LN(x))
    double_ln_kernel<<<NB*NS, 256>>>(x, ln2g, ln2b, mlpg, mlpb, h);

    // 11: m1 = gelu(h @ W1 + b1)
    mma_gemm<EPI_GELU><<<dim3((NE*NC)/128, (NB*NS)/128), 256, MMA_SMEM_BYTES>>>(
        h, NC, wthi + WT_1, wtlo + WT_1, m1, NE*NC, NC, b1, nullptr, nullptr, 1.0f);

    // 12: out = x + (m1 @ W2 + b2)
    mma_gemm<EPI_ADD><<<dim3(NC/128, (NB*NS)/128), 256, MMA_SMEM_BYTES>>>(
        m1, NE*NC, wthi + WT_2, wtlo + WT_2, out, NC, NE*NC, b2, nullptr, x, 1.0f);
}

// round 5
// speedup vs baseline: 2.3144x; 1.5835x over previous
#include <cuda_runtime.h>
#include <cuda_bf16.h>
#include <math.h>
#include <float.h>
#include <stdint.h>

// Problem constants
constexpr int NB = 2;
constexpr int NS = 1024;
constexpr int NC = 1024;
constexpr int NH = 16;
constexpr int HD = 64;
constexpr int NE = 4;

// ---------------------------------------------------------------------------
// Scratch (device globals — no runtime allocation allowed)
// ---------------------------------------------------------------------------
__device__ float g_comb[NB*NS*NC];
__device__ float g_cx  [NB*NS*NC];
__device__ float g_ae  [NB*2*NS*NC];
__device__ float g_q   [NB*NS*NC];
__device__ float g_k   [NB*2*NS*NC];
__device__ float g_v   [NB*2*NS*NC];
__device__ float g_o   [NB*NS*NC];
__device__ float g_x   [NB*NS*NC];
__device__ float g_h   [NB*NS*NC];
__device__ float g_m1  [NB*NS*NE*NC];

// Split-bf16 transposed weights (N x K, K-contiguous)
__device__ __nv_bfloat16 g_wthi[12u<<20];
__device__ __nv_bfloat16 g_wtlo[12u<<20];
constexpr size_t WT_Q = 0;
constexpr size_t WT_K = (size_t)1<<20;
constexpr size_t WT_V = (size_t)2<<20;
constexpr size_t WT_O = (size_t)3<<20;
constexpr size_t WT_1 = (size_t)4<<20;
constexpr size_t WT_2 = (size_t)8<<20;

// ---------------------------------------------------------------------------
// Small helpers
// ---------------------------------------------------------------------------
__device__ __forceinline__ uint32_t smem_u32(const void* p) {
    uint32_t a;
    asm("{ .reg .u64 t; cvta.to.shared.u64 t, %1; cvt.u32.u64 %0, t; }" : "=r"(a) : "l"(p));
    return a;
}
__device__ __forceinline__ uint32_t pack_bf(float a, float b) {
    __nv_bfloat162 h = __floats2bfloat162_rn(a, b);
    return *reinterpret_cast<uint32_t*>(&h);
}
__device__ __forceinline__ void split2(float a, float b, uint32_t& hi, uint32_t& lo) {
    __nv_bfloat16 ha = __float2bfloat16_rn(a);
    __nv_bfloat16 hb = __float2bfloat16_rn(b);
    hi = pack_bf(a, b);
    lo = pack_bf(a - __bfloat162float(ha), b - __bfloat162float(hb));
}
__device__ __forceinline__ void ldm_x4(uint32_t* r, uint32_t addr) {
    asm volatile("ldmatrix.sync.aligned.m8n8.x4.shared.b16 {%0,%1,%2,%3}, [%4];"
        : "=r"(r[0]), "=r"(r[1]), "=r"(r[2]), "=r"(r[3]) : "r"(addr));
}
__device__ __forceinline__ void ldm_x4_t(uint32_t* r, uint32_t addr) {
    asm volatile("ldmatrix.sync.aligned.m8n8.x4.trans.shared.b16 {%0,%1,%2,%3}, [%4];"
        : "=r"(r[0]), "=r"(r[1]), "=r"(r[2]), "=r"(r[3]) : "r"(addr));
}
__device__ __forceinline__ void mma16816(float* d, const uint32_t* a, uint32_t b0, uint32_t b1) {
    asm volatile(
        "mma.sync.aligned.m16n8k16.row.col.f32.bf16.bf16.f32 "
        "{%0,%1,%2,%3}, {%4,%5,%6,%7}, {%8,%9}, {%0,%1,%2,%3};"
        : "+f"(d[0]), "+f"(d[1]), "+f"(d[2]), "+f"(d[3])
        : "r"(a[0]), "r"(a[1]), "r"(a[2]), "r"(a[3]), "r"(b0), "r"(b1));
}

// ---------------------------------------------------------------------------
// Weight transform: W[K,N] fp32 -> Wt_hi/Wt_lo [N,K] bf16
// ---------------------------------------------------------------------------
__global__ void wt_split_kernel(const float* __restrict__ W,
                                __nv_bfloat16* __restrict__ hi,
                                __nv_bfloat16* __restrict__ lo,
                                int K, int N)
{
    __shared__ float t[32][33];
    int n0 = blockIdx.x * 32, k0 = blockIdx.y * 32;
    #pragma unroll
    for (int i = 0; i < 4; i++) {
        int k = k0 + threadIdx.y + 8*i;
        t[threadIdx.y + 8*i][threadIdx.x] = W[(size_t)k*N + n0 + threadIdx.x];
    }
    __syncthreads();
    #pragma unroll
    for (int i = 0; i < 4; i++) {
        int n = n0 + threadIdx.y + 8*i;
        int k = k0 + threadIdx.x;
        float v = t[threadIdx.x][threadIdx.y + 8*i];
        __nv_bfloat16 h = __float2bfloat16_rn(v);
        __nv_bfloat16 l = __float2bfloat16_rn(v - __bfloat162float(h));
        hi[(size_t)n*K + k] = h;
        lo[(size_t)n*K + k] = l;
    }
}

// ---------------------------------------------------------------------------
// MMA bf16x3 GEMM (X @ W paths)
// ---------------------------------------------------------------------------
enum { EPI_NONE = 0, EPI_BIAS = 1, EPI_POS = 2, EPI_ADD = 3, EPI_GELU = 4 };

constexpr int MMA_LDS  = 56;
constexpr int SM_AHI = 0;
constexpr int SM_ALO = 128*MMA_LDS;
constexpr int SM_BHI = 2*128*MMA_LDS;
constexpr int SM_BLO = 3*128*MMA_LDS;
constexpr int MMA_SMEM_BYTES = 4*128*MMA_LDS*2;

template<int EPI>
__device__ __forceinline__ float2 apply_epi(int gm, int gn, float v0, float v1,
                                            const float* bias, const float* pos,
                                            const float* addm, float scale, int ldc)
{
    if (EPI == EPI_BIAS) {
        v0 += bias[gn]; v1 += bias[gn+1];
    } else if (EPI == EPI_POS) {
        const float* pr = pos + (gm % NS)*HD;
        v0 = (v0 + bias[gn]   + pr[gn & (HD-1)])     * scale;
        v1 = (v1 + bias[gn+1] + pr[(gn+1) & (HD-1)]) * scale;
    } else if (EPI == EPI_ADD) {
        float2 am = *reinterpret_cast<const float2*>(addm + (size_t)gm*ldc + gn);
        v0 += bias[gn]   + am.x;
        v1 += bias[gn+1] + am.y;
    } else if (EPI == EPI_GELU) {
        float t0 = v0 + bias[gn], t1 = v1 + bias[gn+1];
        v0 = 0.5f*t0*(1.f + erff(t0*0.70710678118654752f));
        v1 = 0.5f*t1*(1.f + erff(t1*0.70710678118654752f));
    }
    return make_float2(v0, v1);
}

template<int EPI>
__global__ __launch_bounds__(256)
void mma_gemm(const float* __restrict__ A, int lda,
              const __nv_bfloat16* __restrict__ Bhi,
              const __nv_bfloat16* __restrict__ Blo,
              float* __restrict__ C, int ldc,
              int K,
              const float* __restrict__ bias,
              const float* __restrict__ pos,
              const float* __restrict__ addm,
              float scale)
{
    extern __shared__ __nv_bfloat16 sm[];
    const uint32_t smb = smem_u32(sm);

    const int tid  = threadIdx.x;
    const int lane = tid & 31;
    const int wid  = tid >> 5;
    const int wm   = wid >> 1;
    const int wn   = wid & 1;
    const int tileM = blockIdx.y * 128;
    const int tileN = blockIdx.x * 128;

    float acc[2][8][4];
    #pragma unroll
    for (int i = 0; i < 2; i++)
        #pragma unroll
        for (int j = 0; j < 8; j++)
            #pragma unroll
            for (int q = 0; q < 4; q++) acc[i][j][q] = 0.f;

    const int a_row = wm*32 + (lane & 15);
    const int b_row = wn*64 + (lane & 15);
    const int half8 = (lane >> 4) << 3;

    for (int k0 = 0; k0 < K; k0 += 32) {
        #pragma unroll
        for (int i = 0; i < 4; i++) {
            int v = tid + i*256;
            int r = v >> 3, c4 = (v & 7) * 4;
            float4 f = *reinterpret_cast<const float4*>(A + (size_t)(tileM + r)*lda + k0 + c4);
            uint32_t h01, l01, h23, l23;
            split2(f.x, f.y, h01, l01);
            split2(f.z, f.w, h23, l23);
            *reinterpret_cast<uint2*>(&sm[SM_AHI + r*MMA_LDS + c4]) = make_uint2(h01, h23);
            *reinterpret_cast<uint2*>(&sm[SM_ALO + r*MMA_LDS + c4]) = make_uint2(l01, l23);
        }
        #pragma unroll
        for (int i = 0; i < 2; i++) {
            int v = tid + i*256;
            int r = v >> 2, c8 = (v & 3) * 8;
            size_t ga = (size_t)(tileN + r)*K + k0 + c8;
            *reinterpret_cast<uint4*>(&sm[SM_BHI + r*MMA_LDS + c8]) =
                *reinterpret_cast<const uint4*>(Bhi + ga);
            *reinterpret_cast<uint4*>(&sm[SM_BLO + r*MMA_LDS + c8]) =
                *reinterpret_cast<const uint4*>(Blo + ga);
        }
        __syncthreads();

        #pragma unroll
        for (int ks = 0; ks < 32; ks += 16) {
            uint32_t ahi[2][4], alo[2][4];
            #pragma unroll
            for (int mt = 0; mt < 2; mt++) {
                uint32_t off = ((a_row + mt*16)*MMA_LDS + ks + half8) * 2;
                ldm_x4(ahi[mt], smb + (SM_AHI*2) + off);
                ldm_x4(alo[mt], smb + (SM_ALO*2) + off);
            }
            #pragma unroll
            for (int ntp = 0; ntp < 4; ntp++) {
                uint32_t off = ((b_row + ntp*16)*MMA_LDS + ks + half8) * 2;
                uint32_t bh[4], bl[4];
                ldm_x4(bh, smb + (SM_BHI*2) + off);
                ldm_x4(bl, smb + (SM_BLO*2) + off);
                #pragma unroll
                for (int mt = 0; mt < 2; mt++) {
                    float* a0 = acc[mt][ntp*2];
                    float* a1 = acc[mt][ntp*2+1];
                    mma16816(a0, ahi[mt], bh[0], bh[2]);
                    mma16816(a0, ahi[mt], bl[0], bl[2]);
                    mma16816(a0, alo[mt], bh[0], bh[2]);
                    mma16816(a1, ahi[mt], bh[1], bh[3]);
                    mma16816(a1, ahi[mt], bl[1], bl[3]);
                    mma16816(a1, alo[mt], bh[1], bh[3]);
                }
            }
        }
        __syncthreads();
    }

    #pragma unroll
    for (int mt = 0; mt < 2; mt++) {
        #pragma unroll
        for (int nt = 0; nt < 8; nt++) {
            int gm = tileM + wm*32 + mt*16 + (lane >> 2);
            int gn = tileN + wn*64 + nt*8 + (lane & 3)*2;
            float2 r0 = apply_epi<EPI>(gm, gn, acc[mt][nt][0], acc[mt][nt][1],
                                       bias, pos, addm, scale, ldc);
            *reinterpret_cast<float2*>(C + (size_t)gm*ldc + gn) = r0;
            float2 r1 = apply_epi<EPI>(gm+8, gn, acc[mt][nt][2], acc[mt][nt][3],
                                       bias, pos, addm, scale, ldc);
            *reinterpret_cast<float2*>(C + (size_t)(gm+8)*ldc + gn) = r1;
        }
    }
}

// ---------------------------------------------------------------------------
// Flash attention: per (b,h), Q tile 64 rows; online softmax; bf16x3 MMA
// 128 threads = 4 warps, each warp 16 q rows.
// ---------------------------------------------------------------------------
constexpr int FLS  = 72;                  // row stride (bf16) for 64-wide tiles
constexpr int FQHI = 0;
constexpr int FQLO = 64*FLS;
constexpr int FKHI = 2*64*FLS;
constexpr int FKLO = 3*64*FLS;
constexpr int FVHI = 4*64*FLS;
constexpr int FVLO = 5*64*FLS;
constexpr int FLASH_SMEM = 6*64*FLS*2;    // 55296 B

__global__ __launch_bounds__(128)
void flash_kernel(const float* __restrict__ q, const float* __restrict__ kk,
                  const float* __restrict__ vv, float* __restrict__ o)
{
    extern __shared__ __nv_bfloat16 sf[];
    const uint32_t smb = smem_u32(sf);
    const int tid = threadIdx.x, lane = tid & 31, wid = tid >> 5;
    const int bh = blockIdx.y, b = bh >> 4, h = bh & 15;
    const int q0 = blockIdx.x * 64;
    const float* qp = q  + (size_t)b*NS*NC   + h*HD;
    const float* kp = kk + (size_t)b*2*NS*NC + h*HD;
    const float* vp = vv + (size_t)b*2*NS*NC + h*HD;
    float* op       = o  + (size_t)b*NS*NC   + h*HD;

    // stage Q tile (64 x 64 fp32 -> split bf16)
    #pragma unroll
    for (int i = 0; i < 8; i++) {
        int s = tid + i*128;
        int r = s >> 4, c4 = (s & 15) * 4;
        float4 f = *reinterpret_cast<const float4*>(qp + (size_t)(q0 + r)*NC + c4);
        uint32_t h01, l01, h23, l23;
        split2(f.x, f.y, h01, l01);
        split2(f.z, f.w, h23, l23);
        *reinterpret_cast<uint2*>(&sf[FQHI + r*FLS + c4]) = make_uint2(h01, h23);
        *reinterpret_cast<uint2*>(&sf[FQLO + r*FLS + c4]) = make_uint2(l01, l23);
    }
    __syncthreads();

    // Q fragments in registers (4 k-chunks, hi+lo)
    const int arow = wid*16 + (lane & 15);
    const int half8 = (lane >> 4) << 3;
    uint32_t qhi[4][4], qlo[4][4];
    #pragma unroll
    for (int kc = 0; kc < 4; kc++) {
        uint32_t off = (arow*FLS + kc*16 + half8) * 2;
        ldm_x4(qhi[kc], smb + FQHI*2 + off);
        ldm_x4(qlo[kc], smb + FQLO*2 + off);
    }

    float om[8][4];
    #pragma unroll
    for (int i = 0; i < 8; i++)
        #pragma unroll
        for (int j = 0; j < 4; j++) om[i][j] = 0.f;
    float m_i0 = -1e30f, m_i1 = -1e30f, l_i0 = 0.f, l_i1 = 0.f;

    const int qrow0 = q0 + wid*16 + (lane >> 2);   // global q index for rows (c0,c1)

    for (int kt = 0; kt < 32; kt++) {
        const int kg0 = kt * 64;
        const bool fwdh = kg0 < 1024;
        if (fwdh) { if (kg0 > q0 + 63) continue; }
        else      { if (kg0 - 1024 + 63 < q0) continue; }
        const bool full = fwdh ? (kg0 + 63 <= q0) : (kg0 - 1024 >= q0 + 63);

        __syncthreads();
        // stage K,V tiles
        #pragma unroll
        for (int i = 0; i < 8; i++) {
            int s = tid + i*128;
            int r = s >> 4, c4 = (s & 15) * 4;
            float4 f = *reinterpret_cast<const float4*>(kp + (size_t)(kg0 + r)*NC + c4);
            uint32_t h01, l01, h23, l23;
            split2(f.x, f.y, h01, l01);
            split2(f.z, f.w, h23, l23);
            *reinterpret_cast<uint2*>(&sf[FKHI + r*FLS + c4]) = make_uint2(h01, h23);
            *reinterpret_cast<uint2*>(&sf[FKLO + r*FLS + c4]) = make_uint2(l01, l23);
            float4 g = *reinterpret_cast<const float4*>(vp + (size_t)(kg0 + r)*NC + c4);
            split2(g.x, g.y, h01, l01);
            split2(g.z, g.w, h23, l23);
            *reinterpret_cast<uint2*>(&sf[FVHI + r*FLS + c4]) = make_uint2(h01, h23);
            *reinterpret_cast<uint2*>(&sf[FVLO + r*FLS + c4]) = make_uint2(l01, l23);
        }
        __syncthreads();

        // S = Q K^T  (16 x 64 per warp)
        float s[8][4];
        #pragma unroll
        for (int i = 0; i < 8; i++)
            #pragma unroll
            for (int j = 0; j < 4; j++) s[i][j] = 0.f;
        #pragma unroll
        for (int kc = 0; kc < 4; kc++) {
            #pragma unroll
            for (int np = 0; np < 4; np++) {
                uint32_t off = ((np*16 + (lane & 15))*FLS + kc*16 + half8) * 2;
                uint32_t bh4[4], bl4[4];
                ldm_x4(bh4, smb + FKHI*2 + off);
                ldm_x4(bl4, smb + FKLO*2 + off);
                float* s0 = s[np*2];
                float* s1 = s[np*2+1];
                mma16816(s0, qhi[kc], bh4[0], bh4[2]);
                mma16816(s0, qhi[kc], bl4[0], bl4[2]);
                mma16816(s0, qlo[kc], bh4[0], bh4[2]);
                mma16816(s1, qhi[kc], bh4[1], bh4[3]);
                mma16816(s1, qhi[kc], bl4[1], bl4[3]);
                mma16816(s1, qlo[kc], bh4[1], bh4[3]);
            }
        }

        // mask (diagonal tiles only)
        if (!full) {
            #pragma unroll
            for (int nt = 0; nt < 8; nt++) {
                int kbase = kg0 + nt*8 + (lane & 3)*2;
                #pragma unroll
                for (int d = 0; d < 2; d++) {
                    int kidx = kbase + d;
                    bool ok0, ok1;
                    if (fwdh) { ok0 = (kidx <= qrow0); ok1 = (kidx <= qrow0 + 8); }
                    else      { int j = kidx - 1024; ok0 = (j >= qrow0); ok1 = (j >= qrow0 + 8); }
                    if (!ok0) s[nt][d]     = -1e30f;
                    if (!ok1) s[nt][d + 2] = -1e30f;
                }
            }
        }

        // online softmax
        float mx0 = -1e30f, mx1 = -1e30f;
        #pragma unroll
        for (int nt = 0; nt < 8; nt++) {
            mx0 = fmaxf(mx0, fmaxf(s[nt][0], s[nt][1]));
            mx1 = fmaxf(mx1, fmaxf(s[nt][2], s[nt][3]));
        }
        mx0 = fmaxf(mx0, __shfl_xor_sync(0xffffffffu, mx0, 1));
        mx0 = fmaxf(mx0, __shfl_xor_sync(0xffffffffu, mx0, 2));
        mx1 = fmaxf(mx1, __shfl_xor_sync(0xffffffffu, mx1, 1));
        mx1 = fmaxf(mx1, __shfl_xor_sync(0xffffffffu, mx1, 2));
        float mn0 = fmaxf(m_i0, mx0), mn1 = fmaxf(m_i1, mx1);
        float sc0 = __expf(m_i0 - mn0), sc1 = __expf(m_i1 - mn1);
        m_i0 = mn0; m_i1 = mn1;
        float rs0 = 0.f, rs1 = 0.f;
        #pragma unroll
        for (int nt = 0; nt < 8; nt++) {
            s[nt][0] = __expf(s[nt][0] - mn0);
            s[nt][1] = __expf(s[nt][1] - mn0);
            s[nt][2] = __expf(s[nt][2] - mn1);
            s[nt][3] = __expf(s[nt][3] - mn1);
            rs0 += s[nt][0] + s[nt][1];
            rs1 += s[nt][2] + s[nt][3];
        }
        rs0 += __shfl_xor_sync(0xffffffffu, rs0, 1);
        rs0 += __shfl_xor_sync(0xffffffffu, rs0, 2);
        rs1 += __shfl_xor_sync(0xffffffffu, rs1, 1);
        rs1 += __shfl_xor_sync(0xffffffffu, rs1, 2);
        l_i0 = l_i0 * sc0 + rs0;
        l_i1 = l_i1 * sc1 + rs1;
        #pragma unroll
        for (int nt = 0; nt < 8; nt++) {
            om[nt][0] *= sc0; om[nt][1] *= sc0;
            om[nt][2] *= sc1; om[nt][3] *= sc1;
        }

        // O += P V  (P split hi/lo in registers; V frags via ldmatrix.trans)
        #pragma unroll
        for (int kc = 0; kc < 4; kc++) {
            uint32_t ph[4], pl[4];
            split2(s[2*kc][0],   s[2*kc][1],   ph[0], pl[0]);
            split2(s[2*kc][2],   s[2*kc][3],   ph[1], pl[1]);
            split2(s[2*kc+1][0], s[2*kc+1][1], ph[2], pl[2]);
            split2(s[2*kc+1][2], s[2*kc+1][3], ph[3], pl[3]);
            const int vm = lane >> 3, vr = lane & 7;
            #pragma unroll
            for (int hp = 0; hp < 4; hp++) {
                uint32_t vaddr = ((kc*16 + (vm & 1)*8 + vr)*FLS + hp*16 + (vm >> 1)*8) * 2;
                uint32_t vh4[4], vl4[4];
                ldm_x4_t(vh4, smb + FVHI*2 + vaddr);
                ldm_x4_t(vl4, smb + FVLO*2 + vaddr);
                float* o0 = om[hp*2];
                float* o1 = om[hp*2+1];
                mma16816(o0, ph, vh4[0], vh4[1]);
                mma16816(o0, pl, vh4[0], vh4[1]);
                mma16816(o0, ph, vl4[0], vl4[1]);
                mma16816(o1, ph, vh4[2], vh4[3]);
                mma16816(o1, pl, vh4[2], vh4[3]);
                mma16816(o1, ph, vl4[2], vl4[3]);
            }
        }
    }

    // write O (divide by l)
    float il0 = 1.f / l_i0, il1 = 1.f / l_i1;
    #pragma unroll
    for (int nt = 0; nt < 8; nt++) {
        int hd = nt*8 + (lane & 3)*2;
        *reinterpret_cast<float2*>(op + (size_t)qrow0*NC + hd) =
            make_float2(om[nt][0]*il0, om[nt][1]*il0);
        *reinterpret_cast<float2*>(op + (size_t)(qrow0+8)*NC + hd) =
            make_float2(om[nt][2]*il1, om[nt][3]*il1);
    }
}

// ---------------------------------------------------------------------------
// Block reductions (256 threads)
// ---------------------------------------------------------------------------
__device__ __forceinline__ float2 block_reduce_sum2(float a, float b) {
    __shared__ float sha[8], shb[8];
    #pragma unroll
    for (int o = 16; o > 0; o >>= 1) {
        a += __shfl_xor_sync(0xffffffffu, a, o);
        b += __shfl_xor_sync(0xffffffffu, b, o);
    }
    int lane = threadIdx.x & 31, w = threadIdx.x >> 5;
    __syncthreads();
    if (lane == 0) { sha[w] = a; shb[w] = b; }
    __syncthreads();
    a = sha[lane & 7]; b = shb[lane & 7];
    #pragma unroll
    for (int o = 4; o > 0; o >>= 1) {
        a += __shfl_xor_sync(0xffffffffu, a, o);
        b += __shfl_xor_sync(0xffffffffu, b, o);
    }
    return make_float2(a, b);
}

// ---------------------------------------------------------------------------
// LN kernels
// ---------------------------------------------------------------------------
__global__ void ln_comb_kernel(const float* __restrict__ fwd, const float* __restrict__ bwd,
                               const float* __restrict__ g, const float* __restrict__ bta,
                               float* __restrict__ comb, float* __restrict__ cx)
{
    int row = blockIdx.x;
    int b = row / NS, s = row % NS;
    const float* fp = fwd + ((size_t)b*(NS+1) + s) * NC;
    const float* rp = bwd + ((size_t)b*(NS+1) + s + 1) * NC;
    const float rs2 = 0.70710678118654752f;
    float vals[4];
    float sum = 0.f, sq = 0.f;
    #pragma unroll
    for (int t = 0; t < 4; t++) {
        int i = threadIdx.x + t*256;
        float c = (fp[i] + rp[i]) * rs2;
        vals[t] = c; sum += c; sq += c*c;
        comb[(size_t)row*NC + i] = c;
    }
    float2 r2 = block_reduce_sum2(sum, sq);
    float mean = r2.x * (1.f/NC);
    float var  = r2.y * (1.f/NC) - mean*mean;
    float rinv = rsqrtf(var + 1e-5f);
    #pragma unroll
    for (int t = 0; t < 4; t++) {
        int i = threadIdx.x + t*256;
        cx[(size_t)row*NC + i] = (vals[t] - mean) * rinv * g[i] + bta[i];
    }
}

__global__ void ln_ae_kernel(const float* __restrict__ fwd, const float* __restrict__ bwd,
                             const float* __restrict__ g, const float* __restrict__ bta,
                             float* __restrict__ ae)
{
    int row = blockIdx.x;
    int b = row / (2*NS), t = row % (2*NS);
    const float* src = (t < NS) ? fwd + ((size_t)b*(NS+1) + t) * NC
                                : bwd + ((size_t)b*(NS+1) + (t - NS) + 1) * NC;
    float vals[4];
    float sum = 0.f, sq = 0.f;
    #pragma unroll
    for (int u = 0; u < 4; u++) {
        int i = threadIdx.x + u*256;
        float c = src[i];
        vals[u] = c; sum += c; sq += c*c;
    }
    float2 r2 = block_reduce_sum2(sum, sq);
    float mean = r2.x * (1.f/NC);
    float var  = r2.y * (1.f/NC) - mean*mean;
    float rinv = rsqrtf(var + 1e-5f);
    #pragma unroll
    for (int u = 0; u < 4; u++) {
        int i = threadIdx.x + u*256;
        ae[(size_t)row*NC + i] = (vals[u] - mean) * rinv * g[i] + bta[i];
    }
}

__global__ void double_ln_kernel(const float* __restrict__ xin,
                                 const float* __restrict__ g2, const float* __restrict__ b2,
                                 const float* __restrict__ gm, const float* __restrict__ bm,
                                 float* __restrict__ hout)
{
    int row = blockIdx.x;
    const float* xp = xin + (size_t)row*NC;
    float vals[4];
    float s = 0.f, sq = 0.f;
    #pragma unroll
    for (int t = 0; t < 4; t++) {
        int i = threadIdx.x + t*256;
        float vv = xp[i];
        vals[t] = vv; s += vv; sq += vv*vv;
    }
    float2 r2 = block_reduce_sum2(s, sq);
    float mean = r2.x * (1.f/NC);
    float var  = r2.y * (1.f/NC) - mean*mean;
    float rinv = rsqrtf(var + 1e-5f);
    s = 0.f; sq = 0.f;
    #pragma unroll
    for (int t = 0; t < 4; t++) {
        int i = threadIdx.x + t*256;
        float y = (vals[t] - mean) * rinv * g2[i] + b2[i];
        vals[t] = y; s += y; sq += y*y;
    }
    r2 = block_reduce_sum2(s, sq);
    mean = r2.x * (1.f/NC);
    var  = r2.y * (1.f/NC) - mean*mean;
    rinv = rsqrtf(var + 1e-5f);
    #pragma unroll
    for (int t = 0; t < 4; t++) {
        int i = threadIdx.x + t*256;
        hout[(size_t)row*NC + i] = (vals[t] - mean) * rinv * gm[i] + bm[i];
    }
}

// ---------------------------------------------------------------------------
// Launch
// ---------------------------------------------------------------------------
extern "C" void kernel_launch(void* const* d_in, const int* in_sizes, int n_in,
                              void* d_out, int out_size)
{
    (void)in_sizes; (void)n_in; (void)out_size;
    const float* fwd  = (const float*)d_in[0];
    const float* bwd  = (const float*)d_in[1];
    const float* pos  = (const float*)d_in[2];
    const float* ln1g = (const float*)d_in[3];
    const float* ln1b = (const float*)d_in[4];
    const float* Wq   = (const float*)d_in[5];
    const float* bq   = (const float*)d_in[6];
    const float* Wk   = (const float*)d_in[7];
    const float* bk   = (const float*)d_in[8];
    const float* Wv   = (const float*)d_in[9];
    const float* bv   = (const float*)d_in[10];
    const float* Wo   = (const float*)d_in[11];
    const float* bo   = (const float*)d_in[12];
    const float* ln2g = (const float*)d_in[13];
    const float* ln2b = (const float*)d_in[14];
    const float* mlpg = (const float*)d_in[15];
    const float* mlpb = (const float*)d_in[16];
    const float* W1   = (const float*)d_in[17];
    const float* b1   = (const float*)d_in[18];
    const float* W2   = (const float*)d_in[19];
    const float* b2   = (const float*)d_in[20];
    float* out = (float*)d_out;

    float *comb, *cx, *ae, *q, *k, *v, *o, *x, *h, *m1;
    __nv_bfloat16 *wthi, *wtlo;
    cudaGetSymbolAddress((void**)&comb, g_comb);
    cudaGetSymbolAddress((void**)&cx,   g_cx);
    cudaGetSymbolAddress((void**)&ae,   g_ae);
    cudaGetSymbolAddress((void**)&q,    g_q);
    cudaGetSymbolAddress((void**)&k,    g_k);
    cudaGetSymbolAddress((void**)&v,    g_v);
    cudaGetSymbolAddress((void**)&o,    g_o);
    cudaGetSymbolAddress((void**)&x,    g_x);
    cudaGetSymbolAddress((void**)&h,    g_h);
    cudaGetSymbolAddress((void**)&m1,   g_m1);
    cudaGetSymbolAddress((void**)&wthi, g_wthi);
    cudaGetSymbolAddress((void**)&wtlo, g_wtlo);

    cudaFuncSetAttribute(mma_gemm<EPI_POS>,  cudaFuncAttributeMaxDynamicSharedMemorySize, MMA_SMEM_BYTES);
    cudaFuncSetAttribute(mma_gemm<EPI_BIAS>, cudaFuncAttributeMaxDynamicSharedMemorySize, MMA_SMEM_BYTES);
    cudaFuncSetAttribute(mma_gemm<EPI_ADD>,  cudaFuncAttributeMaxDynamicSharedMemorySize, MMA_SMEM_BYTES);
    cudaFuncSetAttribute(mma_gemm<EPI_GELU>, cudaFuncAttributeMaxDynamicSharedMemorySize, MMA_SMEM_BYTES);
    cudaFuncSetAttribute(flash_kernel,       cudaFuncAttributeMaxDynamicSharedMemorySize, FLASH_SMEM);

    // 0: weight transforms
    {
        dim3 blk(32, 8);
        wt_split_kernel<<<dim3(NC/32, NC/32), blk>>>(Wq, wthi + WT_Q, wtlo + WT_Q, NC, NC);
        wt_split_kernel<<<dim3(NC/32, NC/32), blk>>>(Wk, wthi + WT_K, wtlo + WT_K, NC, NC);
        wt_split_kernel<<<dim3(NC/32, NC/32), blk>>>(Wv, wthi + WT_V, wtlo + WT_V, NC, NC);
        wt_split_kernel<<<dim3(NC/32, NC/32), blk>>>(Wo, wthi + WT_O, wtlo + WT_O, NC, NC);
        wt_split_kernel<<<dim3((NE*NC)/32, NC/32), blk>>>(W1, wthi + WT_1, wtlo + WT_1, NC, NE*NC);
        wt_split_kernel<<<dim3(NC/32, (NE*NC)/32), blk>>>(W2, wthi + WT_2, wtlo + WT_2, NE*NC, NC);
    }

    // 1,2: LayerNorms
    ln_comb_kernel<<<NB*NS, 256>>>(fwd, bwd, ln1g, ln1b, comb, cx);
    ln_ae_kernel<<<NB*2*NS, 256>>>(fwd, bwd, ln1g, ln1b, ae);

    // 3-5: Q,K,V projections
    mma_gemm<EPI_POS><<<dim3(NC/128, (NB*NS)/128), 256, MMA_SMEM_BYTES>>>(
        cx, NC, wthi + WT_Q, wtlo + WT_Q, q, NC, NC, bq, pos, nullptr, 0.125f);
    mma_gemm<EPI_POS><<<dim3(NC/128, (NB*2*NS)/128), 256, MMA_SMEM_BYTES>>>(
        ae, NC, wthi + WT_K, wtlo + WT_K, k, NC, NC, bk, pos, nullptr, 1.0f);
    mma_gemm<EPI_BIAS><<<dim3(NC/128, (NB*2*NS)/128), 256, MMA_SMEM_BYTES>>>(
        ae, NC, wthi + WT_V, wtlo + WT_V, v, NC, NC, bv, nullptr, nullptr, 1.0f);

    // 6: fused flash attention (replaces logits GEMM + softmax + PV GEMM)
    flash_kernel<<<dim3(NS/64, NB*NH), 128, FLASH_SMEM>>>(q, k, v, o);

    // 7: x = comb + (o @ Wo + bo)
    mma_gemm<EPI_ADD><<<dim3(NC/128, (NB*NS)/128), 256, MMA_SMEM_BYTES>>>(
        o, NC, wthi + WT_O, wtlo + WT_O, x, NC, NC, bo, nullptr, comb, 1.0f);

    // 8: h = LN(LN(x))
    double_ln_kernel<<<NB*NS, 256>>>(x, ln2g, ln2b, mlpg, mlpb, h);

    // 9: m1 = gelu(h @ W1 + b1)
    mma_gemm<EPI_GELU><<<dim3((NE*NC)/128, (NB*NS)/128), 256, MMA_SMEM_BYTES>>>(
        h, NC, wthi + WT_1, wtlo + WT_1, m1, NE*NC, NC, b1, nullptr, nullptr, 1.0f);

    // 10: out = x + (m1 @ W2 + b2)
    mma_gemm<EPI_ADD><<<dim3(NC/128, (NB*NS)/128), 256, MMA_SMEM_BYTES>>>(
        m1, NE*NC, wthi + WT_2, wtlo + WT_2, out, NC, NE*NC, b2, nullptr, x, 1.0f);
}

// round 6
// speedup vs baseline: 2.5701x; 1.1105x over previous
#include <cuda_runtime.h>
#include <cuda_bf16.h>
#include <math.h>
#include <float.h>
#include <stdint.h>

// Problem constants
constexpr int NB = 2;
constexpr int NS = 1024;
constexpr int NC = 1024;
constexpr int NH = 16;
constexpr int HD = 64;
constexpr int NE = 4;

// ---------------------------------------------------------------------------
// Scratch (device globals)
// ---------------------------------------------------------------------------
__device__ float g_comb[NB*NS*NC];
__device__ float g_x   [NB*NS*NC];

// split-bf16 activations
__device__ __nv_bfloat16 g_cxh[NB*NS*NC],    g_cxl[NB*NS*NC];
__device__ __nv_bfloat16 g_aeh[NB*2*NS*NC],  g_ael[NB*2*NS*NC];
__device__ __nv_bfloat16 g_qh [NB*NS*NC],    g_ql [NB*NS*NC];
__device__ __nv_bfloat16 g_kh [NB*2*NS*NC],  g_kl [NB*2*NS*NC];
__device__ __nv_bfloat16 g_vh [NB*2*NS*NC],  g_vl [NB*2*NS*NC];
__device__ __nv_bfloat16 g_oh [NB*NS*NC],    g_ol [NB*NS*NC];
__device__ __nv_bfloat16 g_hh [NB*NS*NC],    g_hl [NB*NS*NC];
__device__ __nv_bfloat16 g_m1h[NB*NS*NE*NC], g_m1l[NB*NS*NE*NC];

// Split-bf16 transposed weights (N x K, K-contiguous)
__device__ __nv_bfloat16 g_wthi[12u<<20];
__device__ __nv_bfloat16 g_wtlo[12u<<20];
constexpr size_t WT_Q = 0;
constexpr size_t WT_K = (size_t)1<<20;
constexpr size_t WT_V = (size_t)2<<20;
constexpr size_t WT_O = (size_t)3<<20;
constexpr size_t WT_1 = (size_t)4<<20;
constexpr size_t WT_2 = (size_t)8<<20;

// ---------------------------------------------------------------------------
// Helpers
// ---------------------------------------------------------------------------
__device__ __forceinline__ uint32_t smem_u32(const void* p) {
    uint32_t a;
    asm("{ .reg .u64 t; cvta.to.shared.u64 t, %1; cvt.u32.u64 %0, t; }" : "=r"(a) : "l"(p));
    return a;
}
__device__ __forceinline__ uint32_t pack_bf(float a, float b) {
    __nv_bfloat162 h = __floats2bfloat162_rn(a, b);
    return *reinterpret_cast<uint32_t*>(&h);
}
__device__ __forceinline__ void split2(float a, float b, uint32_t& hi, uint32_t& lo) {
    __nv_bfloat16 ha = __float2bfloat16_rn(a);
    __nv_bfloat16 hb = __float2bfloat16_rn(b);
    hi = pack_bf(a, b);
    lo = pack_bf(a - __bfloat162float(ha), b - __bfloat162float(hb));
}
__device__ __forceinline__ void ldm_x4(uint32_t* r, uint32_t addr) {
    asm volatile("ldmatrix.sync.aligned.m8n8.x4.shared.b16 {%0,%1,%2,%3}, [%4];"
        : "=r"(r[0]), "=r"(r[1]), "=r"(r[2]), "=r"(r[3]) : "r"(addr));
}
__device__ __forceinline__ void ldm_x4_t(uint32_t* r, uint32_t addr) {
    asm volatile("ldmatrix.sync.aligned.m8n8.x4.trans.shared.b16 {%0,%1,%2,%3}, [%4];"
        : "=r"(r[0]), "=r"(r[1]), "=r"(r[2]), "=r"(r[3]) : "r"(addr));
}
__device__ __forceinline__ void mma16816(float* d, const uint32_t* a, uint32_t b0, uint32_t b1) {
    asm volatile(
        "mma.sync.aligned.m16n8k16.row.col.f32.bf16.bf16.f32 "
        "{%0,%1,%2,%3}, {%4,%5,%6,%7}, {%8,%9}, {%0,%1,%2,%3};"
        : "+f"(d[0]), "+f"(d[1]), "+f"(d[2]), "+f"(d[3])
        : "r"(a[0]), "r"(a[1]), "r"(a[2]), "r"(a[3]), "r"(b0), "r"(b1));
}
#define CP16(dst, src) \
    asm volatile("cp.async.cg.shared.global [%0], [%1], 16;" :: "r"(dst), "l"(src))
#define CP_COMMIT() asm volatile("cp.async.commit_group;")
#define CP_WAIT0()  asm volatile("cp.async.wait_group 0;")
#define CP_WAIT1()  asm volatile("cp.async.wait_group 1;")

// ---------------------------------------------------------------------------
// Weight transform: W[K,N] fp32 -> Wt_hi/Wt_lo [N,K] bf16
// ---------------------------------------------------------------------------
__global__ void wt_split_kernel(const float* __restrict__ W,
                                __nv_bfloat16* __restrict__ hi,
                                __nv_bfloat16* __restrict__ lo,
                                int K, int N)
{
    __shared__ float t[32][33];
    int n0 = blockIdx.x * 32, k0 = blockIdx.y * 32;
    #pragma unroll
    for (int i = 0; i < 4; i++) {
        int k = k0 + threadIdx.y + 8*i;
        t[threadIdx.y + 8*i][threadIdx.x] = W[(size_t)k*N + n0 + threadIdx.x];
    }
    __syncthreads();
    #pragma unroll
    for (int i = 0; i < 4; i++) {
        int n = n0 + threadIdx.y + 8*i;
        int k = k0 + threadIdx.x;
        float v = t[threadIdx.x][threadIdx.y + 8*i];
        __nv_bfloat16 h = __float2bfloat16_rn(v);
        __nv_bfloat16 l = __float2bfloat16_rn(v - __bfloat162float(h));
        hi[(size_t)n*K + k] = h;
        lo[(size_t)n*K + k] = l;
    }
}

// ---------------------------------------------------------------------------
// MMA bf16x3 GEMM, pre-split operands, cp.async 2-stage pipeline.
// CTA 128x128, BK=32, 256 threads (8 warps = 4M x 2N).
// ---------------------------------------------------------------------------
enum { EPI_BIAS = 1, EPI_POS = 2, EPI_ADD = 3, EPI_GELU = 4 };

constexpr int BLDS = 40;                 // smem row stride (bf16): 80B, conflict-free
constexpr int MSTG = 128*BLDS;           // elems per matrix buffer (5120)
constexpr int MMA_SMEM_BYTES = 2*4*MSTG*2;   // 81920

template<int EPI, bool SPLITOUT>
__global__ __launch_bounds__(256)
void mma_gemm(const __nv_bfloat16* __restrict__ Ahi, const __nv_bfloat16* __restrict__ Alo,
              int lda,
              const __nv_bfloat16* __restrict__ Bhi, const __nv_bfloat16* __restrict__ Blo,
              float* __restrict__ C,
              __nv_bfloat16* __restrict__ Chi, __nv_bfloat16* __restrict__ Clo,
              int ldc, int K,
              const float* __restrict__ bias,
              const float* __restrict__ pos,
              const float* __restrict__ addm,
              float scale)
{
    extern __shared__ __nv_bfloat16 sm[];
    const uint32_t smb = smem_u32(sm);

    const int tid  = threadIdx.x;
    const int lane = tid & 31;
    const int wid  = tid >> 5;
    const int wm   = wid >> 1;
    const int wn   = wid & 1;
    const int tileM = blockIdx.y * 128;
    const int tileN = blockIdx.x * 128;

    float acc[2][8][4];
    #pragma unroll
    for (int i = 0; i < 2; i++)
        #pragma unroll
        for (int j = 0; j < 8; j++)
            #pragma unroll
            for (int q = 0; q < 4; q++) acc[i][j][q] = 0.f;

    const int a_row = wm*32 + (lane & 15);
    const int b_row = wn*64 + (lane & 15);
    const int half8 = (lane >> 4) << 3;

    // per-thread staging coords
    const int sr0 = tid >> 2, sc0 = (tid & 3) * 8;          // iter 0: rows 0..63
    const int sr1 = sr0 + 64;                               // iter 1: rows 64..127
    const int nch = K >> 5;

    // prologue: stage chunk 0 into stage 0
    {
        uint32_t so0 = (0*4*MSTG + sr0*BLDS + sc0) * 2;
        uint32_t so1 = (0*4*MSTG + sr1*BLDS + sc0) * 2;
        size_t gaA0 = (size_t)(tileM + sr0)*lda + sc0;
        size_t gaA1 = (size_t)(tileM + sr1)*lda + sc0;
        size_t gaB0 = (size_t)(tileN + sr0)*K + sc0;
        size_t gaB1 = (size_t)(tileN + sr1)*K + sc0;
        CP16(smb + so0,            Ahi + gaA0);
        CP16(smb + so0 + MSTG*2,   Alo + gaA0);
        CP16(smb + so0 + 2*MSTG*2, Bhi + gaB0);
        CP16(smb + so0 + 3*MSTG*2, Blo + gaB0);
        CP16(smb + so1,            Ahi + gaA1);
        CP16(smb + so1 + MSTG*2,   Alo + gaA1);
        CP16(smb + so1 + 2*MSTG*2, Bhi + gaB1);
        CP16(smb + so1 + 3*MSTG*2, Blo + gaB1);
        CP_COMMIT();
    }

    for (int c = 0; c < nch; c++) {
        const int st = c & 1;
        if (c + 1 < nch) {
            const int k0 = (c + 1) << 5;
            const int s2 = st ^ 1;
            uint32_t so0 = (s2*4*MSTG + sr0*BLDS + sc0) * 2;
            uint32_t so1 = (s2*4*MSTG + sr1*BLDS + sc0) * 2;
            size_t gaA0 = (size_t)(tileM + sr0)*lda + k0 + sc0;
            size_t gaA1 = (size_t)(tileM + sr1)*lda + k0 + sc0;
            size_t gaB0 = (size_t)(tileN + sr0)*K + k0 + sc0;
            size_t gaB1 = (size_t)(tileN + sr1)*K + k0 + sc0;
            CP16(smb + so0,            Ahi + gaA0);
            CP16(smb + so0 + MSTG*2,   Alo + gaA0);
            CP16(smb + so0 + 2*MSTG*2, Bhi + gaB0);
            CP16(smb + so0 + 3*MSTG*2, Blo + gaB0);
            CP16(smb + so1,            Ahi + gaA1);
            CP16(smb + so1 + MSTG*2,   Alo + gaA1);
            CP16(smb + so1 + 2*MSTG*2, Bhi + gaB1);
            CP16(smb + so1 + 3*MSTG*2, Blo + gaB1);
            CP_COMMIT();
            CP_WAIT1();
        } else {
            CP_WAIT0();
        }
        __syncthreads();

        const uint32_t sbase = smb + st*4*MSTG*2;
        #pragma unroll
        for (int ks = 0; ks < 32; ks += 16) {
            uint32_t ahi[2][4], alo[2][4];
            #pragma unroll
            for (int mt = 0; mt < 2; mt++) {
                uint32_t off = ((a_row + mt*16)*BLDS + ks + half8) * 2;
                ldm_x4(ahi[mt], sbase + off);
                ldm_x4(alo[mt], sbase + MSTG*2 + off);
            }
            #pragma unroll
            for (int ntp = 0; ntp < 4; ntp++) {
                uint32_t off = ((b_row + ntp*16)*BLDS + ks + half8) * 2;
                uint32_t bh[4], bl[4];
                ldm_x4(bh, sbase + 2*MSTG*2 + off);
                ldm_x4(bl, sbase + 3*MSTG*2 + off);
                #pragma unroll
                for (int mt = 0; mt < 2; mt++) {
                    float* a0 = acc[mt][ntp*2];
                    float* a1 = acc[mt][ntp*2+1];
                    mma16816(a0, ahi[mt], bh[0], bh[2]);
                    mma16816(a0, ahi[mt], bl[0], bl[2]);
                    mma16816(a0, alo[mt], bh[0], bh[2]);
                    mma16816(a1, ahi[mt], bh[1], bh[3]);
                    mma16816(a1, ahi[mt], bl[1], bl[3]);
                    mma16816(a1, alo[mt], bh[1], bh[3]);
                }
            }
        }
        __syncthreads();
    }

    // epilogue
    #pragma unroll
    for (int mt = 0; mt < 2; mt++) {
        #pragma unroll
        for (int nt = 0; nt < 8; nt++) {
            int gm = tileM + wm*32 + mt*16 + (lane >> 2);
            int gn = tileN + wn*64 + nt*8 + (lane & 3)*2;
            #pragma unroll
            for (int half = 0; half < 2; half++) {
                int gmr = gm + half*8;
                float v0 = acc[mt][nt][half*2], v1 = acc[mt][nt][half*2+1];
                if (EPI == EPI_BIAS) {
                    v0 += bias[gn]; v1 += bias[gn+1];
                } else if (EPI == EPI_POS) {
                    const float* pr = pos + (gmr % NS)*HD;
                    v0 = (v0 + bias[gn]   + pr[gn & (HD-1)])     * scale;
                    v1 = (v1 + bias[gn+1] + pr[(gn+1) & (HD-1)]) * scale;
                } else if (EPI == EPI_ADD) {
                    float2 am = *reinterpret_cast<const float2*>(addm + (size_t)gmr*ldc + gn);
                    v0 += bias[gn] + am.x; v1 += bias[gn+1] + am.y;
                } else if (EPI == EPI_GELU) {
                    float t0 = v0 + bias[gn], t1 = v1 + bias[gn+1];
                    v0 = 0.5f*t0*(1.f + erff(t0*0.70710678118654752f));
                    v1 = 0.5f*t1*(1.f + erff(t1*0.70710678118654752f));
                }
                if (SPLITOUT) {
                    uint32_t hi, lo;
                    split2(v0, v1, hi, lo);
                    *reinterpret_cast<uint32_t*>(Chi + (size_t)gmr*ldc + gn) = hi;
                    *reinterpret_cast<uint32_t*>(Clo + (size_t)gmr*ldc + gn) = lo;
                } else {
                    *reinterpret_cast<float2*>(C + (size_t)gmr*ldc + gn) = make_float2(v0, v1);
                }
            }
        }
    }
}

// ---------------------------------------------------------------------------
// Flash attention on pre-split bf16 Q/K/V; split bf16 O out.
// ---------------------------------------------------------------------------
constexpr int FLS  = 72;
constexpr int FQHI = 0;
constexpr int FQLO = 64*FLS;
constexpr int FKHI = 2*64*FLS;
constexpr int FKLO = 3*64*FLS;
constexpr int FVHI = 4*64*FLS;
constexpr int FVLO = 5*64*FLS;
constexpr int FLASH_SMEM = 6*64*FLS*2;

__global__ __launch_bounds__(128)
void flash_kernel(const __nv_bfloat16* __restrict__ qh, const __nv_bfloat16* __restrict__ ql,
                  const __nv_bfloat16* __restrict__ kh, const __nv_bfloat16* __restrict__ kl,
                  const __nv_bfloat16* __restrict__ vh, const __nv_bfloat16* __restrict__ vl,
                  __nv_bfloat16* __restrict__ oh, __nv_bfloat16* __restrict__ ol)
{
    extern __shared__ __nv_bfloat16 sf[];
    const uint32_t smb = smem_u32(sf);
    const int tid = threadIdx.x, lane = tid & 31, wid = tid >> 5;
    const int bh = blockIdx.y, b = bh >> 4, h = bh & 15;
    const int q0 = blockIdx.x * 64;
    const size_t qoff = (size_t)b*NS*NC   + h*HD;
    const size_t koff = (size_t)b*2*NS*NC + h*HD;

    // stage Q tile
    {
        const int r = tid >> 1, c8 = (tid & 1) * 8;   // covers 64 rows x 16 cols per pass
        #pragma unroll
        for (int i = 0; i < 4; i++) {
            int cc = c8 + i*16;
            size_t ga = qoff + (size_t)(q0 + r)*NC + cc;
            uint32_t so = (r*FLS + cc) * 2;
            CP16(smb + FQHI*2 + so, qh + ga);
            CP16(smb + FQLO*2 + so, ql + ga);
        }
        CP_COMMIT(); CP_WAIT0();
    }
    __syncthreads();

    const int arow = wid*16 + (lane & 15);
    const int half8 = (lane >> 4) << 3;
    uint32_t qhi4[4][4], qlo4[4][4];
    #pragma unroll
    for (int kc = 0; kc < 4; kc++) {
        uint32_t off = (arow*FLS + kc*16 + half8) * 2;
        ldm_x4(qhi4[kc], smb + FQHI*2 + off);
        ldm_x4(qlo4[kc], smb + FQLO*2 + off);
    }

    float om[8][4];
    #pragma unroll
    for (int i = 0; i < 8; i++)
        #pragma unroll
        for (int j = 0; j < 4; j++) om[i][j] = 0.f;
    float m_i0 = -1e30f, m_i1 = -1e30f, l_i0 = 0.f, l_i1 = 0.f;

    const int qrow0 = q0 + wid*16 + (lane >> 2);

    for (int kt = 0; kt < 32; kt++) {
        const int kg0 = kt * 64;
        const bool fwdh = kg0 < 1024;
        if (fwdh) { if (kg0 > q0 + 63) continue; }
        else      { if (kg0 - 1024 + 63 < q0) continue; }
        const bool full = fwdh ? (kg0 + 63 <= q0) : (kg0 - 1024 >= q0 + 63);

        __syncthreads();
        // stage K,V tiles via cp.async
        {
            const int r = tid >> 1, c8 = (tid & 1) * 8;
            #pragma unroll
            for (int i = 0; i < 4; i++) {
                int cc = c8 + i*16;
                size_t ga = koff + (size_t)(kg0 + r)*NC + cc;
                uint32_t so = (r*FLS + cc) * 2;
                CP16(smb + FKHI*2 + so, kh + ga);
                CP16(smb + FKLO*2 + so, kl + ga);
                CP16(smb + FVHI*2 + so, vh + ga);
                CP16(smb + FVLO*2 + so, vl + ga);
            }
            CP_COMMIT(); CP_WAIT0();
        }
        __syncthreads();

        // S = Q K^T
        float s[8][4];
        #pragma unroll
        for (int i = 0; i < 8; i++)
            #pragma unroll
            for (int j = 0; j < 4; j++) s[i][j] = 0.f;
        #pragma unroll
        for (int kc = 0; kc < 4; kc++) {
            #pragma unroll
            for (int np = 0; np < 4; np++) {
                uint32_t off = ((np*16 + (lane & 15))*FLS + kc*16 + half8) * 2;
                uint32_t bh4[4], bl4[4];
                ldm_x4(bh4, smb + FKHI*2 + off);
                ldm_x4(bl4, smb + FKLO*2 + off);
                float* s0 = s[np*2];
                float* s1 = s[np*2+1];
                mma16816(s0, qhi4[kc], bh4[0], bh4[2]);
                mma16816(s0, qhi4[kc], bl4[0], bl4[2]);
                mma16816(s0, qlo4[kc], bh4[0], bh4[2]);
                mma16816(s1, qhi4[kc], bh4[1], bh4[3]);
                mma16816(s1, qhi4[kc], bl4[1], bl4[3]);
                mma16816(s1, qlo4[kc], bh4[1], bh4[3]);
            }
        }

        if (!full) {
            #pragma unroll
            for (int nt = 0; nt < 8; nt++) {
                int kbase = kg0 + nt*8 + (lane & 3)*2;
                #pragma unroll
                for (int d = 0; d < 2; d++) {
                    int kidx = kbase + d;
                    bool ok0, ok1;
                    if (fwdh) { ok0 = (kidx <= qrow0); ok1 = (kidx <= qrow0 + 8); }
                    else      { int j = kidx - 1024; ok0 = (j >= qrow0); ok1 = (j >= qrow0 + 8); }
                    if (!ok0) s[nt][d]     = -1e30f;
                    if (!ok1) s[nt][d + 2] = -1e30f;
                }
            }
        }

        // online softmax
        float mx0 = -1e30f, mx1 = -1e30f;
        #pragma unroll
        for (int nt = 0; nt < 8; nt++) {
            mx0 = fmaxf(mx0, fmaxf(s[nt][0], s[nt][1]));
            mx1 = fmaxf(mx1, fmaxf(s[nt][2], s[nt][3]));
        }
        mx0 = fmaxf(mx0, __shfl_xor_sync(0xffffffffu, mx0, 1));
        mx0 = fmaxf(mx0, __shfl_xor_sync(0xffffffffu, mx0, 2));
        mx1 = fmaxf(mx1, __shfl_xor_sync(0xffffffffu, mx1, 1));
        mx1 = fmaxf(mx1, __shfl_xor_sync(0xffffffffu, mx1, 2));
        float mn0 = fmaxf(m_i0, mx0), mn1 = fmaxf(m_i1, mx1);
        float sc0 = __expf(m_i0 - mn0), sc1 = __expf(m_i1 - mn1);
        m_i0 = mn0; m_i1 = mn1;
        float rs0 = 0.f, rs1 = 0.f;
        #pragma unroll
        for (int nt = 0; nt < 8; nt++) {
            s[nt][0] = __expf(s[nt][0] - mn0);
            s[nt][1] = __expf(s[nt][1] - mn0);
            s[nt][2] = __expf(s[nt][2] - mn1);
            s[nt][3] = __expf(s[nt][3] - mn1);
            rs0 += s[nt][0] + s[nt][1];
            rs1 += s[nt][2] + s[nt][3];
        }
        rs0 += __shfl_xor_sync(0xffffffffu, rs0, 1);
        rs0 += __shfl_xor_sync(0xffffffffu, rs0, 2);
        rs1 += __shfl_xor_sync(0xffffffffu, rs1, 1);
        rs1 += __shfl_xor_sync(0xffffffffu, rs1, 2);
        l_i0 = l_i0 * sc0 + rs0;
        l_i1 = l_i1 * sc1 + rs1;
        #pragma unroll
        for (int nt = 0; nt < 8; nt++) {
            om[nt][0] *= sc0; om[nt][1] *= sc0;
            om[nt][2] *= sc1; om[nt][3] *= sc1;
        }

        // O += P V
        #pragma unroll
        for (int kc = 0; kc < 4; kc++) {
            uint32_t ph[4], pl[4];
            split2(s[2*kc][0],   s[2*kc][1],   ph[0], pl[0]);
            split2(s[2*kc][2],   s[2*kc][3],   ph[1], pl[1]);
            split2(s[2*kc+1][0], s[2*kc+1][1], ph[2], pl[2]);
            split2(s[2*kc+1][2], s[2*kc+1][3], ph[3], pl[3]);
            const int vm = lane >> 3, vr = lane & 7;
            #pragma unroll
            for (int hp = 0; hp < 4; hp++) {
                uint32_t vaddr = ((kc*16 + (vm & 1)*8 + vr)*FLS + hp*16 + (vm >> 1)*8) * 2;
                uint32_t vh4[4], vl4[4];
                ldm_x4_t(vh4, smb + FVHI*2 + vaddr);
                ldm_x4_t(vl4, smb + FVLO*2 + vaddr);
                float* o0 = om[hp*2];
                float* o1 = om[hp*2+1];
                mma16816(o0, ph, vh4[0], vh4[1]);
                mma16816(o0, pl, vh4[0], vh4[1]);
                mma16816(o0, ph, vl4[0], vl4[1]);
                mma16816(o1, ph, vh4[2], vh4[3]);
                mma16816(o1, pl, vh4[2], vh4[3]);
                mma16816(o1, ph, vl4[2], vl4[3]);
            }
        }
    }

    // write O (split bf16)
    float il0 = 1.f / l_i0, il1 = 1.f / l_i1;
    #pragma unroll
    for (int nt = 0; nt < 8; nt++) {
        int hd = nt*8 + (lane & 3)*2;
        uint32_t hi, lo;
        split2(om[nt][0]*il0, om[nt][1]*il0, hi, lo);
        *reinterpret_cast<uint32_t*>(oh + qoff + (size_t)qrow0*NC + hd) = hi;
        *reinterpret_cast<uint32_t*>(ol + qoff + (size_t)qrow0*NC + hd) = lo;
        split2(om[nt][2]*il1, om[nt][3]*il1, hi, lo);
        *reinterpret_cast<uint32_t*>(oh + qoff + (size_t)(qrow0+8)*NC + hd) = hi;
        *reinterpret_cast<uint32_t*>(ol + qoff + (size_t)(qrow0+8)*NC + hd) = lo;
    }
}

// ---------------------------------------------------------------------------
// Block reduction (256 threads)
// ---------------------------------------------------------------------------
__device__ __forceinline__ float2 block_reduce_sum2(float a, float b) {
    __shared__ float sha[8], shb[8];
    #pragma unroll
    for (int o = 16; o > 0; o >>= 1) {
        a += __shfl_xor_sync(0xffffffffu, a, o);
        b += __shfl_xor_sync(0xffffffffu, b, o);
    }
    int lane = threadIdx.x & 31, w = threadIdx.x >> 5;
    __syncthreads();
    if (lane == 0) { sha[w] = a; shb[w] = b; }
    __syncthreads();
    a = sha[lane & 7]; b = shb[lane & 7];
    #pragma unroll
    for (int o = 4; o > 0; o >>= 1) {
        a += __shfl_xor_sync(0xffffffffu, a, o);
        b += __shfl_xor_sync(0xffffffffu, b, o);
    }
    return make_float2(a, b);
}

__device__ __forceinline__ void store_split(__nv_bfloat16* hi, __nv_bfloat16* lo,
                                            size_t idx, float y) {
    __nv_bfloat16 hv = __float2bfloat16_rn(y);
    hi[idx] = hv;
    lo[idx] = __float2bfloat16_rn(y - __bfloat162float(hv));
}

// ---------------------------------------------------------------------------
// LN kernels (split-bf16 outputs)
// ---------------------------------------------------------------------------
__global__ void ln_comb_kernel(const float* __restrict__ fwd, const float* __restrict__ bwd,
                               const float* __restrict__ g, const float* __restrict__ bta,
                               float* __restrict__ comb,
                               __nv_bfloat16* __restrict__ cxh, __nv_bfloat16* __restrict__ cxl)
{
    int row = blockIdx.x;
    int b = row / NS, s = row % NS;
    const float* fp = fwd + ((size_t)b*(NS+1) + s) * NC;
    const float* rp = bwd + ((size_t)b*(NS+1) + s + 1) * NC;
    const float rs2 = 0.70710678118654752f;
    float vals[4];
    float sum = 0.f, sq = 0.f;
    #pragma unroll
    for (int t = 0; t < 4; t++) {
        int i = threadIdx.x + t*256;
        float c = (fp[i] + rp[i]) * rs2;
        vals[t] = c; sum += c; sq += c*c;
        comb[(size_t)row*NC + i] = c;
    }
    float2 r2 = block_reduce_sum2(sum, sq);
    float mean = r2.x * (1.f/NC);
    float var  = r2.y * (1.f/NC) - mean*mean;
    float rinv = rsqrtf(var + 1e-5f);
    #pragma unroll
    for (int t = 0; t < 4; t++) {
        int i = threadIdx.x + t*256;
        store_split(cxh, cxl, (size_t)row*NC + i, (vals[t] - mean) * rinv * g[i] + bta[i]);
    }
}

__global__ void ln_ae_kernel(const float* __restrict__ fwd, const float* __restrict__ bwd,
                             const float* __restrict__ g, const float* __restrict__ bta,
                             __nv_bfloat16* __restrict__ aeh, __nv_bfloat16* __restrict__ ael)
{
    int row = blockIdx.x;
    int b = row / (2*NS), t = row % (2*NS);
    const float* src = (t < NS) ? fwd + ((size_t)b*(NS+1) + t) * NC
                                : bwd + ((size_t)b*(NS+1) + (t - NS) + 1) * NC;
    float vals[4];
    float sum = 0.f, sq = 0.f;
    #pragma unroll
    for (int u = 0; u < 4; u++) {
        int i = threadIdx.x + u*256;
        float c = src[i];
        vals[u] = c; sum += c; sq += c*c;
    }
    float2 r2 = block_reduce_sum2(sum, sq);
    float mean = r2.x * (1.f/NC);
    float var  = r2.y * (1.f/NC) - mean*mean;
    float rinv = rsqrtf(var + 1e-5f);
    #pragma unroll
    for (int u = 0; u < 4; u++) {
        int i = threadIdx.x + u*256;
        store_split(aeh, ael, (size_t)row*NC + i, (vals[u] - mean) * rinv * g[i] + bta[i]);
    }
}

__global__ void double_ln_kernel(const float* __restrict__ xin,
                                 const float* __restrict__ g2, const float* __restrict__ b2,
                                 const float* __restrict__ gm, const float* __restrict__ bm,
                                 __nv_bfloat16* __restrict__ hh, __nv_bfloat16* __restrict__ hl)
{
    int row = blockIdx.x;
    const float* xp = xin + (size_t)row*NC;
    float vals[4];
    float s = 0.f, sq = 0.f;
    #pragma unroll
    for (int t = 0; t < 4; t++) {
        int i = threadIdx.x + t*256;
        float vv = xp[i];
        vals[t] = vv; s += vv; sq += vv*vv;
    }
    float2 r2 = block_reduce_sum2(s, sq);
    float mean = r2.x * (1.f/NC);
    float var  = r2.y * (1.f/NC) - mean*mean;
    float rinv = rsqrtf(var + 1e-5f);
    s = 0.f; sq = 0.f;
    #pragma unroll
    for (int t = 0; t < 4; t++) {
        int i = threadIdx.x + t*256;
        float y = (vals[t] - mean) * rinv * g2[i] + b2[i];
        vals[t] = y; s += y; sq += y*y;
    }
    r2 = block_reduce_sum2(s, sq);
    mean = r2.x * (1.f/NC);
    var  = r2.y * (1.f/NC) - mean*mean;
    rinv = rsqrtf(var + 1e-5f);
    #pragma unroll
    for (int t = 0; t < 4; t++) {
        int i = threadIdx.x + t*256;
        store_split(hh, hl, (size_t)row*NC + i, (vals[t] - mean) * rinv * gm[i] + bm[i]);
    }
}

// ---------------------------------------------------------------------------
// Launch
// ---------------------------------------------------------------------------
extern "C" void kernel_launch(void* const* d_in, const int* in_sizes, int n_in,
                              void* d_out, int out_size)
{
    (void)in_sizes; (void)n_in; (void)out_size;
    const float* fwd  = (const float*)d_in[0];
    const float* bwd  = (const float*)d_in[1];
    const float* pos  = (const float*)d_in[2];
    const float* ln1g = (const float*)d_in[3];
    const float* ln1b = (const float*)d_in[4];
    const float* Wq   = (const float*)d_in[5];
    const float* bq   = (const float*)d_in[6];
    const float* Wk   = (const float*)d_in[7];
    const float* bk   = (const float*)d_in[8];
    const float* Wv   = (const float*)d_in[9];
    const float* bv   = (const float*)d_in[10];
    const float* Wo   = (const float*)d_in[11];
    const float* bo   = (const float*)d_in[12];
    const float* ln2g = (const float*)d_in[13];
    const float* ln2b = (const float*)d_in[14];
    const float* mlpg = (const float*)d_in[15];
    const float* mlpb = (const float*)d_in[16];
    const float* W1   = (const float*)d_in[17];
    const float* b1   = (const float*)d_in[18];
    const float* W2   = (const float*)d_in[19];
    const float* b2   = (const float*)d_in[20];
    float* out = (float*)d_out;

    float *comb, *x;
    __nv_bfloat16 *cxh,*cxl,*aeh,*ael,*qh,*ql,*kh,*kl,*vh,*vl,*oh,*ol,*hh,*hl,*m1h,*m1l;
    __nv_bfloat16 *wthi, *wtlo;
    cudaGetSymbolAddress((void**)&comb, g_comb);
    cudaGetSymbolAddress((void**)&x,    g_x);
    cudaGetSymbolAddress((void**)&cxh,  g_cxh);  cudaGetSymbolAddress((void**)&cxl, g_cxl);
    cudaGetSymbolAddress((void**)&aeh,  g_aeh);  cudaGetSymbolAddress((void**)&ael, g_ael);
    cudaGetSymbolAddress((void**)&qh,   g_qh);   cudaGetSymbolAddress((void**)&ql,  g_ql);
    cudaGetSymbolAddress((void**)&kh,   g_kh);   cudaGetSymbolAddress((void**)&kl,  g_kl);
    cudaGetSymbolAddress((void**)&vh,   g_vh);   cudaGetSymbolAddress((void**)&vl,  g_vl);
    cudaGetSymbolAddress((void**)&oh,   g_oh);   cudaGetSymbolAddress((void**)&ol,  g_ol);
    cudaGetSymbolAddress((void**)&hh,   g_hh);   cudaGetSymbolAddress((void**)&hl,  g_hl);
    cudaGetSymbolAddress((void**)&m1h,  g_m1h);  cudaGetSymbolAddress((void**)&m1l, g_m1l);
    cudaGetSymbolAddress((void**)&wthi, g_wthi);
    cudaGetSymbolAddress((void**)&wtlo, g_wtlo);

    cudaFuncSetAttribute(mma_gemm<EPI_POS,true>,   cudaFuncAttributeMaxDynamicSharedMemorySize, MMA_SMEM_BYTES);
    cudaFuncSetAttribute(mma_gemm<EPI_BIAS,true>,  cudaFuncAttributeMaxDynamicSharedMemorySize, MMA_SMEM_BYTES);
    cudaFuncSetAttribute(mma_gemm<EPI_ADD,false>,  cudaFuncAttributeMaxDynamicSharedMemorySize, MMA_SMEM_BYTES);
    cudaFuncSetAttribute(mma_gemm<EPI_GELU,true>,  cudaFuncAttributeMaxDynamicSharedMemorySize, MMA_SMEM_BYTES);
    cudaFuncSetAttribute(flash_kernel,             cudaFuncAttributeMaxDynamicSharedMemorySize, FLASH_SMEM);

    // 0: weight transforms
    {
        dim3 blk(32, 8);
        wt_split_kernel<<<dim3(NC/32, NC/32), blk>>>(Wq, wthi + WT_Q, wtlo + WT_Q, NC, NC);
        wt_split_kernel<<<dim3(NC/32, NC/32), blk>>>(Wk, wthi + WT_K, wtlo + WT_K, NC, NC);
        wt_split_kernel<<<dim3(NC/32, NC/32), blk>>>(Wv, wthi + WT_V, wtlo + WT_V, NC, NC);
        wt_split_kernel<<<dim3(NC/32, NC/32), blk>>>(Wo, wthi + WT_O, wtlo + WT_O, NC, NC);
        wt_split_kernel<<<dim3((NE*NC)/32, NC/32), blk>>>(W1, wthi + WT_1, wtlo + WT_1, NC, NE*NC);
        wt_split_kernel<<<dim3(NC/32, (NE*NC)/32), blk>>>(W2, wthi + WT_2, wtlo + WT_2, NE*NC, NC);
    }

    // 1,2: LayerNorms (emit split bf16)
    ln_comb_kernel<<<NB*NS, 256>>>(fwd, bwd, ln1g, ln1b, comb, cxh, cxl);
    ln_ae_kernel<<<NB*2*NS, 256>>>(fwd, bwd, ln1g, ln1b, aeh, ael);

    // 3-5: Q,K,V projections (split-bf16 in and out)
    mma_gemm<EPI_POS,true><<<dim3(NC/128, (NB*NS)/128), 256, MMA_SMEM_BYTES>>>(
        cxh, cxl, NC, wthi + WT_Q, wtlo + WT_Q, nullptr, qh, ql, NC, NC, bq, pos, nullptr, 0.125f);
    mma_gemm<EPI_POS,true><<<dim3(NC/128, (NB*2*NS)/128), 256, MMA_SMEM_BYTES>>>(
        aeh, ael, NC, wthi + WT_K, wtlo + WT_K, nullptr, kh, kl, NC, NC, bk, pos, nullptr, 1.0f);
    mma_gemm<EPI_BIAS,true><<<dim3(NC/128, (NB*2*NS)/128), 256, MMA_SMEM_BYTES>>>(
        aeh, ael, NC, wthi + WT_V, wtlo + WT_V, nullptr, vh, vl, NC, NC, bv, nullptr, nullptr, 1.0f);

    // 6: fused flash attention
    flash_kernel<<<dim3(NS/64, NB*NH), 128, FLASH_SMEM>>>(qh, ql, kh, kl, vh, vl, oh, ol);

    // 7: x = comb + (o @ Wo + bo)
    mma_gemm<EPI_ADD,false><<<dim3(NC/128, (NB*NS)/128), 256, MMA_SMEM_BYTES>>>(
        oh, ol, NC, wthi + WT_O, wtlo + WT_O, x, nullptr, nullptr, NC, NC, bo, nullptr, comb, 1.0f);

    // 8: h = LN(LN(x)) (split out)
    double_ln_kernel<<<NB*NS, 256>>>(x, ln2g, ln2b, mlpg, mlpb, hh, hl);

    // 9: m1 = gelu(h @ W1 + b1) (split out)
    mma_gemm<EPI_GELU,true><<<dim3((NE*NC)/128, (NB*NS)/128), 256, MMA_SMEM_BYTES>>>(
        hh, hl, NC, wthi + WT_1, wtlo + WT_1, nullptr, m1h, m1l, NE*NC, NC, b1, nullptr, nullptr, 1.0f);

    // 10: out = x + (m1 @ W2 + b2)
    mma_gemm<EPI_ADD,false><<<dim3(NC/128, (NB*NS)/128), 256, MMA_SMEM_BYTES>>>(
        m1h, m1l, NE*NC, wthi + WT_2, wtlo + WT_2, out, nullptr, nullptr, NC, NE*NC, b2, nullptr, x, 1.0f);
}

// round 9
// speedup vs baseline: 2.7432x; 1.0674x over previous
#include <cuda_runtime.h>
#include <cuda_bf16.h>
#include <math.h>
#include <float.h>
#include <stdint.h>

// Problem constants
constexpr int NB = 2;
constexpr int NS = 1024;
constexpr int NC = 1024;
constexpr int NH = 16;
constexpr int HD = 64;
constexpr int NE = 4;

// ---------------------------------------------------------------------------
// Scratch (device globals)
// ---------------------------------------------------------------------------
__device__ float g_comb[NB*NS*NC];
__device__ float g_x   [NB*NS*NC];

__device__ __nv_bfloat16 g_cxh[NB*NS*NC],    g_cxl[NB*NS*NC];
__device__ __nv_bfloat16 g_aeh[NB*2*NS*NC],  g_ael[NB*2*NS*NC];
__device__ __nv_bfloat16 g_qh [NB*NS*NC],    g_ql [NB*NS*NC];
__device__ __nv_bfloat16 g_kh [NB*2*NS*NC],  g_kl [NB*2*NS*NC];
__device__ __nv_bfloat16 g_vh [NB*2*NS*NC],  g_vl [NB*2*NS*NC];
__device__ __nv_bfloat16 g_oh [NB*NS*NC],    g_ol [NB*NS*NC];
__device__ __nv_bfloat16 g_hh [NB*NS*NC],    g_hl [NB*NS*NC];
__device__ __nv_bfloat16 g_m1h[NB*NS*NE*NC], g_m1l[NB*NS*NE*NC];

__device__ __nv_bfloat16 g_wthi[12u<<20];
__device__ __nv_bfloat16 g_wtlo[12u<<20];
constexpr size_t WT_Q = 0;
constexpr size_t WT_K = (size_t)1<<20;
constexpr size_t WT_V = (size_t)2<<20;
constexpr size_t WT_O = (size_t)3<<20;
constexpr size_t WT_1 = (size_t)4<<20;
constexpr size_t WT_2 = (size_t)8<<20;

// ---------------------------------------------------------------------------
// Helpers
// ---------------------------------------------------------------------------
__device__ __forceinline__ uint32_t smem_u32(const void* p) {
    uint32_t a;
    asm("{ .reg .u64 t; cvta.to.shared.u64 t, %1; cvt.u32.u64 %0, t; }" : "=r"(a) : "l"(p));
    return a;
}
__device__ __forceinline__ uint32_t pack_bf(float a, float b) {
    __nv_bfloat162 h = __floats2bfloat162_rn(a, b);
    return *reinterpret_cast<uint32_t*>(&h);
}
__device__ __forceinline__ void split2(float a, float b, uint32_t& hi, uint32_t& lo) {
    __nv_bfloat16 ha = __float2bfloat16_rn(a);
    __nv_bfloat16 hb = __float2bfloat16_rn(b);
    hi = pack_bf(a, b);
    lo = pack_bf(a - __bfloat162float(ha), b - __bfloat162float(hb));
}
__device__ __forceinline__ void ldm_x4(uint32_t* r, uint32_t addr) {
    asm volatile("ldmatrix.sync.aligned.m8n8.x4.shared.b16 {%0,%1,%2,%3}, [%4];"
        : "=r"(r[0]), "=r"(r[1]), "=r"(r[2]), "=r"(r[3]) : "r"(addr));
}
__device__ __forceinline__ void ldm_x4_t(uint32_t* r, uint32_t addr) {
    asm volatile("ldmatrix.sync.aligned.m8n8.x4.trans.shared.b16 {%0,%1,%2,%3}, [%4];"
        : "=r"(r[0]), "=r"(r[1]), "=r"(r[2]), "=r"(r[3]) : "r"(addr));
}
__device__ __forceinline__ void mma16816(float* d, const uint32_t* a, uint32_t b0, uint32_t b1) {
    asm volatile(
        "mma.sync.aligned.m16n8k16.row.col.f32.bf16.bf16.f32 "
        "{%0,%1,%2,%3}, {%4,%5,%6,%7}, {%8,%9}, {%0,%1,%2,%3};"
        : "+f"(d[0]), "+f"(d[1]), "+f"(d[2]), "+f"(d[3])
        : "r"(a[0]), "r"(a[1]), "r"(a[2]), "r"(a[3]), "r"(b0), "r"(b1));
}
#define CP16(dst, src) \
    asm volatile("cp.async.cg.shared.global [%0], [%1], 16;" :: "r"(dst), "l"(src))
#define CP_COMMIT() asm volatile("cp.async.commit_group;")
#define CP_WAIT0()  asm volatile("cp.async.wait_group 0;")
#define CP_WAIT1()  asm volatile("cp.async.wait_group 1;")

// ---------------------------------------------------------------------------
// Merged weight transform: all 6 weights in one launch (range-decoded grid)
// ---------------------------------------------------------------------------
__global__ void wt_split_all(const float* __restrict__ Wq, const float* __restrict__ Wk,
                             const float* __restrict__ Wv, const float* __restrict__ Wo,
                             const float* __restrict__ W1, const float* __restrict__ W2,
                             __nv_bfloat16* __restrict__ hi_base,
                             __nv_bfloat16* __restrict__ lo_base)
{
    int z = blockIdx.x;
    const float* W; size_t off; int K, N, bx, by;
    if (z < 1024)      { W = Wq; off = WT_Q; K = 1024; N = 1024; bx = z & 31;  by = z >> 5; }
    else if (z < 2048) { int i = z - 1024; W = Wk; off = WT_K; K = 1024; N = 1024; bx = i & 31; by = i >> 5; }
    else if (z < 3072) { int i = z - 2048; W = Wv; off = WT_V; K = 1024; N = 1024; bx = i & 31; by = i >> 5; }
    else if (z < 4096) { int i = z - 3072; W = Wo; off = WT_O; K = 1024; N = 1024; bx = i & 31; by = i >> 5; }
    else if (z < 8192) { int i = z - 4096; W = W1; off = WT_1; K = 1024; N = 4096; bx = i & 127; by = i >> 7; }
    else               { int i = z - 8192; W = W2; off = WT_2; K = 4096; N = 1024; bx = i & 31;  by = i >> 5; }
    __nv_bfloat16* hi = hi_base + off;
    __nv_bfloat16* lo = lo_base + off;

    __shared__ float t[32][33];
    int n0 = bx * 32, k0 = by * 32;
    #pragma unroll
    for (int i = 0; i < 4; i++) {
        int k = k0 + threadIdx.y + 8*i;
        t[threadIdx.y + 8*i][threadIdx.x] = W[(size_t)k*N + n0 + threadIdx.x];
    }
    __syncthreads();
    #pragma unroll
    for (int i = 0; i < 4; i++) {
        int n = n0 + threadIdx.y + 8*i;
        int k = k0 + threadIdx.x;
        float v = t[threadIdx.x][threadIdx.y + 8*i];
        __nv_bfloat16 h = __float2bfloat16_rn(v);
        __nv_bfloat16 l = __float2bfloat16_rn(v - __bfloat162float(h));
        hi[(size_t)n*K + k] = h;
        lo[(size_t)n*K + k] = l;
    }
}

// ---------------------------------------------------------------------------
// GEMM core (shared by all MMA kernels). BM in {128, 64}; 256 threads.
// ---------------------------------------------------------------------------
constexpr int BLDS = 40;     // smem row stride (bf16): 80B, conflict-free ldmatrix

template<int BM> __host__ __device__ constexpr int NACC_OF() { return 2 * ((128 / (8 / (BM/32))) / 16); }
template<int BM> __host__ __device__ constexpr int SSZ_OF()  { return 2*BM*BLDS + 2*128*BLDS; }
template<int BM> __host__ __device__ constexpr int SMEM_OF() { return 2 * SSZ_OF<BM>() * 2; }

template<int BM, int NACC>
__device__ __forceinline__ void gemm_core(
    const __nv_bfloat16* __restrict__ Ahi, const __nv_bfloat16* __restrict__ Alo, int lda,
    const __nv_bfloat16* __restrict__ Bhi, const __nv_bfloat16* __restrict__ Blo, int K,
    int tileM, int tileN, uint32_t smb, float (&acc)[2][NACC][4])
{
    constexpr int WMW = BM/32;
    constexpr int WNW = 8/WMW;
    constexpr int NSPAN = 128/WNW;
    constexpr int NTP = NSPAN/16;
    static_assert(NACC == 2*NTP, "acc shape");
    constexpr int ASZ = BM*BLDS;
    constexpr int BSZ = 128*BLDS;
    constexpr int SSZ = 2*ASZ + 2*BSZ;

    const int tid = threadIdx.x, lane = tid & 31, wid = tid >> 5;
    const int wm = wid / WNW, wn = wid % WNW;
    const int a_row = wm*32 + (lane & 15);
    const int b_row = wn*NSPAN + (lane & 15);
    const int half8 = (lane >> 4) << 3;

    const int sr0 = tid >> 2, sc0 = (tid & 3) * 8;
    const int nch = K >> 5;

    // prologue: stage 0
    {
        #pragma unroll
        for (int p = 0; p < BM/64; p++) {
            int r = sr0 + p*64;
            uint32_t so = (r*BLDS + sc0) * 2;
            size_t ga = (size_t)(tileM + r)*lda + sc0;
            CP16(smb + so,           Ahi + ga);
            CP16(smb + ASZ*2 + so,   Alo + ga);
        }
        #pragma unroll
        for (int p = 0; p < 2; p++) {
            int r = sr0 + p*64;
            uint32_t so = (r*BLDS + sc0) * 2;
            size_t ga = (size_t)(tileN + r)*K + sc0;
            CP16(smb + 2*ASZ*2 + so,         Bhi + ga);
            CP16(smb + (2*ASZ+BSZ)*2 + so,   Blo + ga);
        }
        CP_COMMIT();
    }

    for (int c = 0; c < nch; c++) {
        const int st = c & 1;
        if (c + 1 < nch) {
            const int k0 = (c + 1) << 5;
            const uint32_t sb2 = smb + (uint32_t)((st ^ 1) * SSZ * 2);
            #pragma unroll
            for (int p = 0; p < BM/64; p++) {
                int r = sr0 + p*64;
                uint32_t so = (r*BLDS + sc0) * 2;
                size_t ga = (size_t)(tileM + r)*lda + k0 + sc0;
                CP16(sb2 + so,         Ahi + ga);
                CP16(sb2 + ASZ*2 + so, Alo + ga);
            }
            #pragma unroll
            for (int p = 0; p < 2; p++) {
                int r = sr0 + p*64;
                uint32_t so = (r*BLDS + sc0) * 2;
                size_t ga = (size_t)(tileN + r)*K + k0 + sc0;
                CP16(sb2 + 2*ASZ*2 + so,       Bhi + ga);
                CP16(sb2 + (2*ASZ+BSZ)*2 + so, Blo + ga);
            }
            CP_COMMIT();
            CP_WAIT1();
        } else {
            CP_WAIT0();
        }
        __syncthreads();

        const uint32_t sbase = smb + (uint32_t)(st * SSZ * 2);
        #pragma unroll
        for (int ks = 0; ks < 32; ks += 16) {
            uint32_t ahi[2][4], alo[2][4];
            #pragma unroll
            for (int mt = 0; mt < 2; mt++) {
                uint32_t off = ((a_row + mt*16)*BLDS + ks + half8) * 2;
                ldm_x4(ahi[mt], sbase + off);
                ldm_x4(alo[mt], sbase + ASZ*2 + off);
            }
            #pragma unroll
            for (int ntp = 0; ntp < NTP; ntp++) {
                uint32_t off = ((b_row + ntp*16)*BLDS + ks + half8) * 2;
                uint32_t bh[4], bl[4];
                ldm_x4(bh, sbase + 2*ASZ*2 + off);
                ldm_x4(bl, sbase + (2*ASZ+BSZ)*2 + off);
                #pragma unroll
                for (int mt = 0; mt < 2; mt++) {
                    float* a0 = acc[mt][ntp*2];
                    float* a1 = acc[mt][ntp*2+1];
                    mma16816(a0, ahi[mt], bh[0], bh[2]);
                    mma16816(a0, ahi[mt], bl[0], bl[2]);
                    mma16816(a0, alo[mt], bh[0], bh[2]);
                    mma16816(a1, ahi[mt], bh[1], bh[3]);
                    mma16816(a1, ahi[mt], bl[1], bl[3]);
                    mma16816(a1, alo[mt], bh[1], bh[3]);
                }
            }
        }
        __syncthreads();
    }
}

// ---------------------------------------------------------------------------
// Generic GEMM kernel (Wo / W1 / W2 paths)
// ---------------------------------------------------------------------------
enum { EPI_ADD = 3, EPI_GELU = 4 };

template<int BM, int EPI, bool SPLITOUT>
__global__ __launch_bounds__(256, 2)
void mma_gemm(const __nv_bfloat16* __restrict__ Ahi, const __nv_bfloat16* __restrict__ Alo,
              int lda,
              const __nv_bfloat16* __restrict__ Bhi, const __nv_bfloat16* __restrict__ Blo,
              float* __restrict__ C,
              __nv_bfloat16* __restrict__ Chi, __nv_bfloat16* __restrict__ Clo,
              int ldc, int K,
              const float* __restrict__ bias,
              const float* __restrict__ addm)
{
    extern __shared__ __nv_bfloat16 sm[];
    const uint32_t smb = smem_u32(sm);
    constexpr int NACC = NACC_OF<BM>();
    constexpr int WMW = BM/32;
    constexpr int WNW = 8/WMW;
    constexpr int NSPAN = 128/WNW;

    const int lane = threadIdx.x & 31, wid = threadIdx.x >> 5;
    const int wm = wid / WNW, wn = wid % WNW;
    const int tileM = blockIdx.y * BM;
    const int tileN = blockIdx.x * 128;

    float acc[2][NACC][4];
    #pragma unroll
    for (int i = 0; i < 2; i++)
        #pragma unroll
        for (int j = 0; j < NACC; j++)
            #pragma unroll
            for (int q = 0; q < 4; q++) acc[i][j][q] = 0.f;

    gemm_core<BM, NACC>(Ahi, Alo, lda, Bhi, Blo, K, tileM, tileN, smb, acc);

    #pragma unroll
    for (int mt = 0; mt < 2; mt++) {
        #pragma unroll
        for (int nt = 0; nt < NACC; nt++) {
            int gm = tileM + wm*32 + mt*16 + (lane >> 2);
            int gn = tileN + wn*NSPAN + nt*8 + (lane & 3)*2;
            #pragma unroll
            for (int half = 0; half < 2; half++) {
                int gmr = gm + half*8;
                float v0 = acc[mt][nt][half*2], v1 = acc[mt][nt][half*2+1];
                if (EPI == EPI_ADD) {
                    float2 am = *reinterpret_cast<const float2*>(addm + (size_t)gmr*ldc + gn);
                    v0 += bias[gn] + am.x; v1 += bias[gn+1] + am.y;
                } else if (EPI == EPI_GELU) {
                    float t0 = v0 + bias[gn], t1 = v1 + bias[gn+1];
                    v0 = 0.5f*t0*(1.f + erff(t0*0.70710678118654752f));
                    v1 = 0.5f*t1*(1.f + erff(t1*0.70710678118654752f));
                }
                if (SPLITOUT) {
                    uint32_t hi, lo;
                    split2(v0, v1, hi, lo);
                    *reinterpret_cast<uint32_t*>(Chi + (size_t)gmr*ldc + gn) = hi;
                    *reinterpret_cast<uint32_t*>(Clo + (size_t)gmr*ldc + gn) = lo;
                } else {
                    *reinterpret_cast<float2*>(C + (size_t)gmr*ldc + gn) = make_float2(v0, v1);
                }
            }
        }
    }
}

// ---------------------------------------------------------------------------
// Fused QKV GEMM: 640 CTAs (0..127 Q: 16Mx8N tiles; 128..639 KV: 32Mx16N tiles)
// ---------------------------------------------------------------------------
__global__ __launch_bounds__(256, 2)
void mma_qkv(const __nv_bfloat16* __restrict__ cxh, const __nv_bfloat16* __restrict__ cxl,
             const __nv_bfloat16* __restrict__ aeh, const __nv_bfloat16* __restrict__ ael,
             const __nv_bfloat16* __restrict__ wthi, const __nv_bfloat16* __restrict__ wtlo,
             __nv_bfloat16* __restrict__ qh, __nv_bfloat16* __restrict__ ql,
             __nv_bfloat16* __restrict__ kh, __nv_bfloat16* __restrict__ kl,
             __nv_bfloat16* __restrict__ vh, __nv_bfloat16* __restrict__ vl,
             const float* __restrict__ bq, const float* __restrict__ bk,
             const float* __restrict__ bv, const float* __restrict__ pos)
{
    extern __shared__ __nv_bfloat16 sm[];
    const uint32_t smb = smem_u32(sm);

    const int bz = blockIdx.x;
    const bool isQ = bz < 128;
    const __nv_bfloat16 *Ah, *Al, *Bh, *Bl;
    int tileM, tileN;
    if (isQ) {
        int nx = bz & 7, ny = bz >> 3;           // 8 col-tiles x 16 row-tiles (2048 rows)
        tileM = ny * 128; tileN = nx * 128;
        Ah = cxh; Al = cxl; Bh = wthi + WT_Q; Bl = wtlo + WT_Q;
    } else {
        int i = bz - 128;                         // 512 CTAs
        int nx = i & 15, ny = i >> 4;             // 16 col-tiles (K|V) x 32 row-tiles (4096 rows)
        tileM = ny * 128; tileN = nx * 128;
        Ah = aeh; Al = ael; Bh = wthi + WT_K; Bl = wtlo + WT_K;
    }

    const int lane = threadIdx.x & 31, wid = threadIdx.x >> 5;
    const int wm = wid >> 1, wn = wid & 1;

    float acc[2][8][4];
    #pragma unroll
    for (int i = 0; i < 2; i++)
        #pragma unroll
        for (int j = 0; j < 8; j++)
            #pragma unroll
            for (int q = 0; q < 4; q++) acc[i][j][q] = 0.f;

    gemm_core<128, 8>(Ah, Al, NC, Bh, Bl, NC, tileM, tileN, smb, acc);

    #pragma unroll
    for (int mt = 0; mt < 2; mt++) {
        #pragma unroll
        for (int nt = 0; nt < 8; nt++) {
            int gm = tileM + wm*32 + mt*16 + (lane >> 2);
            int gn = tileN + wn*64 + nt*8 + (lane & 3)*2;
            #pragma unroll
            for (int half = 0; half < 2; half++) {
                int gmr = gm + half*8;
                float v0 = acc[mt][nt][half*2], v1 = acc[mt][nt][half*2+1];
                const float* pr = pos + (gmr % NS)*HD;
                uint32_t hi, lo;
                if (isQ) {
                    v0 = (v0 + bq[gn]   + pr[gn & (HD-1)])     * 0.125f;
                    v1 = (v1 + bq[gn+1] + pr[(gn+1) & (HD-1)]) * 0.125f;
                    split2(v0, v1, hi, lo);
                    *reinterpret_cast<uint32_t*>(qh + (size_t)gmr*NC + gn) = hi;
                    *reinterpret_cast<uint32_t*>(ql + (size_t)gmr*NC + gn) = lo;
                } else if (gn < NC) {
                    v0 = v0 + bk[gn]   + pr[gn & (HD-1)];
                    v1 = v1 + bk[gn+1] + pr[(gn+1) & (HD-1)];
                    split2(v0, v1, hi, lo);
                    *reinterpret_cast<uint32_t*>(kh + (size_t)gmr*NC + gn) = hi;
                    *reinterpret_cast<uint32_t*>(kl + (size_t)gmr*NC + gn) = lo;
                } else {
                    int gv = gn - NC;
                    v0 += bv[gv]; v1 += bv[gv+1];
                    split2(v0, v1, hi, lo);
                    *reinterpret_cast<uint32_t*>(vh + (size_t)gmr*NC + gv) = hi;
                    *reinterpret_cast<uint32_t*>(vl + (size_t)gmr*NC + gv) = lo;
                }
            }
        }
    }
}

// ---------------------------------------------------------------------------
// Flash attention
// ---------------------------------------------------------------------------
constexpr int FLS  = 72;
constexpr int FQHI = 0;
constexpr int FQLO = 64*FLS;
constexpr int FKHI = 2*64*FLS;
constexpr int FKLO = 3*64*FLS;
constexpr int FVHI = 4*64*FLS;
constexpr int FVLO = 5*64*FLS;
constexpr int FLASH_SMEM = 6*64*FLS*2;

__global__ __launch_bounds__(128)
void flash_kernel(const __nv_bfloat16* __restrict__ qh, const __nv_bfloat16* __restrict__ ql,
                  const __nv_bfloat16* __restrict__ kh, const __nv_bfloat16* __restrict__ kl,
                  const __nv_bfloat16* __restrict__ vh, const __nv_bfloat16* __restrict__ vl,
                  __nv_bfloat16* __restrict__ oh, __nv_bfloat16* __restrict__ ol)
{
    extern __shared__ __nv_bfloat16 sf[];
    const uint32_t smb = smem_u32(sf);
    const int tid = threadIdx.x, lane = tid & 31, wid = tid >> 5;
    const int bh = blockIdx.y, b = bh >> 4, h = bh & 15;
    const int q0 = blockIdx.x * 64;
    const size_t qoff = (size_t)b*NS*NC   + h*HD;
    const size_t koff = (size_t)b*2*NS*NC + h*HD;

    {
        const int r = tid >> 1, c8 = (tid & 1) * 8;
        #pragma unroll
        for (int i = 0; i < 4; i++) {
            int cc = c8 + i*16;
            size_t ga = qoff + (size_t)(q0 + r)*NC + cc;
            uint32_t so = (r*FLS + cc) * 2;
            CP16(smb + FQHI*2 + so, qh + ga);
            CP16(smb + FQLO*2 + so, ql + ga);
        }
        CP_COMMIT(); CP_WAIT0();
    }
    __syncthreads();

    const int arow = wid*16 + (lane & 15);
    const int half8 = (lane >> 4) << 3;
    uint32_t qhi4[4][4], qlo4[4][4];
    #pragma unroll
    for (int kc = 0; kc < 4; kc++) {
        uint32_t off = (arow*FLS + kc*16 + half8) * 2;
        ldm_x4(qhi4[kc], smb + FQHI*2 + off);
        ldm_x4(qlo4[kc], smb + FQLO*2 + off);
    }

    float om[8][4];
    #pragma unroll
    for (int i = 0; i < 8; i++)
        #pragma unroll
        for (int j = 0; j < 4; j++) om[i][j] = 0.f;
    float m_i0 = -1e30f, m_i1 = -1e30f, l_i0 = 0.f, l_i1 = 0.f;

    const int qrow0 = q0 + wid*16 + (lane >> 2);

    for (int kt = 0; kt < 32; kt++) {
        const int kg0 = kt * 64;
        const bool fwdh = kg0 < 1024;
        if (fwdh) { if (kg0 > q0 + 63) continue; }
        else      { if (kg0 - 1024 + 63 < q0) continue; }
        const bool full = fwdh ? (kg0 + 63 <= q0) : (kg0 - 1024 >= q0 + 63);

        __syncthreads();
        {
            const int r = tid >> 1, c8 = (tid & 1) * 8;
            #pragma unroll
            for (int i = 0; i < 4; i++) {
                int cc = c8 + i*16;
                size_t ga = koff + (size_t)(kg0 + r)*NC + cc;
                uint32_t so = (r*FLS + cc) * 2;
                CP16(smb + FKHI*2 + so, kh + ga);
                CP16(smb + FKLO*2 + so, kl + ga);
                CP16(smb + FVHI*2 + so, vh + ga);
                CP16(smb + FVLO*2 + so, vl + ga);
            }
            CP_COMMIT(); CP_WAIT0();
        }
        __syncthreads();

        float s[8][4];
        #pragma unroll
        for (int i = 0; i < 8; i++)
            #pragma unroll
            for (int j = 0; j < 4; j++) s[i][j] = 0.f;
        #pragma unroll
        for (int kc = 0; kc < 4; kc++) {
            #pragma unroll
            for (int np = 0; np < 4; np++) {
                uint32_t off = ((np*16 + (lane & 15))*FLS + kc*16 + half8) * 2;
                uint32_t bh4[4], bl4[4];
                ldm_x4(bh4, smb + FKHI*2 + off);
                ldm_x4(bl4, smb + FKLO*2 + off);
                float* s0 = s[np*2];
                float* s1 = s[np*2+1];
                mma16816(s0, qhi4[kc], bh4[0], bh4[2]);
                mma16816(s0, qhi4[kc], bl4[0], bl4[2]);
                mma16816(s0, qlo4[kc], bh4[0], bh4[2]);
                mma16816(s1, qhi4[kc], bh4[1], bh4[3]);
                mma16816(s1, qhi4[kc], bl4[1], bl4[3]);
                mma16816(s1, qlo4[kc], bh4[1], bh4[3]);
            }
        }

        if (!full) {
            #pragma unroll
            for (int nt = 0; nt < 8; nt++) {
                int kbase = kg0 + nt*8 + (lane & 3)*2;
                #pragma unroll
                for (int d = 0; d < 2; d++) {
                    int kidx = kbase + d;
                    bool ok0, ok1;
                    if (fwdh) { ok0 = (kidx <= qrow0); ok1 = (kidx <= qrow0 + 8); }
                    else      { int j = kidx - 1024; ok0 = (j >= qrow0); ok1 = (j >= qrow0 + 8); }
                    if (!ok0) s[nt][d]     = -1e30f;
                    if (!ok1) s[nt][d + 2] = -1e30f;
                }
            }
        }

        float mx0 = -1e30f, mx1 = -1e30f;
        #pragma unroll
        for (int nt = 0; nt < 8; nt++) {
            mx0 = fmaxf(mx0, fmaxf(s[nt][0], s[nt][1]));
            mx1 = fmaxf(mx1, fmaxf(s[nt][2], s[nt][3]));
        }
        mx0 = fmaxf(mx0, __shfl_xor_sync(0xffffffffu, mx0, 1));
        mx0 = fmaxf(mx0, __shfl_xor_sync(0xffffffffu, mx0, 2));
        mx1 = fmaxf(mx1, __shfl_xor_sync(0xffffffffu, mx1, 1));
        mx1 = fmaxf(mx1, __shfl_xor_sync(0xffffffffu, mx1, 2));
        float mn0 = fmaxf(m_i0, mx0), mn1 = fmaxf(m_i1, mx1);
        float sc0 = __expf(m_i0 - mn0), sc1 = __expf(m_i1 - mn1);
        m_i0 = mn0; m_i1 = mn1;
        float rs0 = 0.f, rs1 = 0.f;
        #pragma unroll
        for (int nt = 0; nt < 8; nt++) {
            s[nt][0] = __expf(s[nt][0] - mn0);
            s[nt][1] = __expf(s[nt][1] - mn0);
            s[nt][2] = __expf(s[nt][2] - mn1);
            s[nt][3] = __expf(s[nt][3] - mn1);
            rs0 += s[nt][0] + s[nt][1];
            rs1 += s[nt][2] + s[nt][3];
        }
        rs0 += __shfl_xor_sync(0xffffffffu, rs0, 1);
        rs0 += __shfl_xor_sync(0xffffffffu, rs0, 2);
        rs1 += __shfl_xor_sync(0xffffffffu, rs1, 1);
        rs1 += __shfl_xor_sync(0xffffffffu, rs1, 2);
        l_i0 = l_i0 * sc0 + rs0;
        l_i1 = l_i1 * sc1 + rs1;
        #pragma unroll
        for (int nt = 0; nt < 8; nt++) {
            om[nt][0] *= sc0; om[nt][1] *= sc0;
            om[nt][2] *= sc1; om[nt][3] *= sc1;
        }

        #pragma unroll
        for (int kc = 0; kc < 4; kc++) {
            uint32_t ph[4], pl[4];
            split2(s[2*kc][0],   s[2*kc][1],   ph[0], pl[0]);
            split2(s[2*kc][2],   s[2*kc][3],   ph[1], pl[1]);
            split2(s[2*kc+1][0], s[2*kc+1][1], ph[2], pl[2]);
            split2(s[2*kc+1][2], s[2*kc+1][3], ph[3], pl[3]);
            const int vm = lane >> 3, vr = lane & 7;
            #pragma unroll
            for (int hp = 0; hp < 4; hp++) {
                uint32_t vaddr = ((kc*16 + (vm & 1)*8 + vr)*FLS + hp*16 + (vm >> 1)*8) * 2;
                uint32_t vh4[4], vl4[4];
                ldm_x4_t(vh4, smb + FVHI*2 + vaddr);
                ldm_x4_t(vl4, smb + FVLO*2 + vaddr);
                float* o0 = om[hp*2];
                float* o1 = om[hp*2+1];
                mma16816(o0, ph, vh4[0], vh4[1]);
                mma16816(o0, pl, vh4[0], vh4[1]);
                mma16816(o0, ph, vl4[0], vl4[1]);
                mma16816(o1, ph, vh4[2], vh4[3]);
                mma16816(o1, pl, vh4[2], vh4[3]);
                mma16816(o1, ph, vl4[2], vl4[3]);
            }
        }
    }

    float il0 = 1.f / l_i0, il1 = 1.f / l_i1;
    #pragma unroll
    for (int nt = 0; nt < 8; nt++) {
        int hd = nt*8 + (lane & 3)*2;
        uint32_t hi, lo;
        split2(om[nt][0]*il0, om[nt][1]*il0, hi, lo);
        *reinterpret_cast<uint32_t*>(oh + qoff + (size_t)qrow0*NC + hd) = hi;
        *reinterpret_cast<uint32_t*>(ol + qoff + (size_t)qrow0*NC + hd) = lo;
        split2(om[nt][2]*il1, om[nt][3]*il1, hi, lo);
        *reinterpret_cast<uint32_t*>(oh + qoff + (size_t)(qrow0+8)*NC + hd) = hi;
        *reinterpret_cast<uint32_t*>(ol + qoff + (size_t)(qrow0+8)*NC + hd) = lo;
    }
}

// ---------------------------------------------------------------------------
// Block reduction + LN kernels
// ---------------------------------------------------------------------------
__device__ __forceinline__ float2 block_reduce_sum2(float a, float b) {
    __shared__ float sha[8], shb[8];
    #pragma unroll
    for (int o = 16; o > 0; o >>= 1) {
        a += __shfl_xor_sync(0xffffffffu, a, o);
        b += __shfl_xor_sync(0xffffffffu, b, o);
    }
    int lane = threadIdx.x & 31, w = threadIdx.x >> 5;
    __syncthreads();
    if (lane == 0) { sha[w] = a; shb[w] = b; }
    __syncthreads();
    a = sha[lane & 7]; b = shb[lane & 7];
    #pragma unroll
    for (int o = 4; o > 0; o >>= 1) {
        a += __shfl_xor_sync(0xffffffffu, a, o);
        b += __shfl_xor_sync(0xffffffffu, b, o);
    }
    return make_float2(a, b);
}

__device__ __forceinline__ void store_split(__nv_bfloat16* hi, __nv_bfloat16* lo,
                                            size_t idx, float y) {
    __nv_bfloat16 hv = __float2bfloat16_rn(y);
    hi[idx] = hv;
    lo[idx] = __float2bfloat16_rn(y - __bfloat162float(hv));
}

// Merged LN: blocks [0, NB*NS) -> comb+cx ; [NB*NS, NB*NS+NB*2*NS) -> ae
__global__ void ln_all(const float* __restrict__ fwd, const float* __restrict__ bwd,
                       const float* __restrict__ g, const float* __restrict__ bta,
                       float* __restrict__ comb,
                       __nv_bfloat16* __restrict__ cxh, __nv_bfloat16* __restrict__ cxl,
                       __nv_bfloat16* __restrict__ aeh, __nv_bfloat16* __restrict__ ael)
{
    int z = blockIdx.x;
    if (z < NB*NS) {
        int row = z;
        int b = row / NS, s = row % NS;
        const float* fp = fwd + ((size_t)b*(NS+1) + s) * NC;
        const float* rp = bwd + ((size_t)b*(NS+1) + s + 1) * NC;
        const float rs2 = 0.70710678118654752f;
        float vals[4];
        float sum = 0.f, sq = 0.f;
        #pragma unroll
        for (int t = 0; t < 4; t++) {
            int i = threadIdx.x + t*256;
            float c = (fp[i] + rp[i]) * rs2;
            vals[t] = c; sum += c; sq += c*c;
            comb[(size_t)row*NC + i] = c;
        }
        float2 r2 = block_reduce_sum2(sum, sq);
        float mean = r2.x * (1.f/NC);
        float var  = r2.y * (1.f/NC) - mean*mean;
        float rinv = rsqrtf(var + 1e-5f);
        #pragma unroll
        for (int t = 0; t < 4; t++) {
            int i = threadIdx.x + t*256;
            store_split(cxh, cxl, (size_t)row*NC + i, (vals[t] - mean) * rinv * g[i] + bta[i]);
        }
    } else {
        int row = z - NB*NS;
        int b = row / (2*NS), t = row % (2*NS);
        const float* src = (t < NS) ? fwd + ((size_t)b*(NS+1) + t) * NC
                                    : bwd + ((size_t)b*(NS+1) + (t - NS) + 1) * NC;
        float vals[4];
        float sum = 0.f, sq = 0.f;
        #pragma unroll
        for (int u = 0; u < 4; u++) {
            int i = threadIdx.x + u*256;
            float c = src[i];
            vals[u] = c; sum += c; sq += c*c;
        }
        float2 r2 = block_reduce_sum2(sum, sq);
        float mean = r2.x * (1.f/NC);
        float var  = r2.y * (1.f/NC) - mean*mean;
        float rinv = rsqrtf(var + 1e-5f);
        #pragma unroll
        for (int u = 0; u < 4; u++) {
            int i = threadIdx.x + u*256;
            store_split(aeh, ael, (size_t)row*NC + i, (vals[u] - mean) * rinv * g[i] + bta[i]);
        }
    }
}

__global__ void double_ln_kernel(const float* __restrict__ xin,
                                 const float* __restrict__ g2, const float* __restrict__ b2,
                                 const float* __restrict__ gm, const float* __restrict__ bm,
                                 __nv_bfloat16* __restrict__ hh, __nv_bfloat16* __restrict__ hl)
{
    int row = blockIdx.x;
    const float* xp = xin + (size_t)row*NC;
    float vals[4];
    float s = 0.f, sq = 0.f;
    #pragma unroll
    for (int t = 0; t < 4; t++) {
        int i = threadIdx.x + t*256;
        float vv = xp[i];
        vals[t] = vv; s += vv; sq += vv*vv;
    }
    float2 r2 = block_reduce_sum2(s, sq);
    float mean = r2.x * (1.f/NC);
    float var  = r2.y * (1.f/NC) - mean*mean;
    float rinv = rsqrtf(var + 1e-5f);
    s = 0.f; sq = 0.f;
    #pragma unroll
    for (int t = 0; t < 4; t++) {
        int i = threadIdx.x + t*256;
        float y = (vals[t] - mean) * rinv * g2[i] + b2[i];
        vals[t] = y; s += y; sq += y*y;
    }
    r2 = block_reduce_sum2(s, sq);
    mean = r2.x * (1.f/NC);
    var  = r2.y * (1.f/NC) - mean*mean;
    rinv = rsqrtf(var + 1e-5f);
    #pragma unroll
    for (int t = 0; t < 4; t++) {
        int i = threadIdx.x + t*256;
        store_split(hh, hl, (size_t)row*NC + i, (vals[t] - mean) * rinv * gm[i] + bm[i]);
    }
}

// ---------------------------------------------------------------------------
// Launch
// ---------------------------------------------------------------------------
extern "C" void kernel_launch(void* const* d_in, const int* in_sizes, int n_in,
                              void* d_out, int out_size)
{
    (void)in_sizes; (void)n_in; (void)out_size;
    const float* fwd  = (const float*)d_in[0];
    const float* bwd  = (const float*)d_in[1];
    const float* pos  = (const float*)d_in[2];
    const float* ln1g = (const float*)d_in[3];
    const float* ln1b = (const float*)d_in[4];
    const float* Wq   = (const float*)d_in[5];
    const float* bq   = (const float*)d_in[6];
    const float* Wk   = (const float*)d_in[7];
    const float* bk   = (const float*)d_in[8];
    const float* Wv   = (const float*)d_in[9];
    const float* bv   = (const float*)d_in[10];
    const float* Wo   = (const float*)d_in[11];
    const float* bo   = (const float*)d_in[12];
    const float* ln2g = (const float*)d_in[13];
    const float* ln2b = (const float*)d_in[14];
    const float* mlpg = (const float*)d_in[15];
    const float* mlpb = (const float*)d_in[16];
    const float* W1   = (const float*)d_in[17];
    const float* b1   = (const float*)d_in[18];
    const float* W2   = (const float*)d_in[19];
    const float* b2   = (const float*)d_in[20];
    float* out = (float*)d_out;

    float *comb, *x;
    __nv_bfloat16 *cxh,*cxl,*aeh,*ael,*qh,*ql,*kh,*kl,*vh,*vl,*oh,*ol,*hh,*hl,*m1h,*m1l;
    __nv_bfloat16 *wthi, *wtlo;
    cudaGetSymbolAddress((void**)&comb, g_comb);
    cudaGetSymbolAddress((void**)&x,    g_x);
    cudaGetSymbolAddress((void**)&cxh,  g_cxh);  cudaGetSymbolAddress((void**)&cxl, g_cxl);
    cudaGetSymbolAddress((void**)&aeh,  g_aeh);  cudaGetSymbolAddress((void**)&ael, g_ael);
    cudaGetSymbolAddress((void**)&qh,   g_qh);   cudaGetSymbolAddress((void**)&ql,  g_ql);
    cudaGetSymbolAddress((void**)&kh,   g_kh);   cudaGetSymbolAddress((void**)&kl,  g_kl);
    cudaGetSymbolAddress((void**)&vh,   g_vh);   cudaGetSymbolAddress((void**)&vl,  g_vl);
    cudaGetSymbolAddress((void**)&oh,   g_oh);   cudaGetSymbolAddress((void**)&ol,  g_ol);
    cudaGetSymbolAddress((void**)&hh,   g_hh);   cudaGetSymbolAddress((void**)&hl,  g_hl);
    cudaGetSymbolAddress((void**)&m1h,  g_m1h);  cudaGetSymbolAddress((void**)&m1l, g_m1l);
    cudaGetSymbolAddress((void**)&wthi, g_wthi);
    cudaGetSymbolAddress((void**)&wtlo, g_wtlo);

    constexpr int SM128 = SMEM_OF<128>();   // 81920
    constexpr int SM64  = SMEM_OF<64>();    // 61440
    cudaFuncSetAttribute(mma_qkv,                      cudaFuncAttributeMaxDynamicSharedMemorySize, SM128);
    cudaFuncSetAttribute(mma_gemm<64,EPI_ADD,false>,   cudaFuncAttributeMaxDynamicSharedMemorySize, SM64);
    cudaFuncSetAttribute(mma_gemm<128,EPI_GELU,true>,  cudaFuncAttributeMaxDynamicSharedMemorySize, SM128);
    cudaFuncSetAttribute(flash_kernel,                 cudaFuncAttributeMaxDynamicSharedMemorySize, FLASH_SMEM);

    // 1: all weight transforms, one launch
    wt_split_all<<<12288, dim3(32, 8)>>>(Wq, Wk, Wv, Wo, W1, W2, wthi, wtlo);

    // 2: both LayerNorms, one launch
    ln_all<<<NB*NS + NB*2*NS, 256>>>(fwd, bwd, ln1g, ln1b, comb, cxh, cxl, aeh, ael);

    // 3: fused Q+K+V projections (640 CTAs: 128 Q + 512 KV)
    mma_qkv<<<640, 256, SM128>>>(cxh, cxl, aeh, ael, wthi, wtlo,
                                 qh, ql, kh, kl, vh, vl, bq, bk, bv, pos);

    // 4: fused flash attention
    flash_kernel<<<dim3(NS/64, NB*NH), 128, FLASH_SMEM>>>(qh, ql, kh, kl, vh, vl, oh, ol);

    // 5: x = comb + (o @ Wo + bo)   [BM=64 -> 256 CTAs]
    mma_gemm<64,EPI_ADD,false><<<dim3(NC/128, (NB*NS)/64), 256, SM64>>>(
        oh, ol, NC, wthi + WT_O, wtlo + WT_O, x, nullptr, nullptr, NC, NC, bo, comb);

    // 6: h = LN(LN(x))
    double_ln_kernel<<<NB*NS, 256>>>(x, ln2g, ln2b, mlpg, mlpb, hh, hl);

    // 7: m1 = gelu(h @ W1 + b1)   [512 CTAs]
    mma_gemm<128,EPI_GELU,true><<<dim3((NE*NC)/128, (NB*NS)/128), 256, SM128>>>(
        hh, hl, NC, wthi + WT_1, wtlo + WT_1, nullptr, m1h, m1l, NE*NC, NC, b1, nullptr);

    // 8: out = x + (m1 @ W2 + b2)   [BM=64 -> 256 CTAs]
    mma_gemm<64,EPI_ADD,false><<<dim3(NC/128, (NB*NS)/64), 256, SM64>>>(
        m1h, m1l, NE*NC, wthi + WT_2, wtlo + WT_2, out, nullptr, nullptr, NC, NE*NC, b2, x);
}

// round 10
// speedup vs baseline: 2.8161x; 1.0265x over previous
#include <cuda_runtime.h>
#include <cuda_bf16.h>
#include <math.h>
#include <float.h>
#include <stdint.h>

// Problem constants
constexpr int NB = 2;
constexpr int NS = 1024;
constexpr int NC = 1024;
constexpr int NH = 16;
constexpr int HD = 64;
constexpr int NE = 4;

// ---------------------------------------------------------------------------
// Scratch (device globals)
// ---------------------------------------------------------------------------
__device__ float g_comb[NB*NS*NC];
__device__ float g_x   [NB*NS*NC];

__device__ __nv_bfloat16 g_cxh[NB*NS*NC],    g_cxl[NB*NS*NC];
__device__ __nv_bfloat16 g_aeh[NB*2*NS*NC],  g_ael[NB*2*NS*NC];
__device__ __nv_bfloat16 g_qh [NB*NS*NC],    g_ql [NB*NS*NC];
__device__ __nv_bfloat16 g_kh [NB*2*NS*NC],  g_kl [NB*2*NS*NC];
__device__ __nv_bfloat16 g_vh [NB*2*NS*NC],  g_vl [NB*2*NS*NC];
__device__ __nv_bfloat16 g_oh [NB*NS*NC],    g_ol [NB*NS*NC];
__device__ __nv_bfloat16 g_hh [NB*NS*NC],    g_hl [NB*NS*NC];
__device__ __nv_bfloat16 g_m1h[NB*NS*NE*NC], g_m1l[NB*NS*NE*NC];

__device__ __nv_bfloat16 g_wthi[12u<<20];
__device__ __nv_bfloat16 g_wtlo[12u<<20];
constexpr size_t WT_Q = 0;
constexpr size_t WT_K = (size_t)1<<20;
constexpr size_t WT_V = (size_t)2<<20;
constexpr size_t WT_O = (size_t)3<<20;
constexpr size_t WT_1 = (size_t)4<<20;
constexpr size_t WT_2 = (size_t)8<<20;

// ---------------------------------------------------------------------------
// Helpers
// ---------------------------------------------------------------------------
__device__ __forceinline__ uint32_t smem_u32(const void* p) {
    uint32_t a;
    asm("{ .reg .u64 t; cvta.to.shared.u64 t, %1; cvt.u32.u64 %0, t; }" : "=r"(a) : "l"(p));
    return a;
}
__device__ __forceinline__ uint32_t pack_bf(float a, float b) {
    __nv_bfloat162 h = __floats2bfloat162_rn(a, b);
    return *reinterpret_cast<uint32_t*>(&h);
}
__device__ __forceinline__ void split2(float a, float b, uint32_t& hi, uint32_t& lo) {
    __nv_bfloat16 ha = __float2bfloat16_rn(a);
    __nv_bfloat16 hb = __float2bfloat16_rn(b);
    hi = pack_bf(a, b);
    lo = pack_bf(a - __bfloat162float(ha), b - __bfloat162float(hb));
}
__device__ __forceinline__ void ldm_x4(uint32_t* r, uint32_t addr) {
    asm volatile("ldmatrix.sync.aligned.m8n8.x4.shared.b16 {%0,%1,%2,%3}, [%4];"
        : "=r"(r[0]), "=r"(r[1]), "=r"(r[2]), "=r"(r[3]) : "r"(addr));
}
__device__ __forceinline__ void ldm_x4_t(uint32_t* r, uint32_t addr) {
    asm volatile("ldmatrix.sync.aligned.m8n8.x4.trans.shared.b16 {%0,%1,%2,%3}, [%4];"
        : "=r"(r[0]), "=r"(r[1]), "=r"(r[2]), "=r"(r[3]) : "r"(addr));
}
__device__ __forceinline__ void mma16816(float* d, const uint32_t* a, uint32_t b0, uint32_t b1) {
    asm volatile(
        "mma.sync.aligned.m16n8k16.row.col.f32.bf16.bf16.f32 "
        "{%0,%1,%2,%3}, {%4,%5,%6,%7}, {%8,%9}, {%0,%1,%2,%3};"
        : "+f"(d[0]), "+f"(d[1]), "+f"(d[2]), "+f"(d[3])
        : "r"(a[0]), "r"(a[1]), "r"(a[2]), "r"(a[3]), "r"(b0), "r"(b1));
}
#define CP16(dst, src) \
    asm volatile("cp.async.cg.shared.global [%0], [%1], 16;" :: "r"(dst), "l"(src))
#define CP_COMMIT() asm volatile("cp.async.commit_group;")
#define CP_WAIT0()  asm volatile("cp.async.wait_group 0;")
#define CP_WAIT1()  asm volatile("cp.async.wait_group 1;")

// ---------------------------------------------------------------------------
// Merged weight transform: all 6 weights in one launch (range-decoded grid)
// ---------------------------------------------------------------------------
__global__ void wt_split_all(const float* __restrict__ Wq, const float* __restrict__ Wk,
                             const float* __restrict__ Wv, const float* __restrict__ Wo,
                             const float* __restrict__ W1, const float* __restrict__ W2,
                             __nv_bfloat16* __restrict__ hi_base,
                             __nv_bfloat16* __restrict__ lo_base)
{
    int z = blockIdx.x;
    const float* W; size_t off; int K, N, bx, by;
    if (z < 1024)      { W = Wq; off = WT_Q; K = 1024; N = 1024; bx = z & 31;  by = z >> 5; }
    else if (z < 2048) { int i = z - 1024; W = Wk; off = WT_K; K = 1024; N = 1024; bx = i & 31; by = i >> 5; }
    else if (z < 3072) { int i = z - 2048; W = Wv; off = WT_V; K = 1024; N = 1024; bx = i & 31; by = i >> 5; }
    else if (z < 4096) { int i = z - 3072; W = Wo; off = WT_O; K = 1024; N = 1024; bx = i & 31; by = i >> 5; }
    else if (z < 8192) { int i = z - 4096; W = W1; off = WT_1; K = 1024; N = 4096; bx = i & 127; by = i >> 7; }
    else               { int i = z - 8192; W = W2; off = WT_2; K = 4096; N = 1024; bx = i & 31;  by = i >> 5; }
    __nv_bfloat16* hi = hi_base + off;
    __nv_bfloat16* lo = lo_base + off;

    __shared__ float t[32][33];
    int n0 = bx * 32, k0 = by * 32;
    #pragma unroll
    for (int i = 0; i < 4; i++) {
        int k = k0 + threadIdx.y + 8*i;
        t[threadIdx.y + 8*i][threadIdx.x] = W[(size_t)k*N + n0 + threadIdx.x];
    }
    __syncthreads();
    #pragma unroll
    for (int i = 0; i < 4; i++) {
        int n = n0 + threadIdx.y + 8*i;
        int k = k0 + threadIdx.x;
        float v = t[threadIdx.x][threadIdx.y + 8*i];
        __nv_bfloat16 h = __float2bfloat16_rn(v);
        __nv_bfloat16 l = __float2bfloat16_rn(v - __bfloat162float(h));
        hi[(size_t)n*K + k] = h;
        lo[(size_t)n*K + k] = l;
    }
}

// ---------------------------------------------------------------------------
// GEMM core (shared by all MMA kernels). BM in {128, 64}; 256 threads.
// ---------------------------------------------------------------------------
constexpr int BLDS = 40;     // smem row stride (bf16): 80B, conflict-free ldmatrix

template<int BM> __host__ __device__ constexpr int NACC_OF() { return 2 * ((128 / (8 / (BM/32))) / 16); }
template<int BM> __host__ __device__ constexpr int SSZ_OF()  { return 2*BM*BLDS + 2*128*BLDS; }
template<int BM> __host__ __device__ constexpr int SMEM_OF() { return 2 * SSZ_OF<BM>() * 2; }

template<int BM, int NACC>
__device__ __forceinline__ void gemm_core(
    const __nv_bfloat16* __restrict__ Ahi, const __nv_bfloat16* __restrict__ Alo, int lda,
    const __nv_bfloat16* __restrict__ Bhi, const __nv_bfloat16* __restrict__ Blo, int K,
    int tileM, int tileN, uint32_t smb, float (&acc)[2][NACC][4])
{
    constexpr int WMW = BM/32;
    constexpr int WNW = 8/WMW;
    constexpr int NSPAN = 128/WNW;
    constexpr int NTP = NSPAN/16;
    static_assert(NACC == 2*NTP, "acc shape");
    constexpr int ASZ = BM*BLDS;
    constexpr int BSZ = 128*BLDS;
    constexpr int SSZ = 2*ASZ + 2*BSZ;

    const int tid = threadIdx.x, lane = tid & 31, wid = tid >> 5;
    const int wm = wid / WNW, wn = wid % WNW;
    const int a_row = wm*32 + (lane & 15);
    const int b_row = wn*NSPAN + (lane & 15);
    const int half8 = (lane >> 4) << 3;

    const int sr0 = tid >> 2, sc0 = (tid & 3) * 8;
    const int nch = K >> 5;

    // prologue: stage 0
    {
        #pragma unroll
        for (int p = 0; p < BM/64; p++) {
            int r = sr0 + p*64;
            uint32_t so = (r*BLDS + sc0) * 2;
            size_t ga = (size_t)(tileM + r)*lda + sc0;
            CP16(smb + so,           Ahi + ga);
            CP16(smb + ASZ*2 + so,   Alo + ga);
        }
        #pragma unroll
        for (int p = 0; p < 2; p++) {
            int r = sr0 + p*64;
            uint32_t so = (r*BLDS + sc0) * 2;
            size_t ga = (size_t)(tileN + r)*K + sc0;
            CP16(smb + 2*ASZ*2 + so,         Bhi + ga);
            CP16(smb + (2*ASZ+BSZ)*2 + so,   Blo + ga);
        }
        CP_COMMIT();
    }

    for (int c = 0; c < nch; c++) {
        const int st = c & 1;
        if (c + 1 < nch) {
            const int k0 = (c + 1) << 5;
            const uint32_t sb2 = smb + (uint32_t)((st ^ 1) * SSZ * 2);
            #pragma unroll
            for (int p = 0; p < BM/64; p++) {
                int r = sr0 + p*64;
                uint32_t so = (r*BLDS + sc0) * 2;
                size_t ga = (size_t)(tileM + r)*lda + k0 + sc0;
                CP16(sb2 + so,         Ahi + ga);
                CP16(sb2 + ASZ*2 + so, Alo + ga);
            }
            #pragma unroll
            for (int p = 0; p < 2; p++) {
                int r = sr0 + p*64;
                uint32_t so = (r*BLDS + sc0) * 2;
                size_t ga = (size_t)(tileN + r)*K + k0 + sc0;
                CP16(sb2 + 2*ASZ*2 + so,       Bhi + ga);
                CP16(sb2 + (2*ASZ+BSZ)*2 + so, Blo + ga);
            }
            CP_COMMIT();
            CP_WAIT1();
        } else {
            CP_WAIT0();
        }
        __syncthreads();

        const uint32_t sbase = smb + (uint32_t)(st * SSZ * 2);
        #pragma unroll
        for (int ks = 0; ks < 32; ks += 16) {
            uint32_t ahi[2][4], alo[2][4];
            #pragma unroll
            for (int mt = 0; mt < 2; mt++) {
                uint32_t off = ((a_row + mt*16)*BLDS + ks + half8) * 2;
                ldm_x4(ahi[mt], sbase + off);
                ldm_x4(alo[mt], sbase + ASZ*2 + off);
            }
            // B-fragment register double-buffer: prefetch ntp+1 while mma ntp
            uint32_t bh[2][4], bl[2][4];
            {
                uint32_t off0 = ((b_row + 0*16)*BLDS + ks + half8) * 2;
                ldm_x4(bh[0], sbase + 2*ASZ*2 + off0);
                ldm_x4(bl[0], sbase + (2*ASZ+BSZ)*2 + off0);
            }
            #pragma unroll
            for (int ntp = 0; ntp < NTP; ntp++) {
                const int cur = ntp & 1, nxt = cur ^ 1;
                if (ntp + 1 < NTP) {
                    uint32_t offn = ((b_row + (ntp+1)*16)*BLDS + ks + half8) * 2;
                    ldm_x4(bh[nxt], sbase + 2*ASZ*2 + offn);
                    ldm_x4(bl[nxt], sbase + (2*ASZ+BSZ)*2 + offn);
                }
                #pragma unroll
                for (int mt = 0; mt < 2; mt++) {
                    float* a0 = acc[mt][ntp*2];
                    float* a1 = acc[mt][ntp*2+1];
                    mma16816(a0, ahi[mt], bh[cur][0], bh[cur][2]);
                    mma16816(a0, ahi[mt], bl[cur][0], bl[cur][2]);
                    mma16816(a0, alo[mt], bh[cur][0], bh[cur][2]);
                    mma16816(a1, ahi[mt], bh[cur][1], bh[cur][3]);
                    mma16816(a1, ahi[mt], bl[cur][1], bl[cur][3]);
                    mma16816(a1, alo[mt], bh[cur][1], bh[cur][3]);
                }
            }
        }
        __syncthreads();
    }
}

// ---------------------------------------------------------------------------
// Generic GEMM kernel (Wo / W1 / W2 paths)
// ---------------------------------------------------------------------------
enum { EPI_ADD = 3, EPI_GELU = 4 };

template<int BM, int EPI, bool SPLITOUT>
__global__ __launch_bounds__(256, 2)
void mma_gemm(const __nv_bfloat16* __restrict__ Ahi, const __nv_bfloat16* __restrict__ Alo,
              int lda,
              const __nv_bfloat16* __restrict__ Bhi, const __nv_bfloat16* __restrict__ Blo,
              float* __restrict__ C,
              __nv_bfloat16* __restrict__ Chi, __nv_bfloat16* __restrict__ Clo,
              int ldc, int K,
              const float* __restrict__ bias,
              const float* __restrict__ addm)
{
    extern __shared__ __nv_bfloat16 sm[];
    const uint32_t smb = smem_u32(sm);
    constexpr int NACC = NACC_OF<BM>();
    constexpr int WMW = BM/32;
    constexpr int WNW = 8/WMW;
    constexpr int NSPAN = 128/WNW;

    const int lane = threadIdx.x & 31, wid = threadIdx.x >> 5;
    const int wm = wid / WNW, wn = wid % WNW;
    const int tileM = blockIdx.y * BM;
    const int tileN = blockIdx.x * 128;

    float acc[2][NACC][4];
    #pragma unroll
    for (int i = 0; i < 2; i++)
        #pragma unroll
        for (int j = 0; j < NACC; j++)
            #pragma unroll
            for (int q = 0; q < 4; q++) acc[i][j][q] = 0.f;

    gemm_core<BM, NACC>(Ahi, Alo, lda, Bhi, Blo, K, tileM, tileN, smb, acc);

    #pragma unroll
    for (int mt = 0; mt < 2; mt++) {
        #pragma unroll
        for (int nt = 0; nt < NACC; nt++) {
            int gm = tileM + wm*32 + mt*16 + (lane >> 2);
            int gn = tileN + wn*NSPAN + nt*8 + (lane & 3)*2;
            #pragma unroll
            for (int half = 0; half < 2; half++) {
                int gmr = gm + half*8;
                float v0 = acc[mt][nt][half*2], v1 = acc[mt][nt][half*2+1];
                if (EPI == EPI_ADD) {
                    float2 am = *reinterpret_cast<const float2*>(addm + (size_t)gmr*ldc + gn);
                    v0 += bias[gn] + am.x; v1 += bias[gn+1] + am.y;
                } else if (EPI == EPI_GELU) {
                    float t0 = v0 + bias[gn], t1 = v1 + bias[gn+1];
                    v0 = 0.5f*t0*(1.f + erff(t0*0.70710678118654752f));
                    v1 = 0.5f*t1*(1.f + erff(t1*0.70710678118654752f));
                }
                if (SPLITOUT) {
                    uint32_t hi, lo;
                    split2(v0, v1, hi, lo);
                    *reinterpret_cast<uint32_t*>(Chi + (size_t)gmr*ldc + gn) = hi;
                    *reinterpret_cast<uint32_t*>(Clo + (size_t)gmr*ldc + gn) = lo;
                } else {
                    *reinterpret_cast<float2*>(C + (size_t)gmr*ldc + gn) = make_float2(v0, v1);
                }
            }
        }
    }
}

// ---------------------------------------------------------------------------
// Fused QKV GEMM: 640 CTAs (0..127 Q; 128..639 KV)
// ---------------------------------------------------------------------------
__global__ __launch_bounds__(256, 2)
void mma_qkv(const __nv_bfloat16* __restrict__ cxh, const __nv_bfloat16* __restrict__ cxl,
             const __nv_bfloat16* __restrict__ aeh, const __nv_bfloat16* __restrict__ ael,
             const __nv_bfloat16* __restrict__ wthi, const __nv_bfloat16* __restrict__ wtlo,
             __nv_bfloat16* __restrict__ qh, __nv_bfloat16* __restrict__ ql,
             __nv_bfloat16* __restrict__ kh, __nv_bfloat16* __restrict__ kl,
             __nv_bfloat16* __restrict__ vh, __nv_bfloat16* __restrict__ vl,
             const float* __restrict__ bq, const float* __restrict__ bk,
             const float* __restrict__ bv, const float* __restrict__ pos)
{
    extern __shared__ __nv_bfloat16 sm[];
    const uint32_t smb = smem_u32(sm);

    const int bz = blockIdx.x;
    const bool isQ = bz < 128;
    const __nv_bfloat16 *Ah, *Al, *Bh, *Bl;
    int tileM, tileN;
    if (isQ) {
        int nx = bz & 7, ny = bz >> 3;
        tileM = ny * 128; tileN = nx * 128;
        Ah = cxh; Al = cxl; Bh = wthi + WT_Q; Bl = wtlo + WT_Q;
    } else {
        int i = bz - 128;                         // 512 CTAs
        int nx = i & 15, ny = i >> 4;             // 16 col-tiles (K|V) x 32 row-tiles (4096 rows)
        tileM = ny * 128; tileN = nx * 128;
        Ah = aeh; Al = ael; Bh = wthi + WT_K; Bl = wtlo + WT_K;
    }

    const int lane = threadIdx.x & 31, wid = threadIdx.x >> 5;
    const int wm = wid >> 1, wn = wid & 1;

    float acc[2][8][4];
    #pragma unroll
    for (int i = 0; i < 2; i++)
        #pragma unroll
        for (int j = 0; j < 8; j++)
            #pragma unroll
            for (int q = 0; q < 4; q++) acc[i][j][q] = 0.f;

    gemm_core<128, 8>(Ah, Al, NC, Bh, Bl, NC, tileM, tileN, smb, acc);

    #pragma unroll
    for (int mt = 0; mt < 2; mt++) {
        #pragma unroll
        for (int nt = 0; nt < 8; nt++) {
            int gm = tileM + wm*32 + mt*16 + (lane >> 2);
            int gn = tileN + wn*64 + nt*8 + (lane & 3)*2;
            #pragma unroll
            for (int half = 0; half < 2; half++) {
                int gmr = gm + half*8;
                float v0 = acc[mt][nt][half*2], v1 = acc[mt][nt][half*2+1];
                const float* pr = pos + (gmr % NS)*HD;
                uint32_t hi, lo;
                if (isQ) {
                    v0 = (v0 + bq[gn]   + pr[gn & (HD-1)])     * 0.125f;
                    v1 = (v1 + bq[gn+1] + pr[(gn+1) & (HD-1)]) * 0.125f;
                    split2(v0, v1, hi, lo);
                    *reinterpret_cast<uint32_t*>(qh + (size_t)gmr*NC + gn) = hi;
                    *reinterpret_cast<uint32_t*>(ql + (size_t)gmr*NC + gn) = lo;
                } else if (gn < NC) {
                    v0 = v0 + bk[gn]   + pr[gn & (HD-1)];
                    v1 = v1 + bk[gn+1] + pr[(gn+1) & (HD-1)];
                    split2(v0, v1, hi, lo);
                    *reinterpret_cast<uint32_t*>(kh + (size_t)gmr*NC + gn) = hi;
                    *reinterpret_cast<uint32_t*>(kl + (size_t)gmr*NC + gn) = lo;
                } else {
                    int gv = gn - NC;
                    v0 += bv[gv]; v1 += bv[gv+1];
                    split2(v0, v1, hi, lo);
                    *reinterpret_cast<uint32_t*>(vh + (size_t)gmr*NC + gv) = hi;
                    *reinterpret_cast<uint32_t*>(vl + (size_t)gmr*NC + gv) = lo;
                }
            }
        }
    }
}

// ---------------------------------------------------------------------------
// Flash attention (4 CTAs/SM for single-wave execution)
// ---------------------------------------------------------------------------
constexpr int FLS  = 72;
constexpr int FQHI = 0;
constexpr int FQLO = 64*FLS;
constexpr int FKHI = 2*64*FLS;
constexpr int FKLO = 3*64*FLS;
constexpr int FVHI = 4*64*FLS;
constexpr int FVLO = 5*64*FLS;
constexpr int FLASH_SMEM = 6*64*FLS*2;

__global__ __launch_bounds__(128, 4)
void flash_kernel(const __nv_bfloat16* __restrict__ qh, const __nv_bfloat16* __restrict__ ql,
                  const __nv_bfloat16* __restrict__ kh, const __nv_bfloat16* __restrict__ kl,
                  const __nv_bfloat16* __restrict__ vh, const __nv_bfloat16* __restrict__ vl,
                  __nv_bfloat16* __restrict__ oh, __nv_bfloat16* __restrict__ ol)
{
    extern __shared__ __nv_bfloat16 sf[];
    const uint32_t smb = smem_u32(sf);
    const int tid = threadIdx.x, lane = tid & 31, wid = tid >> 5;
    const int bh = blockIdx.y, b = bh >> 4, h = bh & 15;
    const int q0 = blockIdx.x * 64;
    const size_t qoff = (size_t)b*NS*NC   + h*HD;
    const size_t koff = (size_t)b*2*NS*NC + h*HD;

    {
        const int r = tid >> 1, c8 = (tid & 1) * 8;
        #pragma unroll
        for (int i = 0; i < 4; i++) {
            int cc = c8 + i*16;
            size_t ga = qoff + (size_t)(q0 + r)*NC + cc;
            uint32_t so = (r*FLS + cc) * 2;
            CP16(smb + FQHI*2 + so, qh + ga);
            CP16(smb + FQLO*2 + so, ql + ga);
        }
        CP_COMMIT(); CP_WAIT0();
    }
    __syncthreads();

    const int arow = wid*16 + (lane & 15);
    const int half8 = (lane >> 4) << 3;
    uint32_t qhi4[4][4], qlo4[4][4];
    #pragma unroll
    for (int kc = 0; kc < 4; kc++) {
        uint32_t off = (arow*FLS + kc*16 + half8) * 2;
        ldm_x4(qhi4[kc], smb + FQHI*2 + off);
        ldm_x4(qlo4[kc], smb + FQLO*2 + off);
    }

    float om[8][4];
    #pragma unroll
    for (int i = 0; i < 8; i++)
        #pragma unroll
        for (int j = 0; j < 4; j++) om[i][j] = 0.f;
    float m_i0 = -1e30f, m_i1 = -1e30f, l_i0 = 0.f, l_i1 = 0.f;

    const int qrow0 = q0 + wid*16 + (lane >> 2);

    for (int kt = 0; kt < 32; kt++) {
        const int kg0 = kt * 64;
        const bool fwdh = kg0 < 1024;
        if (fwdh) { if (kg0 > q0 + 63) continue; }
        else      { if (kg0 - 1024 + 63 < q0) continue; }
        const bool full = fwdh ? (kg0 + 63 <= q0) : (kg0 - 1024 >= q0 + 63);

        __syncthreads();
        {
            const int r = tid >> 1, c8 = (tid & 1) * 8;
            #pragma unroll
            for (int i = 0; i < 4; i++) {
                int cc = c8 + i*16;
                size_t ga = koff + (size_t)(kg0 + r)*NC + cc;
                uint32_t so = (r*FLS + cc) * 2;
                CP16(smb + FKHI*2 + so, kh + ga);
                CP16(smb + FKLO*2 + so, kl + ga);
                CP16(smb + FVHI*2 + so, vh + ga);
                CP16(smb + FVLO*2 + so, vl + ga);
            }
            CP_COMMIT(); CP_WAIT0();
        }
        __syncthreads();

        float s[8][4];
        #pragma unroll
        for (int i = 0; i < 8; i++)
            #pragma unroll
            for (int j = 0; j < 4; j++) s[i][j] = 0.f;
        #pragma unroll
        for (int kc = 0; kc < 4; kc++) {
            #pragma unroll
            for (int np = 0; np < 4; np++) {
                uint32_t off = ((np*16 + (lane & 15))*FLS + kc*16 + half8) * 2;
                uint32_t bh4[4], bl4[4];
                ldm_x4(bh4, smb + FKHI*2 + off);
                ldm_x4(bl4, smb + FKLO*2 + off);
                float* s0 = s[np*2];
                float* s1 = s[np*2+1];
                mma16816(s0, qhi4[kc], bh4[0], bh4[2]);
                mma16816(s0, qhi4[kc], bl4[0], bl4[2]);
                mma16816(s0, qlo4[kc], bh4[0], bh4[2]);
                mma16816(s1, qhi4[kc], bh4[1], bh4[3]);
                mma16816(s1, qhi4[kc], bl4[1], bl4[3]);
                mma16816(s1, qlo4[kc], bh4[1], bh4[3]);
            }
        }

        if (!full) {
            #pragma unroll
            for (int nt = 0; nt < 8; nt++) {
                int kbase = kg0 + nt*8 + (lane & 3)*2;
                #pragma unroll
                for (int d = 0; d < 2; d++) {
                    int kidx = kbase + d;
                    bool ok0, ok1;
                    if (fwdh) { ok0 = (kidx <= qrow0); ok1 = (kidx <= qrow0 + 8); }
                    else      { int j = kidx - 1024; ok0 = (j >= qrow0); ok1 = (j >= qrow0 + 8); }
                    if (!ok0) s[nt][d]     = -1e30f;
                    if (!ok1) s[nt][d + 2] = -1e30f;
                }
            }
        }

        float mx0 = -1e30f, mx1 = -1e30f;
        #pragma unroll
        for (int nt = 0; nt < 8; nt++) {
            mx0 = fmaxf(mx0, fmaxf(s[nt][0], s[nt][1]));
            mx1 = fmaxf(mx1, fmaxf(s[nt][2], s[nt][3]));
        }
        mx0 = fmaxf(mx0, __shfl_xor_sync(0xffffffffu, mx0, 1));
        mx0 = fmaxf(mx0, __shfl_xor_sync(0xffffffffu, mx0, 2));
        mx1 = fmaxf(mx1, __shfl_xor_sync(0xffffffffu, mx1, 1));
        mx1 = fmaxf(mx1, __shfl_xor_sync(0xffffffffu, mx1, 2));
        float mn0 = fmaxf(m_i0, mx0), mn1 = fmaxf(m_i1, mx1);
        float sc0 = __expf(m_i0 - mn0), sc1 = __expf(m_i1 - mn1);
        m_i0 = mn0; m_i1 = mn1;
        float rs0 = 0.f, rs1 = 0.f;
        #pragma unroll
        for (int nt = 0; nt < 8; nt++) {
            s[nt][0] = __expf(s[nt][0] - mn0);
            s[nt][1] = __expf(s[nt][1] - mn0);
            s[nt][2] = __expf(s[nt][2] - mn1);
            s[nt][3] = __expf(s[nt][3] - mn1);
            rs0 += s[nt][0] + s[nt][1];
            rs1 += s[nt][2] + s[nt][3];
        }
        rs0 += __shfl_xor_sync(0xffffffffu, rs0, 1);
        rs0 += __shfl_xor_sync(0xffffffffu, rs0, 2);
        rs1 += __shfl_xor_sync(0xffffffffu, rs1, 1);
        rs1 += __shfl_xor_sync(0xffffffffu, rs1, 2);
        l_i0 = l_i0 * sc0 + rs0;
        l_i1 = l_i1 * sc1 + rs1;
        #pragma unroll
        for (int nt = 0; nt < 8; nt++) {
            om[nt][0] *= sc0; om[nt][1] *= sc0;
            om[nt][2] *= sc1; om[nt][3] *= sc1;
        }

        #pragma unroll
        for (int kc = 0; kc < 4; kc++) {
            uint32_t ph[4], pl[4];
            split2(s[2*kc][0],   s[2*kc][1],   ph[0], pl[0]);
            split2(s[2*kc][2],   s[2*kc][3],   ph[1], pl[1]);
            split2(s[2*kc+1][0], s[2*kc+1][1], ph[2], pl[2]);
            split2(s[2*kc+1][2], s[2*kc+1][3], ph[3], pl[3]);
            const int vm = lane >> 3, vr = lane & 7;
            #pragma unroll
            for (int hp = 0; hp < 4; hp++) {
                uint32_t vaddr = ((kc*16 + (vm & 1)*8 + vr)*FLS + hp*16 + (vm >> 1)*8) * 2;
                uint32_t vh4[4], vl4[4];
                ldm_x4_t(vh4, smb + FVHI*2 + vaddr);
                ldm_x4_t(vl4, smb + FVLO*2 + vaddr);
                float* o0 = om[hp*2];
                float* o1 = om[hp*2+1];
                mma16816(o0, ph, vh4[0], vh4[1]);
                mma16816(o0, pl, vh4[0], vh4[1]);
                mma16816(o0, ph, vl4[0], vl4[1]);
                mma16816(o1, ph, vh4[2], vh4[3]);
                mma16816(o1, pl, vh4[2], vh4[3]);
                mma16816(o1, ph, vl4[2], vl4[3]);
            }
        }
    }

    float il0 = 1.f / l_i0, il1 = 1.f / l_i1;
    #pragma unroll
    for (int nt = 0; nt < 8; nt++) {
        int hd = nt*8 + (lane & 3)*2;
        uint32_t hi, lo;
        split2(om[nt][0]*il0, om[nt][1]*il0, hi, lo);
        *reinterpret_cast<uint32_t*>(oh + qoff + (size_t)qrow0*NC + hd) = hi;
        *reinterpret_cast<uint32_t*>(ol + qoff + (size_t)qrow0*NC + hd) = lo;
        split2(om[nt][2]*il1, om[nt][3]*il1, hi, lo);
        *reinterpret_cast<uint32_t*>(oh + qoff + (size_t)(qrow0+8)*NC + hd) = hi;
        *reinterpret_cast<uint32_t*>(ol + qoff + (size_t)(qrow0+8)*NC + hd) = lo;
    }
}

// ---------------------------------------------------------------------------
// Block reduction + LN kernels
// ---------------------------------------------------------------------------
__device__ __forceinline__ float2 block_reduce_sum2(float a, float b) {
    __shared__ float sha[8], shb[8];
    #pragma unroll
    for (int o = 16; o > 0; o >>= 1) {
        a += __shfl_xor_sync(0xffffffffu, a, o);
        b += __shfl_xor_sync(0xffffffffu, b, o);
    }
    int lane = threadIdx.x & 31, w = threadIdx.x >> 5;
    __syncthreads();
    if (lane == 0) { sha[w] = a; shb[w] = b; }
    __syncthreads();
    a = sha[lane & 7]; b = shb[lane & 7];
    #pragma unroll
    for (int o = 4; o > 0; o >>= 1) {
        a += __shfl_xor_sync(0xffffffffu, a, o);
        b += __shfl_xor_sync(0xffffffffu, b, o);
    }
    return make_float2(a, b);
}

__device__ __forceinline__ void store_split(__nv_bfloat16* hi, __nv_bfloat16* lo,
                                            size_t idx, float y) {
    __nv_bfloat16 hv = __float2bfloat16_rn(y);
    hi[idx] = hv;
    lo[idx] = __float2bfloat16_rn(y - __bfloat162float(hv));
}

// Merged LN: blocks [0, NB*NS) -> comb+cx ; [NB*NS, NB*NS+NB*2*NS) -> ae
__global__ void ln_all(const float* __restrict__ fwd, const float* __restrict__ bwd,
                       const float* __restrict__ g, const float* __restrict__ bta,
                       float* __restrict__ comb,
                       __nv_bfloat16* __restrict__ cxh, __nv_bfloat16* __restrict__ cxl,
                       __nv_bfloat16* __restrict__ aeh, __nv_bfloat16* __restrict__ ael)
{
    int z = blockIdx.x;
    if (z < NB*NS) {
        int row = z;
        int b = row / NS, s = row % NS;
        const float* fp = fwd + ((size_t)b*(NS+1) + s) * NC;
        const float* rp = bwd + ((size_t)b*(NS+1) + s + 1) * NC;
        const float rs2 = 0.70710678118654752f;
        float vals[4];
        float sum = 0.f, sq = 0.f;
        #pragma unroll
        for (int t = 0; t < 4; t++) {
            int i = threadIdx.x + t*256;
            float c = (fp[i] + rp[i]) * rs2;
            vals[t] = c; sum += c; sq += c*c;
            comb[(size_t)row*NC + i] = c;
        }
        float2 r2 = block_reduce_sum2(sum, sq);
        float mean = r2.x * (1.f/NC);
        float var  = r2.y * (1.f/NC) - mean*mean;
        float rinv = rsqrtf(var + 1e-5f);
        #pragma unroll
        for (int t = 0; t < 4; t++) {
            int i = threadIdx.x + t*256;
            store_split(cxh, cxl, (size_t)row*NC + i, (vals[t] - mean) * rinv * g[i] + bta[i]);
        }
    } else {
        int row = z - NB*NS;
        int b = row / (2*NS), t = row % (2*NS);
        const float* src = (t < NS) ? fwd + ((size_t)b*(NS+1) + t) * NC
                                    : bwd + ((size_t)b*(NS+1) + (t - NS) + 1) * NC;
        float vals[4];
        float sum = 0.f, sq = 0.f;
        #pragma unroll
        for (int u = 0; u < 4; u++) {
            int i = threadIdx.x + u*256;
            float c = src[i];
            vals[u] = c; sum += c; sq += c*c;
        }
        float2 r2 = block_reduce_sum2(sum, sq);
        float mean = r2.x * (1.f/NC);
        float var  = r2.y * (1.f/NC) - mean*mean;
        float rinv = rsqrtf(var + 1e-5f);
        #pragma unroll
        for (int u = 0; u < 4; u++) {
            int i = threadIdx.x + u*256;
            store_split(aeh, ael, (size_t)row*NC + i, (vals[u] - mean) * rinv * g[i] + bta[i]);
        }
    }
}

__global__ void double_ln_kernel(const float* __restrict__ xin,
                                 const float* __restrict__ g2, const float* __restrict__ b2,
                                 const float* __restrict__ gm, const float* __restrict__ bm,
                                 __nv_bfloat16* __restrict__ hh, __nv_bfloat16* __restrict__ hl)
{
    int row = blockIdx.x;
    const float* xp = xin + (size_t)row*NC;
    float vals[4];
    float s = 0.f, sq = 0.f;
    #pragma unroll
    for (int t = 0; t < 4; t++) {
        int i = threadIdx.x + t*256;
        float vv = xp[i];
        vals[t] = vv; s += vv; sq += vv*vv;
    }
    float2 r2 = block_reduce_sum2(s, sq);
    float mean = r2.x * (1.f/NC);
    float var  = r2.y * (1.f/NC) - mean*mean;
    float rinv = rsqrtf(var + 1e-5f);
    s = 0.f; sq = 0.f;
    #pragma unroll
    for (int t = 0; t < 4; t++) {
        int i = threadIdx.x + t*256;
        float y = (vals[t] - mean) * rinv * g2[i] + b2[i];
        vals[t] = y; s += y; sq += y*y;
    }
    r2 = block_reduce_sum2(s, sq);
    mean = r2.x * (1.f/NC);
    var  = r2.y * (1.f/NC) - mean*mean;
    rinv = rsqrtf(var + 1e-5f);
    #pragma unroll
    for (int t = 0; t < 4; t++) {
        int i = threadIdx.x + t*256;
        store_split(hh, hl, (size_t)row*NC + i, (vals[t] - mean) * rinv * gm[i] + bm[i]);
    }
}

// ---------------------------------------------------------------------------
// Launch
// ---------------------------------------------------------------------------
extern "C" void kernel_launch(void* const* d_in, const int* in_sizes, int n_in,
                              void* d_out, int out_size)
{
    (void)in_sizes; (void)n_in; (void)out_size;
    const float* fwd  = (const float*)d_in[0];
    const float* bwd  = (const float*)d_in[1];
    const float* pos  = (const float*)d_in[2];
    const float* ln1g = (const float*)d_in[3];
    const float* ln1b = (const float*)d_in[4];
    const float* Wq   = (const float*)d_in[5];
    const float* bq   = (const float*)d_in[6];
    const float* Wk   = (const float*)d_in[7];
    const float* bk   = (const float*)d_in[8];
    const float* Wv   = (const float*)d_in[9];
    const float* bv   = (const float*)d_in[10];
    const float* Wo   = (const float*)d_in[11];
    const float* bo   = (const float*)d_in[12];
    const float* ln2g = (const float*)d_in[13];
    const float* ln2b = (const float*)d_in[14];
    const float* mlpg = (const float*)d_in[15];
    const float* mlpb = (const float*)d_in[16];
    const float* W1   = (const float*)d_in[17];
    const float* b1   = (const float*)d_in[18];
    const float* W2   = (const float*)d_in[19];
    const float* b2   = (const float*)d_in[20];
    float* out = (float*)d_out;

    float *comb, *x;
    __nv_bfloat16 *cxh,*cxl,*aeh,*ael,*qh,*ql,*kh,*kl,*vh,*vl,*oh,*ol,*hh,*hl,*m1h,*m1l;
    __nv_bfloat16 *wthi, *wtlo;
    cudaGetSymbolAddress((void**)&comb, g_comb);
    cudaGetSymbolAddress((void**)&x,    g_x);
    cudaGetSymbolAddress((void**)&cxh,  g_cxh);  cudaGetSymbolAddress((void**)&cxl, g_cxl);
    cudaGetSymbolAddress((void**)&aeh,  g_aeh);  cudaGetSymbolAddress((void**)&ael, g_ael);
    cudaGetSymbolAddress((void**)&qh,   g_qh);   cudaGetSymbolAddress((void**)&ql,  g_ql);
    cudaGetSymbolAddress((void**)&kh,   g_kh);   cudaGetSymbolAddress((void**)&kl,  g_kl);
    cudaGetSymbolAddress((void**)&vh,   g_vh);   cudaGetSymbolAddress((void**)&vl,  g_vl);
    cudaGetSymbolAddress((void**)&oh,   g_oh);   cudaGetSymbolAddress((void**)&ol,  g_ol);
    cudaGetSymbolAddress((void**)&hh,   g_hh);   cudaGetSymbolAddress((void**)&hl,  g_hl);
    cudaGetSymbolAddress((void**)&m1h,  g_m1h);  cudaGetSymbolAddress((void**)&m1l, g_m1l);
    cudaGetSymbolAddress((void**)&wthi, g_wthi);
    cudaGetSymbolAddress((void**)&wtlo, g_wtlo);

    constexpr int SM128 = SMEM_OF<128>();   // 81920
    constexpr int SM64  = SMEM_OF<64>();    // 61440
    cudaFuncSetAttribute(mma_qkv,                      cudaFuncAttributeMaxDynamicSharedMemorySize, SM128);
    cudaFuncSetAttribute(mma_gemm<64,EPI_ADD,false>,   cudaFuncAttributeMaxDynamicSharedMemorySize, SM64);
    cudaFuncSetAttribute(mma_gemm<128,EPI_GELU,true>,  cudaFuncAttributeMaxDynamicSharedMemorySize, SM128);
    cudaFuncSetAttribute(flash_kernel,                 cudaFuncAttributeMaxDynamicSharedMemorySize, FLASH_SMEM);

    // 1: all weight transforms, one launch
    wt_split_all<<<12288, dim3(32, 8)>>>(Wq, Wk, Wv, Wo, W1, W2, wthi, wtlo);

    // 2: both LayerNorms, one launch
    ln_all<<<NB*NS + NB*2*NS, 256>>>(fwd, bwd, ln1g, ln1b, comb, cxh, cxl, aeh, ael);

    // 3: fused Q+K+V projections (640 CTAs: 128 Q + 512 KV)
    mma_qkv<<<640, 256, SM128>>>(cxh, cxl, aeh, ael, wthi, wtlo,
                                 qh, ql, kh, kl, vh, vl, bq, bk, bv, pos);

    // 4: fused flash attention (512 CTAs, 4/SM -> single wave)
    flash_kernel<<<dim3(NS/64, NB*NH), 128, FLASH_SMEM>>>(qh, ql, kh, kl, vh, vl, oh, ol);

    // 5: x = comb + (o @ Wo + bo)   [BM=64 -> 256 CTAs]
    mma_gemm<64,EPI_ADD,false><<<dim3(NC/128, (NB*NS)/64), 256, SM64>>>(
        oh, ol, NC, wthi + WT_O, wtlo + WT_O, x, nullptr, nullptr, NC, NC, bo, comb);

    // 6: h = LN(LN(x))
    double_ln_kernel<<<NB*NS, 256>>>(x, ln2g, ln2b, mlpg, mlpb, hh, hl);

    // 7: m1 = gelu(h @ W1 + b1)   [512 CTAs]
    mma_gemm<128,EPI_GELU,true><<<dim3((NE*NC)/128, (NB*NS)/128), 256, SM128>>>(
        hh, hl, NC, wthi + WT_1, wtlo + WT_1, nullptr, m1h, m1l, NE*NC, NC, b1, nullptr);

    // 8: out = x + (m1 @ W2 + b2)   [BM=64 -> 256 CTAs]
    mma_gemm<64,EPI_ADD,false><<<dim3(NC/128, (NB*NS)/64), 256, SM64>>>(
        m1h, m1l, NE*NC, wthi + WT_2, wtlo + WT_2, out, nullptr, nullptr, NC, NE*NC, b2, x);
}